// round 6
// baseline (speedup 1.0000x reference)
#include <cuda_runtime.h>
#include <cuda_bf16.h>
#include <math.h>
#include <stdint.h>

#define BB 4
#define SS 512
#define EE 512
#define HH 8
#define HD 64
#define CC 128
#define NROW (BB*SS)          // 2048
#define PSTR 40               // smem row stride in bf16 (80B) -> conflict-free ldmatrix

// ---------------- scratch (static device globals; no allocation) ----------------
__device__ __nv_bfloat16 g_xhi[NROW*EE], g_xlo[NROW*EE];
__device__ __nv_bfloat16 g_wthi[4*EE*EE], g_wtlo[4*EE*EE];           // transposed [n][k]
__device__ __nv_bfloat16 g_qhi[BB*HH*SS*HD], g_qlo[BB*HH*SS*HD];     // [bh][s][d]
__device__ __nv_bfloat16 g_khi[BB*HH*SS*HD], g_klo[BB*HH*SS*HD];     // [bh][s][d]
__device__ __nv_bfloat16 g_vthi[BB*HH*HD*SS], g_vtlo[BB*HH*HD*SS];   // [bh][d][s]
__device__ float g_s[(size_t)BB*HH*SS*SS];                           // 32MB
__device__ float g_ma[BB*SS*SS];
__device__ float g_tp[BB*SS*SS];
__device__ __nv_bfloat16 g_ahi[(size_t)BB*HH*SS*SS], g_alo[(size_t)BB*HH*SS*SS];
__device__ __nv_bfloat16 g_ohhi[NROW*EE], g_ohlo[NROW*EE];           // [B,S,E]
__device__ double g_acc[BB*5];
__device__ int    g_amax[BB];
__device__ float  g_coef[BB*3];

// ---------------- helpers ----------------
__device__ __forceinline__ float clipf(float v, float lo, float hi) {
    return fminf(fmaxf(v, lo), hi);
}
__device__ __forceinline__ uint32_t smem_u32(const void* p) {
    uint32_t a;
    asm("{ .reg .u64 t; cvta.to.shared.u64 t, %1; cvt.u32.u64 %0, t; }" : "=r"(a) : "l"(p));
    return a;
}
__device__ __forceinline__ void ldsm4(uint32_t* a, uint32_t addr) {
    asm volatile("ldmatrix.sync.aligned.m8n8.x4.shared.b16 {%0,%1,%2,%3}, [%4];"
        : "=r"(a[0]), "=r"(a[1]), "=r"(a[2]), "=r"(a[3]) : "r"(addr));
}
__device__ __forceinline__ void ldsm2(uint32_t* a, uint32_t addr) {
    asm volatile("ldmatrix.sync.aligned.m8n8.x2.shared.b16 {%0,%1}, [%2];"
        : "=r"(a[0]), "=r"(a[1]) : "r"(addr));
}
__device__ __forceinline__ void mma_bf16(float* d, const uint32_t* a, const uint32_t* b) {
    asm volatile("mma.sync.aligned.m16n8k16.row.col.f32.bf16.bf16.f32 "
        "{%0,%1,%2,%3}, {%4,%5,%6,%7}, {%8,%9}, {%0,%1,%2,%3};"
        : "+f"(d[0]), "+f"(d[1]), "+f"(d[2]), "+f"(d[3])
        : "r"(a[0]), "r"(a[1]), "r"(a[2]), "r"(a[3]), "r"(b[0]), "r"(b[1]));
}
__device__ __forceinline__ void cpa16(uint32_t dst, const void* src) {
    asm volatile("cp.async.cg.shared.global [%0], [%1], 16;" :: "r"(dst), "l"(src) : "memory");
}
#define CP_COMMIT() asm volatile("cp.async.commit_group;" ::: "memory")
#define CP_WAIT1()  asm volatile("cp.async.wait_group 1;" ::: "memory")
#define CP_WAIT0()  asm volatile("cp.async.wait_group 0;" ::: "memory")

__device__ __forceinline__ float warpSum(float v) {
    #pragma unroll
    for (int o = 16; o > 0; o >>= 1) v += __shfl_xor_sync(0xffffffffu, v, o);
    return v;
}
__device__ __forceinline__ float warpMax(float v) {
    #pragma unroll
    for (int o = 16; o > 0; o >>= 1) v = fmaxf(v, __shfl_xor_sync(0xffffffffu, v, o));
    return v;
}

// ================= conversion kernels =================
__global__ void conv_split(const float* __restrict__ in, __nv_bfloat16* __restrict__ hi,
                           __nv_bfloat16* __restrict__ lo, int n)
{
    int i = (blockIdx.x * 256 + threadIdx.x) * 4;
    if (i < n) {
        float4 v = *(const float4*)(in + i);
        __nv_bfloat16 h0 = __float2bfloat16_rn(v.x);
        __nv_bfloat16 h1 = __float2bfloat16_rn(v.y);
        __nv_bfloat16 h2 = __float2bfloat16_rn(v.z);
        __nv_bfloat16 h3 = __float2bfloat16_rn(v.w);
        __nv_bfloat162 H0(h0, h1), H1(h2, h3);
        __nv_bfloat162 L0(__float2bfloat16_rn(v.x - __bfloat162float(h0)),
                          __float2bfloat16_rn(v.y - __bfloat162float(h1)));
        __nv_bfloat162 L1(__float2bfloat16_rn(v.z - __bfloat162float(h2)),
                          __float2bfloat16_rn(v.w - __bfloat162float(h3)));
        *(__nv_bfloat162*)(hi + i)     = H0;
        *(__nv_bfloat162*)(hi + i + 2) = H1;
        *(__nv_bfloat162*)(lo + i)     = L0;
        *(__nv_bfloat162*)(lo + i + 2) = L1;
    }
}

// transpose + split: wt[n][k] = W[k][n]; grid.z selects which W
__global__ void conv_w4(const float* __restrict__ Wq, const float* __restrict__ Wk,
                        const float* __restrict__ Wv, const float* __restrict__ Wo,
                        __nv_bfloat16* __restrict__ thi, __nv_bfloat16* __restrict__ tlo)
{
    __shared__ float tile[32][33];
    int z = blockIdx.z;
    const float* W = (z == 0) ? Wq : (z == 1) ? Wk : (z == 2) ? Wv : Wo;
    __nv_bfloat16* th = thi + (size_t)z * EE * EE;
    __nv_bfloat16* tl = tlo + (size_t)z * EE * EE;
    int bx = blockIdx.x * 32, by = blockIdx.y * 32;
    int x = threadIdx.x, y = threadIdx.y;
    #pragma unroll
    for (int j = 0; j < 4; j++)
        tile[y + j * 8][x] = W[(size_t)(by + y + j * 8) * EE + bx + x];
    __syncthreads();
    #pragma unroll
    for (int j = 0; j < 4; j++) {
        float v = tile[x][y + j * 8];
        __nv_bfloat16 h = __float2bfloat16_rn(v);
        size_t dst = (size_t)(bx + y + j * 8) * EE + by + x;
        th[dst] = h;
        tl[dst] = __float2bfloat16_rn(v - __bfloat162float(h));
    }
}

// ================= pipelined 128x128 GEMM core pieces =================
// dynamic smem layout: stage stride 40960B; within stage: Ah 0, Al 10240, Bh 20480, Bl 30720
#define STG_STRIDE 40960

// ================= fused QKV projection (cp.async 2-stage) =================
// grid (4, 16, 3): z=0 -> q [bh][s][d], z=1 -> k, z=2 -> v transposed [bh][d][s]
__global__ void __launch_bounds__(256) proj_qkv(
    const __nv_bfloat16* __restrict__ xhi, const __nv_bfloat16* __restrict__ xlo,
    const __nv_bfloat16* __restrict__ wthi, const __nv_bfloat16* __restrict__ wtlo,
    const float* __restrict__ bq, const float* __restrict__ bk, const float* __restrict__ bv,
    __nv_bfloat16* __restrict__ qhi, __nv_bfloat16* __restrict__ qlo,
    __nv_bfloat16* __restrict__ khi, __nv_bfloat16* __restrict__ klo,
    __nv_bfloat16* __restrict__ vthi, __nv_bfloat16* __restrict__ vtlo)
{
    extern __shared__ char dsm[];
    uint32_t sb0 = smem_u32(dsm);
    int t = threadIdx.x, lane = t & 31, wid = t >> 5;
    int wm = wid >> 2, wn = wid & 3;
    int z = blockIdx.z;
    int n0 = blockIdx.x * 128, m0 = blockIdx.y * 128;
    const __nv_bfloat16* Bh = wthi + (size_t)z * EE * EE;
    const __nv_bfloat16* Bl = wtlo + (size_t)z * EE * EE;
    const float* bias = (z == 0) ? bq : ((z == 1) ? bk : bv);

    float acc[4][4][4] = {};
    int mat = lane >> 3, r8 = lane & 7;

    // stage loader
    auto load_stage = [&](int kc, int st) {
        uint32_t base = sb0 + st * STG_STRIDE;
        #pragma unroll
        for (int i = t; i < 512; i += 256) {
            int row = i >> 2, seg = i & 3;
            uint32_t so = (uint32_t)(row * PSTR + seg * 8) * 2;
            size_t ga = (size_t)(m0 + row) * EE + kc * 32 + seg * 8;
            size_t gb = (size_t)(n0 + row) * EE + kc * 32 + seg * 8;
            cpa16(base + so,         &xhi[ga]);
            cpa16(base + 10240 + so, &xlo[ga]);
            cpa16(base + 20480 + so, &Bh[gb]);
            cpa16(base + 30720 + so, &Bl[gb]);
        }
    };

    load_stage(0, 0); CP_COMMIT();

    #pragma unroll 1
    for (int kc = 0; kc < 16; kc++) {
        int st = kc & 1;
        if (kc + 1 < 16) { load_stage(kc + 1, st ^ 1); CP_COMMIT(); CP_WAIT1(); }
        else CP_WAIT0();
        __syncthreads();
        uint32_t bAh = sb0 + st * STG_STRIDE;
        uint32_t bAl = bAh + 10240, bBh = bAh + 20480, bBl = bAh + 30720;
        #pragma unroll
        for (int kk = 0; kk < 2; kk++) {
            uint32_t ah[4][4], al[4][4], bhf[4][2], blf[4][2];
            uint32_t aoff = (uint32_t)((wm * 64 + r8 + (mat & 1) * 8) * PSTR + kk * 16 + (mat >> 1) * 8) * 2;
            #pragma unroll
            for (int fm = 0; fm < 4; fm++) {
                uint32_t o = aoff + fm * 16 * PSTR * 2;
                ldsm4(ah[fm], bAh + o);
                ldsm4(al[fm], bAl + o);
            }
            uint32_t boff = (uint32_t)((wn * 32 + r8) * PSTR + kk * 16 + (mat & 1) * 8) * 2;
            #pragma unroll
            for (int fn = 0; fn < 4; fn++) {
                uint32_t o = boff + fn * 8 * PSTR * 2;
                ldsm2(bhf[fn], bBh + o);
                ldsm2(blf[fn], bBl + o);
            }
            #pragma unroll
            for (int fm = 0; fm < 4; fm++)
                #pragma unroll
                for (int fn = 0; fn < 4; fn++) {
                    mma_bf16(acc[fm][fn], ah[fm], bhf[fn]);
                    mma_bf16(acc[fm][fn], ah[fm], blf[fn]);
                    mma_bf16(acc[fm][fn], al[fm], bhf[fn]);
                }
        }
        __syncthreads();
    }

    #pragma unroll
    for (int fm = 0; fm < 4; fm++)
        #pragma unroll
        for (int fn = 0; fn < 4; fn++)
            #pragma unroll
            for (int dr = 0; dr < 4; dr++) {
                int m = m0 + wm * 64 + fm * 16 + (lane >> 2) + (dr >> 1) * 8;
                int n = n0 + wn * 32 + fn * 8 + (lane & 3) * 2 + (dr & 1);
                float v = acc[fm][fn][dr] + bias[n];
                int b = m >> 9, s = m & 511;
                int h = n >> 6, d = n & 63;
                __nv_bfloat16 hh = __float2bfloat16_rn(v);
                __nv_bfloat16 ll = __float2bfloat16_rn(v - __bfloat162float(hh));
                if (z == 0) {
                    size_t dst = (((size_t)(b * HH + h) * SS) + s) * HD + d;
                    qhi[dst] = hh; qlo[dst] = ll;
                } else if (z == 1) {
                    size_t dst = (((size_t)(b * HH + h) * SS) + s) * HD + d;
                    khi[dst] = hh; klo[dst] = ll;
                } else {
                    size_t dst = (((size_t)(b * HH + h) * HD) + d) * SS + s;
                    vthi[dst] = hh; vtlo[dst] = ll;
                }
            }
}

// ================= output projection (cp.async 2-stage): fp32 result =================
__global__ void __launch_bounds__(256) proj_out(
    const __nv_bfloat16* __restrict__ ahi, const __nv_bfloat16* __restrict__ alo,
    const __nv_bfloat16* __restrict__ wthi, const __nv_bfloat16* __restrict__ wtlo,
    const float* __restrict__ bias, float* __restrict__ out)
{
    extern __shared__ char dsm[];
    uint32_t sb0 = smem_u32(dsm);
    int t = threadIdx.x, lane = t & 31, wid = t >> 5;
    int wm = wid >> 2, wn = wid & 3;
    int n0 = blockIdx.x * 128, m0 = blockIdx.y * 128;
    const __nv_bfloat16* Bh = wthi + (size_t)3 * EE * EE;
    const __nv_bfloat16* Bl = wtlo + (size_t)3 * EE * EE;

    float acc[4][4][4] = {};
    int mat = lane >> 3, r8 = lane & 7;

    auto load_stage = [&](int kc, int st) {
        uint32_t base = sb0 + st * STG_STRIDE;
        #pragma unroll
        for (int i = t; i < 512; i += 256) {
            int row = i >> 2, seg = i & 3;
            uint32_t so = (uint32_t)(row * PSTR + seg * 8) * 2;
            size_t ga = (size_t)(m0 + row) * EE + kc * 32 + seg * 8;
            size_t gb = (size_t)(n0 + row) * EE + kc * 32 + seg * 8;
            cpa16(base + so,         &ahi[ga]);
            cpa16(base + 10240 + so, &alo[ga]);
            cpa16(base + 20480 + so, &Bh[gb]);
            cpa16(base + 30720 + so, &Bl[gb]);
        }
    };

    load_stage(0, 0); CP_COMMIT();

    #pragma unroll 1
    for (int kc = 0; kc < 16; kc++) {
        int st = kc & 1;
        if (kc + 1 < 16) { load_stage(kc + 1, st ^ 1); CP_COMMIT(); CP_WAIT1(); }
        else CP_WAIT0();
        __syncthreads();
        uint32_t bAh = sb0 + st * STG_STRIDE;
        uint32_t bAl = bAh + 10240, bBh = bAh + 20480, bBl = bAh + 30720;
        #pragma unroll
        for (int kk = 0; kk < 2; kk++) {
            uint32_t ah[4][4], al[4][4], bhf[4][2], blf[4][2];
            uint32_t aoff = (uint32_t)((wm * 64 + r8 + (mat & 1) * 8) * PSTR + kk * 16 + (mat >> 1) * 8) * 2;
            #pragma unroll
            for (int fm = 0; fm < 4; fm++) {
                uint32_t o = aoff + fm * 16 * PSTR * 2;
                ldsm4(ah[fm], bAh + o);
                ldsm4(al[fm], bAl + o);
            }
            uint32_t boff = (uint32_t)((wn * 32 + r8) * PSTR + kk * 16 + (mat & 1) * 8) * 2;
            #pragma unroll
            for (int fn = 0; fn < 4; fn++) {
                uint32_t o = boff + fn * 8 * PSTR * 2;
                ldsm2(bhf[fn], bBh + o);
                ldsm2(blf[fn], bBl + o);
            }
            #pragma unroll
            for (int fm = 0; fm < 4; fm++)
                #pragma unroll
                for (int fn = 0; fn < 4; fn++) {
                    mma_bf16(acc[fm][fn], ah[fm], bhf[fn]);
                    mma_bf16(acc[fm][fn], ah[fm], blf[fn]);
                    mma_bf16(acc[fm][fn], al[fm], bhf[fn]);
                }
        }
        __syncthreads();
    }

    #pragma unroll
    for (int fm = 0; fm < 4; fm++)
        #pragma unroll
        for (int fn = 0; fn < 4; fn++)
            #pragma unroll
            for (int dr = 0; dr < 4; dr++) {
                int m = m0 + wm * 64 + fm * 16 + (lane >> 2) + (dr >> 1) * 8;
                int n = n0 + wn * 32 + fn * 8 + (lane & 3) * 2 + (dr & 1);
                out[(size_t)m * EE + n] = acc[fm][fn][dr] + bias[n];
            }
}

// ================= batched QK^T (K=64, static smem, unchanged from R5) =================
__global__ void __launch_bounds__(256) qk_mma(
    const __nv_bfloat16* __restrict__ qhi, const __nv_bfloat16* __restrict__ qlo,
    const __nv_bfloat16* __restrict__ khi, const __nv_bfloat16* __restrict__ klo,
    float* __restrict__ s)
{
    __shared__ __nv_bfloat16 sAh[128*PSTR], sAl[128*PSTR], sBh[128*PSTR], sBl[128*PSTR];
    int t = threadIdx.x, lane = t & 31, wid = t >> 5;
    int wm = wid >> 2, wn = wid & 3;
    int j0 = blockIdx.x * 128, i0 = blockIdx.y * 128, bh = blockIdx.z;

    uint32_t bAh = smem_u32(sAh), bAl = smem_u32(sAl), bBh = smem_u32(sBh), bBl = smem_u32(sBl);
    float acc[4][4][4] = {};
    int mat = lane >> 3, r8 = lane & 7;

    for (int kc = 0; kc < 2; kc++) {
        #pragma unroll
        for (int i = t; i < 512; i += 256) {
            int row = i >> 2, seg = i & 3;
            size_t ga = ((size_t)bh * SS + i0 + row) * HD + kc * 32 + seg * 8;
            *(uint4*)&sAh[row * PSTR + seg * 8] = *(const uint4*)&qhi[ga];
            *(uint4*)&sAl[row * PSTR + seg * 8] = *(const uint4*)&qlo[ga];
            size_t gb = ((size_t)bh * SS + j0 + row) * HD + kc * 32 + seg * 8;
            *(uint4*)&sBh[row * PSTR + seg * 8] = *(const uint4*)&khi[gb];
            *(uint4*)&sBl[row * PSTR + seg * 8] = *(const uint4*)&klo[gb];
        }
        __syncthreads();
        #pragma unroll
        for (int kk = 0; kk < 2; kk++) {
            uint32_t ah[4][4], al[4][4], bhf[4][2], blf[4][2];
            uint32_t aoff = (uint32_t)((wm * 64 + r8 + (mat & 1) * 8) * PSTR + kk * 16 + (mat >> 1) * 8) * 2;
            #pragma unroll
            for (int fm = 0; fm < 4; fm++) {
                uint32_t o = aoff + fm * 16 * PSTR * 2;
                ldsm4(ah[fm], bAh + o);
                ldsm4(al[fm], bAl + o);
            }
            uint32_t boff = (uint32_t)((wn * 32 + r8) * PSTR + kk * 16 + (mat & 1) * 8) * 2;
            #pragma unroll
            for (int fn = 0; fn < 4; fn++) {
                uint32_t o = boff + fn * 8 * PSTR * 2;
                ldsm2(bhf[fn], bBh + o);
                ldsm2(blf[fn], bBl + o);
            }
            #pragma unroll
            for (int fm = 0; fm < 4; fm++)
                #pragma unroll
                for (int fn = 0; fn < 4; fn++) {
                    mma_bf16(acc[fm][fn], ah[fm], bhf[fn]);
                    mma_bf16(acc[fm][fn], ah[fm], blf[fn]);
                    mma_bf16(acc[fm][fn], al[fm], bhf[fn]);
                }
        }
        __syncthreads();
    }

    float* sbase = s + (size_t)bh * SS * SS;
    #pragma unroll
    for (int fm = 0; fm < 4; fm++)
        #pragma unroll
        for (int fn = 0; fn < 4; fn++)
            #pragma unroll
            for (int dr = 0; dr < 4; dr++) {
                int mi = i0 + wm * 64 + fm * 16 + (lane >> 2) + (dr >> 1) * 8;
                int nj = j0 + wn * 32 + fn * 8 + (lane & 3) * 2 + (dr & 1);
                float v = acc[fm][fn][dr] * 0.125f;
                if (isnan(v)) v = 0.f;
                else if (isinf(v)) v = v > 0.f ? 10.f : -10.f;
                v = clipf(v, -15.f, 15.f);
                sbase[(size_t)mi * SS + nj] = v;
            }
}

// ================= batched attn @ V (cp.async 2-stage) =================
// dynamic smem: stage stride 30720B: Ah 0, Al 10240, Bh 20480, Bl 25600
#define AV_STG 30720
__global__ void __launch_bounds__(256) av_mma(
    const __nv_bfloat16* __restrict__ ahi, const __nv_bfloat16* __restrict__ alo,
    const __nv_bfloat16* __restrict__ vthi, const __nv_bfloat16* __restrict__ vtlo,
    __nv_bfloat16* __restrict__ ohi, __nv_bfloat16* __restrict__ olo)
{
    extern __shared__ char dsm[];
    uint32_t sb0 = smem_u32(dsm);
    int t = threadIdx.x, lane = t & 31, wid = t >> 5;
    int wm = wid >> 2, wn = wid & 3;
    int i0 = blockIdx.x * 128, bh = blockIdx.y;
    int b = bh >> 3, h = bh & 7;

    float acc[4][2][4] = {};
    int mat = lane >> 3, r8 = lane & 7;

    auto load_stage = [&](int kc, int st) {
        uint32_t base = sb0 + st * AV_STG;
        #pragma unroll
        for (int i = t; i < 512; i += 256) {
            int row = i >> 2, seg = i & 3;
            uint32_t so = (uint32_t)(row * PSTR + seg * 8) * 2;
            size_t ga = (size_t)bh * SS * SS + (size_t)(i0 + row) * SS + kc * 32 + seg * 8;
            cpa16(base + so,         &ahi[ga]);
            cpa16(base + 10240 + so, &alo[ga]);
        }
        {
            int row = t >> 2, seg = t & 3;   // 64 rows x 4 segs
            uint32_t so = (uint32_t)(row * PSTR + seg * 8) * 2;
            size_t gb = ((size_t)bh * HD + row) * SS + kc * 32 + seg * 8;
            cpa16(base + 20480 + so, &vthi[gb]);
            cpa16(base + 25600 + so, &vtlo[gb]);
        }
    };

    load_stage(0, 0); CP_COMMIT();

    #pragma unroll 1
    for (int kc = 0; kc < 16; kc++) {
        int st = kc & 1;
        if (kc + 1 < 16) { load_stage(kc + 1, st ^ 1); CP_COMMIT(); CP_WAIT1(); }
        else CP_WAIT0();
        __syncthreads();
        uint32_t bAh = sb0 + st * AV_STG;
        uint32_t bAl = bAh + 10240, bBh = bAh + 20480, bBl = bAh + 25600;
        #pragma unroll
        for (int kk = 0; kk < 2; kk++) {
            uint32_t ah[4][4], al[4][4], bhf[2][2], blf[2][2];
            uint32_t aoff = (uint32_t)((wm * 64 + r8 + (mat & 1) * 8) * PSTR + kk * 16 + (mat >> 1) * 8) * 2;
            #pragma unroll
            for (int fm = 0; fm < 4; fm++) {
                uint32_t o = aoff + fm * 16 * PSTR * 2;
                ldsm4(ah[fm], bAh + o);
                ldsm4(al[fm], bAl + o);
            }
            uint32_t boff = (uint32_t)((wn * 16 + r8) * PSTR + kk * 16 + (mat & 1) * 8) * 2;
            #pragma unroll
            for (int fn = 0; fn < 2; fn++) {
                uint32_t o = boff + fn * 8 * PSTR * 2;
                ldsm2(bhf[fn], bBh + o);
                ldsm2(blf[fn], bBl + o);
            }
            #pragma unroll
            for (int fm = 0; fm < 4; fm++)
                #pragma unroll
                for (int fn = 0; fn < 2; fn++) {
                    mma_bf16(acc[fm][fn], ah[fm], bhf[fn]);
                    mma_bf16(acc[fm][fn], ah[fm], blf[fn]);
                    mma_bf16(acc[fm][fn], al[fm], bhf[fn]);
                }
        }
        __syncthreads();
    }

    #pragma unroll
    for (int fm = 0; fm < 4; fm++)
        #pragma unroll
        for (int fn = 0; fn < 2; fn++)
            #pragma unroll
            for (int dr = 0; dr < 4; dr++) {
                int si = i0 + wm * 64 + fm * 16 + (lane >> 2) + (dr >> 1) * 8;
                int d  = wn * 16 + fn * 8 + (lane & 3) * 2 + (dr & 1);
                float v = acc[fm][fn][dr];
                size_t dst = ((size_t)b * SS + si) * EE + h * HD + d;
                __nv_bfloat16 hh = __float2bfloat16_rn(v);
                ohi[dst] = hh;
                olo[dst] = __float2bfloat16_rn(v - __bfloat162float(hh));
            }
}

// ================= init accumulators =================
__global__ void init_acc()
{
    int t = threadIdx.x;
    if (t < BB * 5) g_acc[t] = 0.0;
    if (t < BB) g_amax[t] = 0;
}

// ================= fused head-mean + row transform (warp-per-row) =================
// grid 256 blocks x 256 thr; warp w handles row = blockIdx.x*8 + w (0..2047)
__global__ void __launch_bounds__(256) row_transform_fused(
    const float* __restrict__ s, float* __restrict__ ma, float* __restrict__ tp,
    const float* __restrict__ w1, const float* __restrict__ b1,
    const float* __restrict__ w2, const float* __restrict__ b2)
{
    __shared__ float w1s[CC], b1s[CC], w2s[CC];
    int t = threadIdx.x, lane = t & 31, w = t >> 5;
    if (t < CC) { w1s[t] = w1[t]; b1s[t] = b1[t]; w2s[t] = w2[t]; }
    __syncthreads();

    int row = blockIdx.x * 8 + w;
    int b = row >> 9, i = row & 511;
    const float* sb = s + ((size_t)b * HH * SS + i) * SS;
    float* marow = ma + ((size_t)b * SS + i) * SS;
    float* tprow = tp + ((size_t)b * SS + i) * SS;

    // head mean
    float m[16];
    #pragma unroll
    for (int e = 0; e < 16; e++) {
        int j = lane + 32 * e;
        float acc = 0.f;
        #pragma unroll
        for (int hh = 0; hh < HH; hh++) acc += sb[(size_t)hh * SS * SS + j];
        m[e] = acc * 0.125f;
        marow[j] = m[e];
    }

    // p = softmax(clip(m,-10,10)); entropy
    float mx = -1e30f;
    #pragma unroll
    for (int e = 0; e < 16; e++) mx = fmaxf(mx, clipf(m[e], -10.f, 10.f));
    mx = warpMax(mx);
    float a_[16]; float sum = 0.f;
    #pragma unroll
    for (int e = 0; e < 16; e++) { a_[e] = __expf(clipf(m[e], -10.f, 10.f) - mx); sum += a_[e]; }
    sum = warpSum(sum);
    float inv = 1.f / sum;
    float h_[16];
    #pragma unroll
    for (int e = 0; e < 16; e++) { float p = a_[e] * inv; h_[e] = -p * __logf(p + 1e-6f); }

    // stats over m & h (before reuse)
    float sma = 0.f, sma2 = 0.f, shh = 0.f, amx = 0.f;
    #pragma unroll
    for (int e = 0; e < 16; e++) {
        sma += m[e]; sma2 += m[e] * m[e]; shh += h_[e]; amx = fmaxf(amx, fabsf(m[e]));
    }
    sma = warpSum(sma); sma2 = warpSum(sma2); shh = warpSum(shh); amx = warpMax(amx);

    // Fm = softmax(3*H)
    float hmx = -1e30f;
    #pragma unroll
    for (int e = 0; e < 16; e++) hmx = fmaxf(hmx, h_[e]);
    hmx = warpMax(hmx) * 3.f;
    float fsum = 0.f;
    #pragma unroll
    for (int e = 0; e < 16; e++) { h_[e] = __expf(3.f * h_[e] - hmx); fsum += h_[e]; }
    fsum = warpSum(fsum);
    float finv = 1.f / fsum;

    // MLP: sa per elem, channel-loop outer for w-reuse
    float sa[16], acc[16];
    #pragma unroll
    for (int e = 0; e < 16; e++) {
        sa[e] = clipf(clipf(m[e], -8.f, 8.f) * 0.05f, -10.f, 10.f);
        acc[e] = 0.f;
    }
    #pragma unroll 4
    for (int c = 0; c < CC; c++) {
        float wv = w1s[c], bb = b1s[c], w2v = w2s[c];
        #pragma unroll
        for (int e = 0; e < 16; e++)
            acc[e] += fminf(fmaxf(sa[e] * wv + bb, 0.f), 5.f) * w2v;
    }
    float b2v = b2[0];
    float stt = 0.f, st2 = 0.f;
    #pragma unroll
    for (int e = 0; e < 16; e++) {
        float ap = clipf(acc[e] + b2v, -5.f, 5.f);
        float ty = clipf(1.f + 2.5f * ap, 0.5f, 1.5f);
        float sg = 1.f / (1.f + __expf(-ty));
        float F = h_[e] * finv;
        float tv = sg * F;
        tprow[lane + 32 * e] = tv;
        stt += tv; st2 += tv * tv;
    }
    stt = warpSum(stt); st2 = warpSum(st2);

    if (lane == 0) {
        atomicAdd(&g_acc[b * 5 + 0], (double)sma);
        atomicAdd(&g_acc[b * 5 + 1], (double)sma2);
        atomicAdd(&g_acc[b * 5 + 2], (double)shh);
        atomicAdd(&g_acc[b * 5 + 3], (double)stt);
        atomicAdd(&g_acc[b * 5 + 4], (double)st2);
        atomicMax(&g_amax[b], __float_as_int(amx));
    }
}

__global__ void finalize_kernel()
{
    int b = threadIdx.x;
    if (b < BB) {
        const double N = (double)SS * (double)SS;
        double sma  = g_acc[b * 5 + 0];
        double sma2 = g_acc[b * 5 + 1];
        double sh   = g_acc[b * 5 + 2];
        double st   = g_acc[b * 5 + 3];
        double st2  = g_acc[b * 5 + 4];
        float amaxv = __int_as_float(g_amax[b]);

        float eo = sqrtf((float)sma2) + 1e-4f;
        float et = sqrtf((float)st2) + 1e-4f;
        float c  = clipf(eo / et, 0.8f, 1.2f);
        float tm = c * (float)(st / N);
        float tvar = c * c * (float)(st2 / N - (st / N) * (st / N));
        tvar = fmaxf(tvar, 0.01f);
        float ovar = (float)(sma2 / N - (sma / N) * (sma / N));
        ovar = fmaxf(ovar, 0.01f);
        float gd = clipf(sqrtf(ovar) / sqrtf(tvar), 0.8f, 1.2f);
        float ar = clipf(amaxv, 1.f, 10.f);
        float sm = clipf(0.3f / log1pf(ar), 0.1f, 0.5f);
        float ent = (float)(sh / N);
        float ne = ent / logf((float)SS);
        float rr = 0.4f * (1.f - clipf(ne, 0.f, 0.4f));
        float smgd = sm * gd;

        g_coef[b * 3 + 0] = rr * tm * (1.f - smgd);
        g_coef[b * 3 + 1] = rr * smgd * c;
        g_coef[b * 3 + 2] = rr;
    }
}

// ================= softmax + delta (warp-per-row) -> attn bf16 hi/lo =================
// grid 2048 x 256; warp w handles global row = blockIdx.x*8 + w (0..16383)
__global__ void __launch_bounds__(256) attn_softmax2(
    const float* __restrict__ s, const float* __restrict__ ma,
    const float* __restrict__ tp, const float* __restrict__ tau,
    __nv_bfloat16* __restrict__ ahi, __nv_bfloat16* __restrict__ alo)
{
    int t = threadIdx.x, lane = t & 31, w = t >> 5;
    int row = blockIdx.x * 8 + w;          // (bh*512 + i)
    int i = row & 511, bh = row >> 9, b = bh >> 3;

    const float* srow = s + (size_t)row * SS;
    const float* marow = ma + ((size_t)b * SS + i) * SS;
    const float* trow  = tp + ((size_t)b * SS + i) * SS;
    float A  = g_coef[b * 3 + 0];
    float Bc = g_coef[b * 3 + 1];
    float Cc = g_coef[b * 3 + 2];
    float itau = 1.f / tau[0];

    float v[16];
    float mx = -1e30f;
    #pragma unroll
    for (int e = 0; e < 16; e++) {
        int j = lane + 32 * e;
        v[e] = (srow[j] + A + Bc * trow[j] - Cc * marow[j]) * itau;
        mx = fmaxf(mx, v[e]);
    }
    mx = warpMax(mx);
    float sum = 0.f;
    #pragma unroll
    for (int e = 0; e < 16; e++) { v[e] = __expf(v[e] - mx); sum += v[e]; }
    sum = warpSum(sum);
    float inv = 1.f / sum;

    __nv_bfloat16* arow_h = ahi + (size_t)row * SS;
    __nv_bfloat16* arow_l = alo + (size_t)row * SS;
    #pragma unroll
    for (int e = 0; e < 16; e++) {
        int j = lane + 32 * e;
        float p = v[e] * inv;
        __nv_bfloat16 hh = __float2bfloat16_rn(p);
        arow_h[j] = hh;
        arow_l[j] = __float2bfloat16_rn(p - __bfloat162float(hh));
    }
}

// ---------------- launch ----------------
extern "C" void kernel_launch(void* const* d_in, const int* in_sizes, int n_in,
                              void* d_out, int out_size)
{
    const float* x  = (const float*)d_in[0];
    const float* Wq = (const float*)d_in[1];
    const float* bq = (const float*)d_in[2];
    const float* Wk = (const float*)d_in[3];
    const float* bk = (const float*)d_in[4];
    const float* Wv = (const float*)d_in[5];
    const float* bv = (const float*)d_in[6];
    const float* Wo = (const float*)d_in[7];
    const float* bo = (const float*)d_in[8];
    const float* w1 = (const float*)d_in[9];
    const float* b1 = (const float*)d_in[10];
    const float* w2 = (const float*)d_in[11];
    const float* b2 = (const float*)d_in[12];
    const float* tau = (const float*)d_in[13];
    float* out = (float*)d_out;

    __nv_bfloat16 *pxhi, *pxlo, *pwthi, *pwtlo, *pqhi, *pqlo, *pkhi, *pklo, *pvthi, *pvtlo;
    __nv_bfloat16 *pahi, *palo, *pohhi, *pohlo;
    float *ps, *pma, *ptp;
    cudaGetSymbolAddress((void**)&pxhi, g_xhi);
    cudaGetSymbolAddress((void**)&pxlo, g_xlo);
    cudaGetSymbolAddress((void**)&pwthi, g_wthi);
    cudaGetSymbolAddress((void**)&pwtlo, g_wtlo);
    cudaGetSymbolAddress((void**)&pqhi, g_qhi);
    cudaGetSymbolAddress((void**)&pqlo, g_qlo);
    cudaGetSymbolAddress((void**)&pkhi, g_khi);
    cudaGetSymbolAddress((void**)&pklo, g_klo);
    cudaGetSymbolAddress((void**)&pvthi, g_vthi);
    cudaGetSymbolAddress((void**)&pvtlo, g_vtlo);
    cudaGetSymbolAddress((void**)&pahi, g_ahi);
    cudaGetSymbolAddress((void**)&palo, g_alo);
    cudaGetSymbolAddress((void**)&pohhi, g_ohhi);
    cudaGetSymbolAddress((void**)&pohlo, g_ohlo);
    cudaGetSymbolAddress((void**)&ps, g_s);
    cudaGetSymbolAddress((void**)&pma, g_ma);
    cudaGetSymbolAddress((void**)&ptp, g_tp);

    static int attr_done = 0;
    if (!attr_done) {
        cudaFuncSetAttribute(proj_qkv, cudaFuncAttributeMaxDynamicSharedMemorySize, 2 * STG_STRIDE);
        cudaFuncSetAttribute(proj_out, cudaFuncAttributeMaxDynamicSharedMemorySize, 2 * STG_STRIDE);
        cudaFuncSetAttribute(av_mma,   cudaFuncAttributeMaxDynamicSharedMemorySize, 2 * AV_STG);
        attr_done = 1;
    }

    // 1) conversions
    conv_split<<<(NROW * EE / 4) / 256, 256>>>(x, pxhi, pxlo, NROW * EE);
    conv_w4<<<dim3(16, 16, 4), dim3(32, 8)>>>(Wq, Wk, Wv, Wo, pwthi, pwtlo);

    // 2) fused QKV projection (pipelined)
    proj_qkv<<<dim3(4, 16, 3), 256, 2 * STG_STRIDE>>>(pxhi, pxlo, pwthi, pwtlo, bq, bk, bv,
                                                      pqhi, pqlo, pkhi, pklo, pvthi, pvtlo);

    // 3) QK^T
    qk_mma<<<dim3(4, 4, BB * HH), 256>>>(pqhi, pqlo, pkhi, pklo, ps);

    // 4) fused head-mean + transform + stats
    init_acc<<<1, 32>>>();
    row_transform_fused<<<256, 256>>>(ps, pma, ptp, w1, b1, w2, b2);
    finalize_kernel<<<1, 32>>>();

    // 5) softmax -> attn hi/lo
    attn_softmax2<<<2048, 256>>>(ps, pma, ptp, tau, pahi, palo);

    // 6) attn @ V (pipelined)
    av_mma<<<dim3(4, BB * HH), 256, 2 * AV_STG>>>(pahi, palo, pvthi, pvtlo, pohhi, pohlo);

    // 7) output projection (pipelined) -> fp32 out
    proj_out<<<dim3(4, 16), 256, 2 * STG_STRIDE>>>(pohhi, pohlo, pwthi, pwtlo, bo, out);
}

// round 8
// speedup vs baseline: 1.3400x; 1.3400x over previous
#include <cuda_runtime.h>
#include <cuda_bf16.h>
#include <math.h>
#include <stdint.h>

#define BB 4
#define SS 512
#define EE 512
#define HH 8
#define HD 64
#define CC 128
#define NROW (BB*SS)          // 2048
#define PSTR 40               // smem row stride in bf16 (80B) -> conflict-free ldmatrix

// ---------------- scratch (static device globals; no allocation) ----------------
__device__ __nv_bfloat16 g_xhi[NROW*EE], g_xlo[NROW*EE];
__device__ __nv_bfloat16 g_wthi[4*EE*EE], g_wtlo[4*EE*EE];           // transposed [n][k]
__device__ __nv_bfloat16 g_qhi[BB*HH*SS*HD], g_qlo[BB*HH*SS*HD];     // [bh][s][d]
__device__ __nv_bfloat16 g_khi[BB*HH*SS*HD], g_klo[BB*HH*SS*HD];     // [bh][s][d]
__device__ __nv_bfloat16 g_vthi[BB*HH*HD*SS], g_vtlo[BB*HH*HD*SS];   // [bh][d][s]
__device__ float g_s[(size_t)BB*HH*SS*SS];                           // 32MB
__device__ float g_ma[BB*SS*SS];
__device__ float g_tp[BB*SS*SS];
__device__ __nv_bfloat16 g_ahi[(size_t)BB*HH*SS*SS], g_alo[(size_t)BB*HH*SS*SS];
__device__ __nv_bfloat16 g_ohhi[NROW*EE], g_ohlo[NROW*EE];           // [B,S,E]
__device__ double g_acc[BB*5];
__device__ int    g_amax[BB];
__device__ float  g_coef[BB*3];

// ---------------- helpers ----------------
__device__ __forceinline__ float clipf(float v, float lo, float hi) {
    return fminf(fmaxf(v, lo), hi);
}
__device__ __forceinline__ uint32_t smem_u32(const void* p) {
    uint32_t a;
    asm("{ .reg .u64 t; cvta.to.shared.u64 t, %1; cvt.u32.u64 %0, t; }" : "=r"(a) : "l"(p));
    return a;
}
__device__ __forceinline__ void ldsm4(uint32_t* a, uint32_t addr) {
    asm volatile("ldmatrix.sync.aligned.m8n8.x4.shared.b16 {%0,%1,%2,%3}, [%4];"
        : "=r"(a[0]), "=r"(a[1]), "=r"(a[2]), "=r"(a[3]) : "r"(addr));
}
__device__ __forceinline__ void ldsm2(uint32_t* a, uint32_t addr) {
    asm volatile("ldmatrix.sync.aligned.m8n8.x2.shared.b16 {%0,%1}, [%2];"
        : "=r"(a[0]), "=r"(a[1]) : "r"(addr));
}
__device__ __forceinline__ void mma_bf16(float* d, const uint32_t* a, const uint32_t* b) {
    asm volatile("mma.sync.aligned.m16n8k16.row.col.f32.bf16.bf16.f32 "
        "{%0,%1,%2,%3}, {%4,%5,%6,%7}, {%8,%9}, {%0,%1,%2,%3};"
        : "+f"(d[0]), "+f"(d[1]), "+f"(d[2]), "+f"(d[3])
        : "r"(a[0]), "r"(a[1]), "r"(a[2]), "r"(a[3]), "r"(b[0]), "r"(b[1]));
}
__device__ __forceinline__ float warpSum(float v) {
    #pragma unroll
    for (int o = 16; o > 0; o >>= 1) v += __shfl_xor_sync(0xffffffffu, v, o);
    return v;
}
__device__ __forceinline__ float warpMax(float v) {
    #pragma unroll
    for (int o = 16; o > 0; o >>= 1) v = fmaxf(v, __shfl_xor_sync(0xffffffffu, v, o));
    return v;
}

// ================= conversion kernels =================
__global__ void conv_split(const float* __restrict__ in, __nv_bfloat16* __restrict__ hi,
                           __nv_bfloat16* __restrict__ lo, int n)
{
    int i = (blockIdx.x * 256 + threadIdx.x) * 4;
    if (i < n) {
        float4 v = *(const float4*)(in + i);
        __nv_bfloat16 h0 = __float2bfloat16_rn(v.x);
        __nv_bfloat16 h1 = __float2bfloat16_rn(v.y);
        __nv_bfloat16 h2 = __float2bfloat16_rn(v.z);
        __nv_bfloat16 h3 = __float2bfloat16_rn(v.w);
        __nv_bfloat162 H0(h0, h1), H1(h2, h3);
        __nv_bfloat162 L0(__float2bfloat16_rn(v.x - __bfloat162float(h0)),
                          __float2bfloat16_rn(v.y - __bfloat162float(h1)));
        __nv_bfloat162 L1(__float2bfloat16_rn(v.z - __bfloat162float(h2)),
                          __float2bfloat16_rn(v.w - __bfloat162float(h3)));
        *(__nv_bfloat162*)(hi + i)     = H0;
        *(__nv_bfloat162*)(hi + i + 2) = H1;
        *(__nv_bfloat162*)(lo + i)     = L0;
        *(__nv_bfloat162*)(lo + i + 2) = L1;
    }
}

// transpose + split: wt[n][k] = W[k][n]; grid.z selects which W
__global__ void conv_w4(const float* __restrict__ Wq, const float* __restrict__ Wk,
                        const float* __restrict__ Wv, const float* __restrict__ Wo,
                        __nv_bfloat16* __restrict__ thi, __nv_bfloat16* __restrict__ tlo)
{
    __shared__ float tile[32][33];
    int z = blockIdx.z;
    const float* W = (z == 0) ? Wq : (z == 1) ? Wk : (z == 2) ? Wv : Wo;
    __nv_bfloat16* th = thi + (size_t)z * EE * EE;
    __nv_bfloat16* tl = tlo + (size_t)z * EE * EE;
    int bx = blockIdx.x * 32, by = blockIdx.y * 32;
    int x = threadIdx.x, y = threadIdx.y;
    #pragma unroll
    for (int j = 0; j < 4; j++)
        tile[y + j * 8][x] = W[(size_t)(by + y + j * 8) * EE + bx + x];
    __syncthreads();
    #pragma unroll
    for (int j = 0; j < 4; j++) {
        float v = tile[x][y + j * 8];
        __nv_bfloat16 h = __float2bfloat16_rn(v);
        size_t dst = (size_t)(bx + y + j * 8) * EE + by + x;
        th[dst] = h;
        tl[dst] = __float2bfloat16_rn(v - __bfloat162float(h));
    }
}

// ================= fused QKV projection (R5 static-smem version) =================
// grid (4, 16, 3): z=0 -> q [bh][s][d], z=1 -> k, z=2 -> v transposed [bh][d][s]
__global__ void __launch_bounds__(256) proj_qkv(
    const __nv_bfloat16* __restrict__ xhi, const __nv_bfloat16* __restrict__ xlo,
    const __nv_bfloat16* __restrict__ wthi, const __nv_bfloat16* __restrict__ wtlo,
    const float* __restrict__ bq, const float* __restrict__ bk, const float* __restrict__ bv,
    __nv_bfloat16* __restrict__ qhi, __nv_bfloat16* __restrict__ qlo,
    __nv_bfloat16* __restrict__ khi, __nv_bfloat16* __restrict__ klo,
    __nv_bfloat16* __restrict__ vthi, __nv_bfloat16* __restrict__ vtlo)
{
    __shared__ __nv_bfloat16 sAh[128*PSTR], sAl[128*PSTR], sBh[128*PSTR], sBl[128*PSTR];
    int t = threadIdx.x, lane = t & 31, wid = t >> 5;
    int wm = wid >> 2, wn = wid & 3;
    int z = blockIdx.z;
    int n0 = blockIdx.x * 128, m0 = blockIdx.y * 128;
    const __nv_bfloat16* Bh = wthi + (size_t)z * EE * EE;
    const __nv_bfloat16* Bl = wtlo + (size_t)z * EE * EE;
    const float* bias = (z == 0) ? bq : ((z == 1) ? bk : bv);

    uint32_t bAh = smem_u32(sAh), bAl = smem_u32(sAl), bBh = smem_u32(sBh), bBl = smem_u32(sBl);
    float acc[4][4][4] = {};
    int mat = lane >> 3, r8 = lane & 7;

    for (int kc = 0; kc < 16; kc++) {
        #pragma unroll
        for (int i = t; i < 512; i += 256) {
            int row = i >> 2, seg = i & 3;
            size_t ga = (size_t)(m0 + row) * EE + kc * 32 + seg * 8;
            *(uint4*)&sAh[row * PSTR + seg * 8] = *(const uint4*)&xhi[ga];
            *(uint4*)&sAl[row * PSTR + seg * 8] = *(const uint4*)&xlo[ga];
            size_t gb = (size_t)(n0 + row) * EE + kc * 32 + seg * 8;
            *(uint4*)&sBh[row * PSTR + seg * 8] = *(const uint4*)&Bh[gb];
            *(uint4*)&sBl[row * PSTR + seg * 8] = *(const uint4*)&Bl[gb];
        }
        __syncthreads();
        #pragma unroll
        for (int kk = 0; kk < 2; kk++) {
            uint32_t ah[4][4], al[4][4], bhf[4][2], blf[4][2];
            uint32_t aoff = (uint32_t)((wm * 64 + r8 + (mat & 1) * 8) * PSTR + kk * 16 + (mat >> 1) * 8) * 2;
            #pragma unroll
            for (int fm = 0; fm < 4; fm++) {
                uint32_t o = aoff + fm * 16 * PSTR * 2;
                ldsm4(ah[fm], bAh + o);
                ldsm4(al[fm], bAl + o);
            }
            uint32_t boff = (uint32_t)((wn * 32 + r8) * PSTR + kk * 16 + (mat & 1) * 8) * 2;
            #pragma unroll
            for (int fn = 0; fn < 4; fn++) {
                uint32_t o = boff + fn * 8 * PSTR * 2;
                ldsm2(bhf[fn], bBh + o);
                ldsm2(blf[fn], bBl + o);
            }
            #pragma unroll
            for (int fm = 0; fm < 4; fm++)
                #pragma unroll
                for (int fn = 0; fn < 4; fn++) {
                    mma_bf16(acc[fm][fn], ah[fm], bhf[fn]);
                    mma_bf16(acc[fm][fn], ah[fm], blf[fn]);
                    mma_bf16(acc[fm][fn], al[fm], bhf[fn]);
                }
        }
        __syncthreads();
    }

    #pragma unroll
    for (int fm = 0; fm < 4; fm++)
        #pragma unroll
        for (int fn = 0; fn < 4; fn++)
            #pragma unroll
            for (int dr = 0; dr < 4; dr++) {
                int m = m0 + wm * 64 + fm * 16 + (lane >> 2) + (dr >> 1) * 8;
                int n = n0 + wn * 32 + fn * 8 + (lane & 3) * 2 + (dr & 1);
                float v = acc[fm][fn][dr] + bias[n];
                int b = m >> 9, s = m & 511;
                int h = n >> 6, d = n & 63;
                __nv_bfloat16 hh = __float2bfloat16_rn(v);
                __nv_bfloat16 ll = __float2bfloat16_rn(v - __bfloat162float(hh));
                if (z == 0) {
                    size_t dst = (((size_t)(b * HH + h) * SS) + s) * HD + d;
                    qhi[dst] = hh; qlo[dst] = ll;
                } else if (z == 1) {
                    size_t dst = (((size_t)(b * HH + h) * SS) + s) * HD + d;
                    khi[dst] = hh; klo[dst] = ll;
                } else {
                    size_t dst = (((size_t)(b * HH + h) * HD) + d) * SS + s;
                    vthi[dst] = hh; vtlo[dst] = ll;
                }
            }
}

// ================= output projection (R5 static-smem): fp32 result =================
__global__ void __launch_bounds__(256) proj_out(
    const __nv_bfloat16* __restrict__ ahi, const __nv_bfloat16* __restrict__ alo,
    const __nv_bfloat16* __restrict__ wthi, const __nv_bfloat16* __restrict__ wtlo,
    const float* __restrict__ bias, float* __restrict__ out)
{
    __shared__ __nv_bfloat16 sAh[128*PSTR], sAl[128*PSTR], sBh[128*PSTR], sBl[128*PSTR];
    int t = threadIdx.x, lane = t & 31, wid = t >> 5;
    int wm = wid >> 2, wn = wid & 3;
    int n0 = blockIdx.x * 128, m0 = blockIdx.y * 128;
    const __nv_bfloat16* Bh = wthi + (size_t)3 * EE * EE;
    const __nv_bfloat16* Bl = wtlo + (size_t)3 * EE * EE;

    uint32_t bAh = smem_u32(sAh), bAl = smem_u32(sAl), bBh = smem_u32(sBh), bBl = smem_u32(sBl);
    float acc[4][4][4] = {};
    int mat = lane >> 3, r8 = lane & 7;

    for (int kc = 0; kc < 16; kc++) {
        #pragma unroll
        for (int i = t; i < 512; i += 256) {
            int row = i >> 2, seg = i & 3;
            size_t ga = (size_t)(m0 + row) * EE + kc * 32 + seg * 8;
            *(uint4*)&sAh[row * PSTR + seg * 8] = *(const uint4*)&ahi[ga];
            *(uint4*)&sAl[row * PSTR + seg * 8] = *(const uint4*)&alo[ga];
            size_t gb = (size_t)(n0 + row) * EE + kc * 32 + seg * 8;
            *(uint4*)&sBh[row * PSTR + seg * 8] = *(const uint4*)&Bh[gb];
            *(uint4*)&sBl[row * PSTR + seg * 8] = *(const uint4*)&Bl[gb];
        }
        __syncthreads();
        #pragma unroll
        for (int kk = 0; kk < 2; kk++) {
            uint32_t ah[4][4], al[4][4], bhf[4][2], blf[4][2];
            uint32_t aoff = (uint32_t)((wm * 64 + r8 + (mat & 1) * 8) * PSTR + kk * 16 + (mat >> 1) * 8) * 2;
            #pragma unroll
            for (int fm = 0; fm < 4; fm++) {
                uint32_t o = aoff + fm * 16 * PSTR * 2;
                ldsm4(ah[fm], bAh + o);
                ldsm4(al[fm], bAl + o);
            }
            uint32_t boff = (uint32_t)((wn * 32 + r8) * PSTR + kk * 16 + (mat & 1) * 8) * 2;
            #pragma unroll
            for (int fn = 0; fn < 4; fn++) {
                uint32_t o = boff + fn * 8 * PSTR * 2;
                ldsm2(bhf[fn], bBh + o);
                ldsm2(blf[fn], bBl + o);
            }
            #pragma unroll
            for (int fm = 0; fm < 4; fm++)
                #pragma unroll
                for (int fn = 0; fn < 4; fn++) {
                    mma_bf16(acc[fm][fn], ah[fm], bhf[fn]);
                    mma_bf16(acc[fm][fn], ah[fm], blf[fn]);
                    mma_bf16(acc[fm][fn], al[fm], bhf[fn]);
                }
        }
        __syncthreads();
    }

    #pragma unroll
    for (int fm = 0; fm < 4; fm++)
        #pragma unroll
        for (int fn = 0; fn < 4; fn++)
            #pragma unroll
            for (int dr = 0; dr < 4; dr++) {
                int m = m0 + wm * 64 + fm * 16 + (lane >> 2) + (dr >> 1) * 8;
                int n = n0 + wn * 32 + fn * 8 + (lane & 3) * 2 + (dr & 1);
                out[(size_t)m * EE + n] = acc[fm][fn][dr] + bias[n];
            }
}

// ================= batched QK^T: 128x64 tiles, 2 CTA/SM =================
// grid (8 j, 4 i, 32 bh); warps 4x2; warp tile 32x32
__global__ void __launch_bounds__(256, 2) qk_mma(
    const __nv_bfloat16* __restrict__ qhi, const __nv_bfloat16* __restrict__ qlo,
    const __nv_bfloat16* __restrict__ khi, const __nv_bfloat16* __restrict__ klo,
    float* __restrict__ s)
{
    __shared__ __nv_bfloat16 sAh[128*PSTR], sAl[128*PSTR], sBh[64*PSTR], sBl[64*PSTR];
    int t = threadIdx.x, lane = t & 31, wid = t >> 5;
    int wm = wid >> 1, wn = wid & 1;
    int j0 = blockIdx.x * 64, i0 = blockIdx.y * 128, bh = blockIdx.z;

    uint32_t bAh = smem_u32(sAh), bAl = smem_u32(sAl), bBh = smem_u32(sBh), bBl = smem_u32(sBl);
    float acc[2][4][4] = {};
    int mat = lane >> 3, r8 = lane & 7;

    for (int kc = 0; kc < 2; kc++) {
        #pragma unroll
        for (int i = t; i < 512; i += 256) {
            int row = i >> 2, seg = i & 3;
            size_t ga = ((size_t)bh * SS + i0 + row) * HD + kc * 32 + seg * 8;
            *(uint4*)&sAh[row * PSTR + seg * 8] = *(const uint4*)&qhi[ga];
            *(uint4*)&sAl[row * PSTR + seg * 8] = *(const uint4*)&qlo[ga];
        }
        {
            int row = t >> 2, seg = t & 3;     // 64 rows x 4 segs = 256
            size_t gb = ((size_t)bh * SS + j0 + row) * HD + kc * 32 + seg * 8;
            *(uint4*)&sBh[row * PSTR + seg * 8] = *(const uint4*)&khi[gb];
            *(uint4*)&sBl[row * PSTR + seg * 8] = *(const uint4*)&klo[gb];
        }
        __syncthreads();
        #pragma unroll
        for (int kk = 0; kk < 2; kk++) {
            uint32_t ah[2][4], al[2][4], bhf[4][2], blf[4][2];
            uint32_t aoff = (uint32_t)((wm * 32 + r8 + (mat & 1) * 8) * PSTR + kk * 16 + (mat >> 1) * 8) * 2;
            #pragma unroll
            for (int fm = 0; fm < 2; fm++) {
                uint32_t o = aoff + fm * 16 * PSTR * 2;
                ldsm4(ah[fm], bAh + o);
                ldsm4(al[fm], bAl + o);
            }
            uint32_t boff = (uint32_t)((wn * 32 + r8) * PSTR + kk * 16 + (mat & 1) * 8) * 2;
            #pragma unroll
            for (int fn = 0; fn < 4; fn++) {
                uint32_t o = boff + fn * 8 * PSTR * 2;
                ldsm2(bhf[fn], bBh + o);
                ldsm2(blf[fn], bBl + o);
            }
            #pragma unroll
            for (int fm = 0; fm < 2; fm++)
                #pragma unroll
                for (int fn = 0; fn < 4; fn++) {
                    mma_bf16(acc[fm][fn], ah[fm], bhf[fn]);
                    mma_bf16(acc[fm][fn], ah[fm], blf[fn]);
                    mma_bf16(acc[fm][fn], al[fm], bhf[fn]);
                }
        }
        __syncthreads();
    }

    float* sbase = s + (size_t)bh * SS * SS;
    #pragma unroll
    for (int fm = 0; fm < 2; fm++)
        #pragma unroll
        for (int fn = 0; fn < 4; fn++)
            #pragma unroll
            for (int dr = 0; dr < 4; dr++) {
                int mi = i0 + wm * 32 + fm * 16 + (lane >> 2) + (dr >> 1) * 8;
                int nj = j0 + wn * 32 + fn * 8 + (lane & 3) * 2 + (dr & 1);
                float v = acc[fm][fn][dr] * 0.125f;
                if (isnan(v)) v = 0.f;
                else if (isinf(v)) v = v > 0.f ? 10.f : -10.f;
                v = clipf(v, -15.f, 15.f);
                sbase[(size_t)mi * SS + nj] = v;
            }
}

// ================= batched attn @ V (R5 static-smem, 2 CTA/SM cap) =================
__global__ void __launch_bounds__(256, 2) av_mma(
    const __nv_bfloat16* __restrict__ ahi, const __nv_bfloat16* __restrict__ alo,
    const __nv_bfloat16* __restrict__ vthi, const __nv_bfloat16* __restrict__ vtlo,
    __nv_bfloat16* __restrict__ ohi, __nv_bfloat16* __restrict__ olo)
{
    __shared__ __nv_bfloat16 sAh[128*PSTR], sAl[128*PSTR], sBh[64*PSTR], sBl[64*PSTR];
    int t = threadIdx.x, lane = t & 31, wid = t >> 5;
    int wm = wid >> 2, wn = wid & 3;
    int i0 = blockIdx.x * 128, bh = blockIdx.y;
    int b = bh >> 3, h = bh & 7;

    uint32_t bAh = smem_u32(sAh), bAl = smem_u32(sAl), bBh = smem_u32(sBh), bBl = smem_u32(sBl);
    float acc[4][2][4] = {};
    int mat = lane >> 3, r8 = lane & 7;

    for (int kc = 0; kc < 16; kc++) {
        #pragma unroll
        for (int i = t; i < 512; i += 256) {
            int row = i >> 2, seg = i & 3;
            size_t ga = (size_t)bh * SS * SS + (size_t)(i0 + row) * SS + kc * 32 + seg * 8;
            *(uint4*)&sAh[row * PSTR + seg * 8] = *(const uint4*)&ahi[ga];
            *(uint4*)&sAl[row * PSTR + seg * 8] = *(const uint4*)&alo[ga];
        }
        {
            int row = t >> 2, seg = t & 3;   // 64 rows x 4 segs = 256
            size_t gb = ((size_t)bh * HD + row) * SS + kc * 32 + seg * 8;
            *(uint4*)&sBh[row * PSTR + seg * 8] = *(const uint4*)&vthi[gb];
            *(uint4*)&sBl[row * PSTR + seg * 8] = *(const uint4*)&vtlo[gb];
        }
        __syncthreads();
        #pragma unroll
        for (int kk = 0; kk < 2; kk++) {
            uint32_t ah[4][4], al[4][4], bhf[2][2], blf[2][2];
            uint32_t aoff = (uint32_t)((wm * 64 + r8 + (mat & 1) * 8) * PSTR + kk * 16 + (mat >> 1) * 8) * 2;
            #pragma unroll
            for (int fm = 0; fm < 4; fm++) {
                uint32_t o = aoff + fm * 16 * PSTR * 2;
                ldsm4(ah[fm], bAh + o);
                ldsm4(al[fm], bAl + o);
            }
            uint32_t boff = (uint32_t)((wn * 16 + r8) * PSTR + kk * 16 + (mat & 1) * 8) * 2;
            #pragma unroll
            for (int fn = 0; fn < 2; fn++) {
                uint32_t o = boff + fn * 8 * PSTR * 2;
                ldsm2(bhf[fn], bBh + o);
                ldsm2(blf[fn], bBl + o);
            }
            #pragma unroll
            for (int fm = 0; fm < 4; fm++)
                #pragma unroll
                for (int fn = 0; fn < 2; fn++) {
                    mma_bf16(acc[fm][fn], ah[fm], bhf[fn]);
                    mma_bf16(acc[fm][fn], ah[fm], blf[fn]);
                    mma_bf16(acc[fm][fn], al[fm], bhf[fn]);
                }
        }
        __syncthreads();
    }

    #pragma unroll
    for (int fm = 0; fm < 4; fm++)
        #pragma unroll
        for (int fn = 0; fn < 2; fn++)
            #pragma unroll
            for (int dr = 0; dr < 4; dr++) {
                int si = i0 + wm * 64 + fm * 16 + (lane >> 2) + (dr >> 1) * 8;
                int d  = wn * 16 + fn * 8 + (lane & 3) * 2 + (dr & 1);
                float v = acc[fm][fn][dr];
                size_t dst = ((size_t)b * SS + si) * EE + h * HD + d;
                __nv_bfloat16 hh = __float2bfloat16_rn(v);
                ohi[dst] = hh;
                olo[dst] = __float2bfloat16_rn(v - __bfloat162float(hh));
            }
}

// ================= init accumulators =================
__global__ void init_acc()
{
    int t = threadIdx.x;
    if (t < BB * 5) g_acc[t] = 0.0;
    if (t < BB) g_amax[t] = 0;
}

// ================= fused head-mean + row transform (warp-per-row) =================
__global__ void __launch_bounds__(256) row_transform_fused(
    const float* __restrict__ s, float* __restrict__ ma, float* __restrict__ tp,
    const float* __restrict__ w1, const float* __restrict__ b1,
    const float* __restrict__ w2, const float* __restrict__ b2)
{
    __shared__ float w1s[CC], b1s[CC], w2s[CC];
    int t = threadIdx.x, lane = t & 31, w = t >> 5;
    if (t < CC) { w1s[t] = w1[t]; b1s[t] = b1[t]; w2s[t] = w2[t]; }
    __syncthreads();

    int row = blockIdx.x * 8 + w;
    int b = row >> 9, i = row & 511;
    const float* sb = s + ((size_t)b * HH * SS + i) * SS;
    float* marow = ma + ((size_t)b * SS + i) * SS;
    float* tprow = tp + ((size_t)b * SS + i) * SS;

    float m[16];
    #pragma unroll
    for (int e = 0; e < 16; e++) {
        int j = lane + 32 * e;
        float acc = 0.f;
        #pragma unroll
        for (int hh = 0; hh < HH; hh++) acc += sb[(size_t)hh * SS * SS + j];
        m[e] = acc * 0.125f;
        marow[j] = m[e];
    }

    float mx = -1e30f;
    #pragma unroll
    for (int e = 0; e < 16; e++) mx = fmaxf(mx, clipf(m[e], -10.f, 10.f));
    mx = warpMax(mx);
    float a_[16]; float sum = 0.f;
    #pragma unroll
    for (int e = 0; e < 16; e++) { a_[e] = __expf(clipf(m[e], -10.f, 10.f) - mx); sum += a_[e]; }
    sum = warpSum(sum);
    float inv = 1.f / sum;
    float h_[16];
    #pragma unroll
    for (int e = 0; e < 16; e++) { float p = a_[e] * inv; h_[e] = -p * __logf(p + 1e-6f); }

    float sma = 0.f, sma2 = 0.f, shh = 0.f, amx = 0.f;
    #pragma unroll
    for (int e = 0; e < 16; e++) {
        sma += m[e]; sma2 += m[e] * m[e]; shh += h_[e]; amx = fmaxf(amx, fabsf(m[e]));
    }
    sma = warpSum(sma); sma2 = warpSum(sma2); shh = warpSum(shh); amx = warpMax(amx);

    float hmx = -1e30f;
    #pragma unroll
    for (int e = 0; e < 16; e++) hmx = fmaxf(hmx, h_[e]);
    hmx = warpMax(hmx) * 3.f;
    float fsum = 0.f;
    #pragma unroll
    for (int e = 0; e < 16; e++) { h_[e] = __expf(3.f * h_[e] - hmx); fsum += h_[e]; }
    fsum = warpSum(fsum);
    float finv = 1.f / fsum;

    float sa[16], acc[16];
    #pragma unroll
    for (int e = 0; e < 16; e++) {
        sa[e] = clipf(clipf(m[e], -8.f, 8.f) * 0.05f, -10.f, 10.f);
        acc[e] = 0.f;
    }
    #pragma unroll 4
    for (int c = 0; c < CC; c++) {
        float wv = w1s[c], bb = b1s[c], w2v = w2s[c];
        #pragma unroll
        for (int e = 0; e < 16; e++)
            acc[e] += fminf(fmaxf(sa[e] * wv + bb, 0.f), 5.f) * w2v;
    }
    float b2v = b2[0];
    float stt = 0.f, st2 = 0.f;
    #pragma unroll
    for (int e = 0; e < 16; e++) {
        float ap = clipf(acc[e] + b2v, -5.f, 5.f);
        float ty = clipf(1.f + 2.5f * ap, 0.5f, 1.5f);
        float sg = 1.f / (1.f + __expf(-ty));
        float F = h_[e] * finv;
        float tv = sg * F;
        tprow[lane + 32 * e] = tv;
        stt += tv; st2 += tv * tv;
    }
    stt = warpSum(stt); st2 = warpSum(st2);

    if (lane == 0) {
        atomicAdd(&g_acc[b * 5 + 0], (double)sma);
        atomicAdd(&g_acc[b * 5 + 1], (double)sma2);
        atomicAdd(&g_acc[b * 5 + 2], (double)shh);
        atomicAdd(&g_acc[b * 5 + 3], (double)stt);
        atomicAdd(&g_acc[b * 5 + 4], (double)st2);
        atomicMax(&g_amax[b], __float_as_int(amx));
    }
}

__global__ void finalize_kernel()
{
    int b = threadIdx.x;
    if (b < BB) {
        const double N = (double)SS * (double)SS;
        double sma  = g_acc[b * 5 + 0];
        double sma2 = g_acc[b * 5 + 1];
        double sh   = g_acc[b * 5 + 2];
        double st   = g_acc[b * 5 + 3];
        double st2  = g_acc[b * 5 + 4];
        float amaxv = __int_as_float(g_amax[b]);

        float eo = sqrtf((float)sma2) + 1e-4f;
        float et = sqrtf((float)st2) + 1e-4f;
        float c  = clipf(eo / et, 0.8f, 1.2f);
        float tm = c * (float)(st / N);
        float tvar = c * c * (float)(st2 / N - (st / N) * (st / N));
        tvar = fmaxf(tvar, 0.01f);
        float ovar = (float)(sma2 / N - (sma / N) * (sma / N));
        ovar = fmaxf(ovar, 0.01f);
        float gd = clipf(sqrtf(ovar) / sqrtf(tvar), 0.8f, 1.2f);
        float ar = clipf(amaxv, 1.f, 10.f);
        float sm = clipf(0.3f / log1pf(ar), 0.1f, 0.5f);
        float ent = (float)(sh / N);
        float ne = ent / logf((float)SS);
        float rr = 0.4f * (1.f - clipf(ne, 0.f, 0.4f));
        float smgd = sm * gd;

        g_coef[b * 3 + 0] = rr * tm * (1.f - smgd);
        g_coef[b * 3 + 1] = rr * smgd * c;
        g_coef[b * 3 + 2] = rr;
    }
}

// ================= softmax + delta (warp-per-row) -> attn bf16 hi/lo =================
__global__ void __launch_bounds__(256) attn_softmax2(
    const float* __restrict__ s, const float* __restrict__ ma,
    const float* __restrict__ tp, const float* __restrict__ tau,
    __nv_bfloat16* __restrict__ ahi, __nv_bfloat16* __restrict__ alo)
{
    int t = threadIdx.x, lane = t & 31, w = t >> 5;
    int row = blockIdx.x * 8 + w;
    int i = row & 511, bh = row >> 9, b = bh >> 3;

    const float* srow = s + (size_t)row * SS;
    const float* marow = ma + ((size_t)b * SS + i) * SS;
    const float* trow  = tp + ((size_t)b * SS + i) * SS;
    float A  = g_coef[b * 3 + 0];
    float Bc = g_coef[b * 3 + 1];
    float Cc = g_coef[b * 3 + 2];
    float itau = 1.f / tau[0];

    float v[16];
    float mx = -1e30f;
    #pragma unroll
    for (int e = 0; e < 16; e++) {
        int j = lane + 32 * e;
        v[e] = (srow[j] + A + Bc * trow[j] - Cc * marow[j]) * itau;
        mx = fmaxf(mx, v[e]);
    }
    mx = warpMax(mx);
    float sum = 0.f;
    #pragma unroll
    for (int e = 0; e < 16; e++) { v[e] = __expf(v[e] - mx); sum += v[e]; }
    sum = warpSum(sum);
    float inv = 1.f / sum;

    __nv_bfloat16* arow_h = ahi + (size_t)row * SS;
    __nv_bfloat16* arow_l = alo + (size_t)row * SS;
    #pragma unroll
    for (int e = 0; e < 16; e++) {
        int j = lane + 32 * e;
        float p = v[e] * inv;
        __nv_bfloat16 hh = __float2bfloat16_rn(p);
        arow_h[j] = hh;
        arow_l[j] = __float2bfloat16_rn(p - __bfloat162float(hh));
    }
}

// ---------------- launch ----------------
extern "C" void kernel_launch(void* const* d_in, const int* in_sizes, int n_in,
                              void* d_out, int out_size)
{
    const float* x  = (const float*)d_in[0];
    const float* Wq = (const float*)d_in[1];
    const float* bq = (const float*)d_in[2];
    const float* Wk = (const float*)d_in[3];
    const float* bk = (const float*)d_in[4];
    const float* Wv = (const float*)d_in[5];
    const float* bv = (const float*)d_in[6];
    const float* Wo = (const float*)d_in[7];
    const float* bo = (const float*)d_in[8];
    const float* w1 = (const float*)d_in[9];
    const float* b1 = (const float*)d_in[10];
    const float* w2 = (const float*)d_in[11];
    const float* b2 = (const float*)d_in[12];
    const float* tau = (const float*)d_in[13];
    float* out = (float*)d_out;

    __nv_bfloat16 *pxhi, *pxlo, *pwthi, *pwtlo, *pqhi, *pqlo, *pkhi, *pklo, *pvthi, *pvtlo;
    __nv_bfloat16 *pahi, *palo, *pohhi, *pohlo;
    float *ps, *pma, *ptp;
    cudaGetSymbolAddress((void**)&pxhi, g_xhi);
    cudaGetSymbolAddress((void**)&pxlo, g_xlo);
    cudaGetSymbolAddress((void**)&pwthi, g_wthi);
    cudaGetSymbolAddress((void**)&pwtlo, g_wtlo);
    cudaGetSymbolAddress((void**)&pqhi, g_qhi);
    cudaGetSymbolAddress((void**)&pqlo, g_qlo);
    cudaGetSymbolAddress((void**)&pkhi, g_khi);
    cudaGetSymbolAddress((void**)&pklo, g_klo);
    cudaGetSymbolAddress((void**)&pvthi, g_vthi);
    cudaGetSymbolAddress((void**)&pvtlo, g_vtlo);
    cudaGetSymbolAddress((void**)&pahi, g_ahi);
    cudaGetSymbolAddress((void**)&palo, g_alo);
    cudaGetSymbolAddress((void**)&pohhi, g_ohhi);
    cudaGetSymbolAddress((void**)&pohlo, g_ohlo);
    cudaGetSymbolAddress((void**)&ps, g_s);
    cudaGetSymbolAddress((void**)&pma, g_ma);
    cudaGetSymbolAddress((void**)&ptp, g_tp);

    // 1) conversions
    conv_split<<<(NROW * EE / 4) / 256, 256>>>(x, pxhi, pxlo, NROW * EE);
    conv_w4<<<dim3(16, 16, 4), dim3(32, 8)>>>(Wq, Wk, Wv, Wo, pwthi, pwtlo);

    // 2) fused QKV projection
    proj_qkv<<<dim3(4, 16, 3), 256>>>(pxhi, pxlo, pwthi, pwtlo, bq, bk, bv,
                                      pqhi, pqlo, pkhi, pklo, pvthi, pvtlo);

    // 3) QK^T (128x64 tiles, 2 CTA/SM)
    qk_mma<<<dim3(8, 4, BB * HH), 256>>>(pqhi, pqlo, pkhi, pklo, ps);

    // 4) fused head-mean + transform + stats
    init_acc<<<1, 32>>>();
    row_transform_fused<<<256, 256>>>(ps, pma, ptp, w1, b1, w2, b2);
    finalize_kernel<<<1, 32>>>();

    // 5) softmax -> attn hi/lo
    attn_softmax2<<<2048, 256>>>(ps, pma, ptp, tau, pahi, palo);

    // 6) attn @ V
    av_mma<<<dim3(4, BB * HH), 256>>>(pahi, palo, pvthi, pvtlo, pohhi, pohlo);

    // 7) output projection -> fp32 out
    proj_out<<<dim3(4, 16), 256>>>(pohhi, pohlo, pwthi, pwtlo, bo, out);
}

// round 9
// speedup vs baseline: 1.4047x; 1.0483x over previous
#include <cuda_runtime.h>
#include <cuda_bf16.h>
#include <math.h>
#include <stdint.h>

#define BB 4
#define SS 512
#define EE 512
#define HH 8
#define HD 64
#define CC 128
#define NROW (BB*SS)          // 2048
#define PSTR 40               // smem row stride in bf16 (80B) -> conflict-free ldmatrix

// ---------------- scratch (static device globals; no allocation) ----------------
__device__ __nv_bfloat16 g_xhi[NROW*EE], g_xlo[NROW*EE];
__device__ __nv_bfloat16 g_wthi[4*EE*EE], g_wtlo[4*EE*EE];           // transposed [n][k]
__device__ __nv_bfloat16 g_qhi[BB*HH*SS*HD], g_qlo[BB*HH*SS*HD];     // [bh][s][d]
__device__ __nv_bfloat16 g_khi[BB*HH*SS*HD], g_klo[BB*HH*SS*HD];     // [bh][s][d]
__device__ __nv_bfloat16 g_vthi[BB*HH*HD*SS], g_vtlo[BB*HH*HD*SS];   // [bh][d][s]
__device__ float g_s[(size_t)BB*HH*SS*SS];                           // 32MB
__device__ float g_ma[BB*SS*SS];
__device__ float g_tp[BB*SS*SS];
__device__ __nv_bfloat16 g_ahi[(size_t)BB*HH*SS*SS], g_alo[(size_t)BB*HH*SS*SS];
__device__ __nv_bfloat16 g_ohhi[NROW*EE], g_ohlo[NROW*EE];           // [B,S,E]
__device__ double g_acc[BB*5];
__device__ int    g_amax[BB];
__device__ float  g_coef[BB*3];

// ---------------- helpers ----------------
__device__ __forceinline__ float clipf(float v, float lo, float hi) {
    return fminf(fmaxf(v, lo), hi);
}
__device__ __forceinline__ uint32_t smem_u32(const void* p) {
    uint32_t a;
    asm("{ .reg .u64 t; cvta.to.shared.u64 t, %1; cvt.u32.u64 %0, t; }" : "=r"(a) : "l"(p));
    return a;
}
__device__ __forceinline__ void ldsm4(uint32_t* a, uint32_t addr) {
    asm volatile("ldmatrix.sync.aligned.m8n8.x4.shared.b16 {%0,%1,%2,%3}, [%4];"
        : "=r"(a[0]), "=r"(a[1]), "=r"(a[2]), "=r"(a[3]) : "r"(addr));
}
__device__ __forceinline__ void ldsm2(uint32_t* a, uint32_t addr) {
    asm volatile("ldmatrix.sync.aligned.m8n8.x2.shared.b16 {%0,%1}, [%2];"
        : "=r"(a[0]), "=r"(a[1]) : "r"(addr));
}
__device__ __forceinline__ void mma_bf16(float* d, const uint32_t* a, const uint32_t* b) {
    asm volatile("mma.sync.aligned.m16n8k16.row.col.f32.bf16.bf16.f32 "
        "{%0,%1,%2,%3}, {%4,%5,%6,%7}, {%8,%9}, {%0,%1,%2,%3};"
        : "+f"(d[0]), "+f"(d[1]), "+f"(d[2]), "+f"(d[3])
        : "r"(a[0]), "r"(a[1]), "r"(a[2]), "r"(a[3]), "r"(b[0]), "r"(b[1]));
}
__device__ __forceinline__ float warpSum(float v) {
    #pragma unroll
    for (int o = 16; o > 0; o >>= 1) v += __shfl_xor_sync(0xffffffffu, v, o);
    return v;
}
__device__ __forceinline__ float warpMax(float v) {
    #pragma unroll
    for (int o = 16; o > 0; o >>= 1) v = fmaxf(v, __shfl_xor_sync(0xffffffffu, v, o));
    return v;
}

// ================= conversion kernels =================
__global__ void conv_split(const float* __restrict__ in, __nv_bfloat16* __restrict__ hi,
                           __nv_bfloat16* __restrict__ lo, int n)
{
    int i = (blockIdx.x * 256 + threadIdx.x) * 4;
    if (i < n) {
        float4 v = *(const float4*)(in + i);
        __nv_bfloat16 h0 = __float2bfloat16_rn(v.x);
        __nv_bfloat16 h1 = __float2bfloat16_rn(v.y);
        __nv_bfloat16 h2 = __float2bfloat16_rn(v.z);
        __nv_bfloat16 h3 = __float2bfloat16_rn(v.w);
        __nv_bfloat162 H0(h0, h1), H1(h2, h3);
        __nv_bfloat162 L0(__float2bfloat16_rn(v.x - __bfloat162float(h0)),
                          __float2bfloat16_rn(v.y - __bfloat162float(h1)));
        __nv_bfloat162 L1(__float2bfloat16_rn(v.z - __bfloat162float(h2)),
                          __float2bfloat16_rn(v.w - __bfloat162float(h3)));
        *(__nv_bfloat162*)(hi + i)     = H0;
        *(__nv_bfloat162*)(hi + i + 2) = H1;
        *(__nv_bfloat162*)(lo + i)     = L0;
        *(__nv_bfloat162*)(lo + i + 2) = L1;
    }
}

// transpose + split: wt[n][k] = W[k][n]; grid.z selects which W
__global__ void conv_w4(const float* __restrict__ Wq, const float* __restrict__ Wk,
                        const float* __restrict__ Wv, const float* __restrict__ Wo,
                        __nv_bfloat16* __restrict__ thi, __nv_bfloat16* __restrict__ tlo)
{
    __shared__ float tile[32][33];
    int z = blockIdx.z;
    const float* W = (z == 0) ? Wq : (z == 1) ? Wk : (z == 2) ? Wv : Wo;
    __nv_bfloat16* th = thi + (size_t)z * EE * EE;
    __nv_bfloat16* tl = tlo + (size_t)z * EE * EE;
    int bx = blockIdx.x * 32, by = blockIdx.y * 32;
    int x = threadIdx.x, y = threadIdx.y;
    #pragma unroll
    for (int j = 0; j < 4; j++)
        tile[y + j * 8][x] = W[(size_t)(by + y + j * 8) * EE + bx + x];
    __syncthreads();
    #pragma unroll
    for (int j = 0; j < 4; j++) {
        float v = tile[x][y + j * 8];
        __nv_bfloat16 h = __float2bfloat16_rn(v);
        size_t dst = (size_t)(bx + y + j * 8) * EE + by + x;
        th[dst] = h;
        tl[dst] = __float2bfloat16_rn(v - __bfloat162float(h));
    }
}

// ================= fused QKV projection: 128x64 tiles, 2 CTA/SM =================
// grid (8, 16, 3): z=0 -> q [bh][s][d], z=1 -> k, z=2 -> v transposed [bh][d][s]
// warps 4x2, warp tile 32x32
__global__ void __launch_bounds__(256, 2) proj_qkv(
    const __nv_bfloat16* __restrict__ xhi, const __nv_bfloat16* __restrict__ xlo,
    const __nv_bfloat16* __restrict__ wthi, const __nv_bfloat16* __restrict__ wtlo,
    const float* __restrict__ bq, const float* __restrict__ bk, const float* __restrict__ bv,
    __nv_bfloat16* __restrict__ qhi, __nv_bfloat16* __restrict__ qlo,
    __nv_bfloat16* __restrict__ khi, __nv_bfloat16* __restrict__ klo,
    __nv_bfloat16* __restrict__ vthi, __nv_bfloat16* __restrict__ vtlo)
{
    __shared__ __nv_bfloat16 sAh[128*PSTR], sAl[128*PSTR], sBh[64*PSTR], sBl[64*PSTR];
    int t = threadIdx.x, lane = t & 31, wid = t >> 5;
    int wm = wid >> 1, wn = wid & 1;
    int z = blockIdx.z;
    int n0 = blockIdx.x * 64, m0 = blockIdx.y * 128;
    const __nv_bfloat16* Bh = wthi + (size_t)z * EE * EE;
    const __nv_bfloat16* Bl = wtlo + (size_t)z * EE * EE;
    const float* bias = (z == 0) ? bq : ((z == 1) ? bk : bv);

    uint32_t bAh = smem_u32(sAh), bAl = smem_u32(sAl), bBh = smem_u32(sBh), bBl = smem_u32(sBl);
    float acc[2][4][4] = {};
    int mat = lane >> 3, r8 = lane & 7;

    for (int kc = 0; kc < 16; kc++) {
        #pragma unroll
        for (int i = t; i < 512; i += 256) {
            int row = i >> 2, seg = i & 3;
            size_t ga = (size_t)(m0 + row) * EE + kc * 32 + seg * 8;
            *(uint4*)&sAh[row * PSTR + seg * 8] = *(const uint4*)&xhi[ga];
            *(uint4*)&sAl[row * PSTR + seg * 8] = *(const uint4*)&xlo[ga];
        }
        {
            int row = t >> 2, seg = t & 3;    // 64 rows x 4 segs
            size_t gb = (size_t)(n0 + row) * EE + kc * 32 + seg * 8;
            *(uint4*)&sBh[row * PSTR + seg * 8] = *(const uint4*)&Bh[gb];
            *(uint4*)&sBl[row * PSTR + seg * 8] = *(const uint4*)&Bl[gb];
        }
        __syncthreads();
        #pragma unroll
        for (int kk = 0; kk < 2; kk++) {
            uint32_t ah[2][4], al[2][4], bhf[4][2], blf[4][2];
            uint32_t aoff = (uint32_t)((wm * 32 + r8 + (mat & 1) * 8) * PSTR + kk * 16 + (mat >> 1) * 8) * 2;
            #pragma unroll
            for (int fm = 0; fm < 2; fm++) {
                uint32_t o = aoff + fm * 16 * PSTR * 2;
                ldsm4(ah[fm], bAh + o);
                ldsm4(al[fm], bAl + o);
            }
            uint32_t boff = (uint32_t)((wn * 32 + r8) * PSTR + kk * 16 + (mat & 1) * 8) * 2;
            #pragma unroll
            for (int fn = 0; fn < 4; fn++) {
                uint32_t o = boff + fn * 8 * PSTR * 2;
                ldsm2(bhf[fn], bBh + o);
                ldsm2(blf[fn], bBl + o);
            }
            #pragma unroll
            for (int fm = 0; fm < 2; fm++)
                #pragma unroll
                for (int fn = 0; fn < 4; fn++) {
                    mma_bf16(acc[fm][fn], ah[fm], bhf[fn]);
                    mma_bf16(acc[fm][fn], ah[fm], blf[fn]);
                    mma_bf16(acc[fm][fn], al[fm], bhf[fn]);
                }
        }
        __syncthreads();
    }

    #pragma unroll
    for (int fm = 0; fm < 2; fm++)
        #pragma unroll
        for (int fn = 0; fn < 4; fn++)
            #pragma unroll
            for (int dr = 0; dr < 4; dr++) {
                int m = m0 + wm * 32 + fm * 16 + (lane >> 2) + (dr >> 1) * 8;
                int n = n0 + wn * 32 + fn * 8 + (lane & 3) * 2 + (dr & 1);
                float v = acc[fm][fn][dr] + bias[n];
                int b = m >> 9, s = m & 511;
                int h = n >> 6, d = n & 63;
                __nv_bfloat16 hh = __float2bfloat16_rn(v);
                __nv_bfloat16 ll = __float2bfloat16_rn(v - __bfloat162float(hh));
                if (z == 0) {
                    size_t dst = (((size_t)(b * HH + h) * SS) + s) * HD + d;
                    qhi[dst] = hh; qlo[dst] = ll;
                } else if (z == 1) {
                    size_t dst = (((size_t)(b * HH + h) * SS) + s) * HD + d;
                    khi[dst] = hh; klo[dst] = ll;
                } else {
                    size_t dst = (((size_t)(b * HH + h) * HD) + d) * SS + s;
                    vthi[dst] = hh; vtlo[dst] = ll;
                }
            }
}

// ================= output projection: 128x64 tiles, 2 CTA/SM, fp32 result =================
__global__ void __launch_bounds__(256, 2) proj_out(
    const __nv_bfloat16* __restrict__ ahi, const __nv_bfloat16* __restrict__ alo,
    const __nv_bfloat16* __restrict__ wthi, const __nv_bfloat16* __restrict__ wtlo,
    const float* __restrict__ bias, float* __restrict__ out)
{
    __shared__ __nv_bfloat16 sAh[128*PSTR], sAl[128*PSTR], sBh[64*PSTR], sBl[64*PSTR];
    int t = threadIdx.x, lane = t & 31, wid = t >> 5;
    int wm = wid >> 1, wn = wid & 1;
    int n0 = blockIdx.x * 64, m0 = blockIdx.y * 128;
    const __nv_bfloat16* Bh = wthi + (size_t)3 * EE * EE;
    const __nv_bfloat16* Bl = wtlo + (size_t)3 * EE * EE;

    uint32_t bAh = smem_u32(sAh), bAl = smem_u32(sAl), bBh = smem_u32(sBh), bBl = smem_u32(sBl);
    float acc[2][4][4] = {};
    int mat = lane >> 3, r8 = lane & 7;

    for (int kc = 0; kc < 16; kc++) {
        #pragma unroll
        for (int i = t; i < 512; i += 256) {
            int row = i >> 2, seg = i & 3;
            size_t ga = (size_t)(m0 + row) * EE + kc * 32 + seg * 8;
            *(uint4*)&sAh[row * PSTR + seg * 8] = *(const uint4*)&ahi[ga];
            *(uint4*)&sAl[row * PSTR + seg * 8] = *(const uint4*)&alo[ga];
        }
        {
            int row = t >> 2, seg = t & 3;
            size_t gb = (size_t)(n0 + row) * EE + kc * 32 + seg * 8;
            *(uint4*)&sBh[row * PSTR + seg * 8] = *(const uint4*)&Bh[gb];
            *(uint4*)&sBl[row * PSTR + seg * 8] = *(const uint4*)&Bl[gb];
        }
        __syncthreads();
        #pragma unroll
        for (int kk = 0; kk < 2; kk++) {
            uint32_t ah[2][4], al[2][4], bhf[4][2], blf[4][2];
            uint32_t aoff = (uint32_t)((wm * 32 + r8 + (mat & 1) * 8) * PSTR + kk * 16 + (mat >> 1) * 8) * 2;
            #pragma unroll
            for (int fm = 0; fm < 2; fm++) {
                uint32_t o = aoff + fm * 16 * PSTR * 2;
                ldsm4(ah[fm], bAh + o);
                ldsm4(al[fm], bAl + o);
            }
            uint32_t boff = (uint32_t)((wn * 32 + r8) * PSTR + kk * 16 + (mat & 1) * 8) * 2;
            #pragma unroll
            for (int fn = 0; fn < 4; fn++) {
                uint32_t o = boff + fn * 8 * PSTR * 2;
                ldsm2(bhf[fn], bBh + o);
                ldsm2(blf[fn], bBl + o);
            }
            #pragma unroll
            for (int fm = 0; fm < 2; fm++)
                #pragma unroll
                for (int fn = 0; fn < 4; fn++) {
                    mma_bf16(acc[fm][fn], ah[fm], bhf[fn]);
                    mma_bf16(acc[fm][fn], ah[fm], blf[fn]);
                    mma_bf16(acc[fm][fn], al[fm], bhf[fn]);
                }
        }
        __syncthreads();
    }

    #pragma unroll
    for (int fm = 0; fm < 2; fm++)
        #pragma unroll
        for (int fn = 0; fn < 4; fn++)
            #pragma unroll
            for (int dr = 0; dr < 4; dr++) {
                int m = m0 + wm * 32 + fm * 16 + (lane >> 2) + (dr >> 1) * 8;
                int n = n0 + wn * 32 + fn * 8 + (lane & 3) * 2 + (dr & 1);
                out[(size_t)m * EE + n] = acc[fm][fn][dr] + bias[n];
            }
}

// ================= batched QK^T: 128x64 tiles, 2 CTA/SM =================
// grid (8 j, 4 i, 32 bh); warps 4x2; warp tile 32x32
__global__ void __launch_bounds__(256, 2) qk_mma(
    const __nv_bfloat16* __restrict__ qhi, const __nv_bfloat16* __restrict__ qlo,
    const __nv_bfloat16* __restrict__ khi, const __nv_bfloat16* __restrict__ klo,
    float* __restrict__ s)
{
    __shared__ __nv_bfloat16 sAh[128*PSTR], sAl[128*PSTR], sBh[64*PSTR], sBl[64*PSTR];
    int t = threadIdx.x, lane = t & 31, wid = t >> 5;
    int wm = wid >> 1, wn = wid & 1;
    int j0 = blockIdx.x * 64, i0 = blockIdx.y * 128, bh = blockIdx.z;

    uint32_t bAh = smem_u32(sAh), bAl = smem_u32(sAl), bBh = smem_u32(sBh), bBl = smem_u32(sBl);
    float acc[2][4][4] = {};
    int mat = lane >> 3, r8 = lane & 7;

    for (int kc = 0; kc < 2; kc++) {
        #pragma unroll
        for (int i = t; i < 512; i += 256) {
            int row = i >> 2, seg = i & 3;
            size_t ga = ((size_t)bh * SS + i0 + row) * HD + kc * 32 + seg * 8;
            *(uint4*)&sAh[row * PSTR + seg * 8] = *(const uint4*)&qhi[ga];
            *(uint4*)&sAl[row * PSTR + seg * 8] = *(const uint4*)&qlo[ga];
        }
        {
            int row = t >> 2, seg = t & 3;     // 64 rows x 4 segs = 256
            size_t gb = ((size_t)bh * SS + j0 + row) * HD + kc * 32 + seg * 8;
            *(uint4*)&sBh[row * PSTR + seg * 8] = *(const uint4*)&khi[gb];
            *(uint4*)&sBl[row * PSTR + seg * 8] = *(const uint4*)&klo[gb];
        }
        __syncthreads();
        #pragma unroll
        for (int kk = 0; kk < 2; kk++) {
            uint32_t ah[2][4], al[2][4], bhf[4][2], blf[4][2];
            uint32_t aoff = (uint32_t)((wm * 32 + r8 + (mat & 1) * 8) * PSTR + kk * 16 + (mat >> 1) * 8) * 2;
            #pragma unroll
            for (int fm = 0; fm < 2; fm++) {
                uint32_t o = aoff + fm * 16 * PSTR * 2;
                ldsm4(ah[fm], bAh + o);
                ldsm4(al[fm], bAl + o);
            }
            uint32_t boff = (uint32_t)((wn * 32 + r8) * PSTR + kk * 16 + (mat & 1) * 8) * 2;
            #pragma unroll
            for (int fn = 0; fn < 4; fn++) {
                uint32_t o = boff + fn * 8 * PSTR * 2;
                ldsm2(bhf[fn], bBh + o);
                ldsm2(blf[fn], bBl + o);
            }
            #pragma unroll
            for (int fm = 0; fm < 2; fm++)
                #pragma unroll
                for (int fn = 0; fn < 4; fn++) {
                    mma_bf16(acc[fm][fn], ah[fm], bhf[fn]);
                    mma_bf16(acc[fm][fn], ah[fm], blf[fn]);
                    mma_bf16(acc[fm][fn], al[fm], bhf[fn]);
                }
        }
        __syncthreads();
    }

    float* sbase = s + (size_t)bh * SS * SS;
    #pragma unroll
    for (int fm = 0; fm < 2; fm++)
        #pragma unroll
        for (int fn = 0; fn < 4; fn++)
            #pragma unroll
            for (int dr = 0; dr < 4; dr++) {
                int mi = i0 + wm * 32 + fm * 16 + (lane >> 2) + (dr >> 1) * 8;
                int nj = j0 + wn * 32 + fn * 8 + (lane & 3) * 2 + (dr & 1);
                float v = acc[fm][fn][dr] * 0.125f;
                if (isnan(v)) v = 0.f;
                else if (isinf(v)) v = v > 0.f ? 10.f : -10.f;
                v = clipf(v, -15.f, 15.f);
                sbase[(size_t)mi * SS + nj] = v;
            }
}

// ================= batched attn @ V (128x64, 2 CTA/SM) =================
__global__ void __launch_bounds__(256, 2) av_mma(
    const __nv_bfloat16* __restrict__ ahi, const __nv_bfloat16* __restrict__ alo,
    const __nv_bfloat16* __restrict__ vthi, const __nv_bfloat16* __restrict__ vtlo,
    __nv_bfloat16* __restrict__ ohi, __nv_bfloat16* __restrict__ olo)
{
    __shared__ __nv_bfloat16 sAh[128*PSTR], sAl[128*PSTR], sBh[64*PSTR], sBl[64*PSTR];
    int t = threadIdx.x, lane = t & 31, wid = t >> 5;
    int wm = wid >> 2, wn = wid & 3;
    int i0 = blockIdx.x * 128, bh = blockIdx.y;
    int b = bh >> 3, h = bh & 7;

    uint32_t bAh = smem_u32(sAh), bAl = smem_u32(sAl), bBh = smem_u32(sBh), bBl = smem_u32(sBl);
    float acc[4][2][4] = {};
    int mat = lane >> 3, r8 = lane & 7;

    for (int kc = 0; kc < 16; kc++) {
        #pragma unroll
        for (int i = t; i < 512; i += 256) {
            int row = i >> 2, seg = i & 3;
            size_t ga = (size_t)bh * SS * SS + (size_t)(i0 + row) * SS + kc * 32 + seg * 8;
            *(uint4*)&sAh[row * PSTR + seg * 8] = *(const uint4*)&ahi[ga];
            *(uint4*)&sAl[row * PSTR + seg * 8] = *(const uint4*)&alo[ga];
        }
        {
            int row = t >> 2, seg = t & 3;   // 64 rows x 4 segs = 256
            size_t gb = ((size_t)bh * HD + row) * SS + kc * 32 + seg * 8;
            *(uint4*)&sBh[row * PSTR + seg * 8] = *(const uint4*)&vthi[gb];
            *(uint4*)&sBl[row * PSTR + seg * 8] = *(const uint4*)&vtlo[gb];
        }
        __syncthreads();
        #pragma unroll
        for (int kk = 0; kk < 2; kk++) {
            uint32_t ah[4][4], al[4][4], bhf[2][2], blf[2][2];
            uint32_t aoff = (uint32_t)((wm * 64 + r8 + (mat & 1) * 8) * PSTR + kk * 16 + (mat >> 1) * 8) * 2;
            #pragma unroll
            for (int fm = 0; fm < 4; fm++) {
                uint32_t o = aoff + fm * 16 * PSTR * 2;
                ldsm4(ah[fm], bAh + o);
                ldsm4(al[fm], bAl + o);
            }
            uint32_t boff = (uint32_t)((wn * 16 + r8) * PSTR + kk * 16 + (mat & 1) * 8) * 2;
            #pragma unroll
            for (int fn = 0; fn < 2; fn++) {
                uint32_t o = boff + fn * 8 * PSTR * 2;
                ldsm2(bhf[fn], bBh + o);
                ldsm2(blf[fn], bBl + o);
            }
            #pragma unroll
            for (int fm = 0; fm < 4; fm++)
                #pragma unroll
                for (int fn = 0; fn < 2; fn++) {
                    mma_bf16(acc[fm][fn], ah[fm], bhf[fn]);
                    mma_bf16(acc[fm][fn], ah[fm], blf[fn]);
                    mma_bf16(acc[fm][fn], al[fm], bhf[fn]);
                }
        }
        __syncthreads();
    }

    #pragma unroll
    for (int fm = 0; fm < 4; fm++)
        #pragma unroll
        for (int fn = 0; fn < 2; fn++)
            #pragma unroll
            for (int dr = 0; dr < 4; dr++) {
                int si = i0 + wm * 64 + fm * 16 + (lane >> 2) + (dr >> 1) * 8;
                int d  = wn * 16 + fn * 8 + (lane & 3) * 2 + (dr & 1);
                float v = acc[fm][fn][dr];
                size_t dst = ((size_t)b * SS + si) * EE + h * HD + d;
                __nv_bfloat16 hh = __float2bfloat16_rn(v);
                ohi[dst] = hh;
                olo[dst] = __float2bfloat16_rn(v - __bfloat162float(hh));
            }
}

// ================= init accumulators =================
__global__ void init_acc()
{
    int t = threadIdx.x;
    if (t < BB * 5) g_acc[t] = 0.0;
    if (t < BB) g_amax[t] = 0;
}

// ================= fused head-mean + row transform (warp-per-row) =================
__global__ void __launch_bounds__(256) row_transform_fused(
    const float* __restrict__ s, float* __restrict__ ma, float* __restrict__ tp,
    const float* __restrict__ w1, const float* __restrict__ b1,
    const float* __restrict__ w2, const float* __restrict__ b2)
{
    __shared__ float w1s[CC], b1s[CC], w2s[CC];
    int t = threadIdx.x, lane = t & 31, w = t >> 5;
    if (t < CC) { w1s[t] = w1[t]; b1s[t] = b1[t]; w2s[t] = w2[t]; }
    __syncthreads();

    int row = blockIdx.x * 8 + w;
    int b = row >> 9, i = row & 511;
    const float* sb = s + ((size_t)b * HH * SS + i) * SS;
    float* marow = ma + ((size_t)b * SS + i) * SS;
    float* tprow = tp + ((size_t)b * SS + i) * SS;

    float m[16];
    #pragma unroll
    for (int e = 0; e < 16; e++) {
        int j = lane + 32 * e;
        float acc = 0.f;
        #pragma unroll
        for (int hh = 0; hh < HH; hh++) acc += sb[(size_t)hh * SS * SS + j];
        m[e] = acc * 0.125f;
        marow[j] = m[e];
    }

    float mx = -1e30f;
    #pragma unroll
    for (int e = 0; e < 16; e++) mx = fmaxf(mx, clipf(m[e], -10.f, 10.f));
    mx = warpMax(mx);
    float a_[16]; float sum = 0.f;
    #pragma unroll
    for (int e = 0; e < 16; e++) { a_[e] = __expf(clipf(m[e], -10.f, 10.f) - mx); sum += a_[e]; }
    sum = warpSum(sum);
    float inv = 1.f / sum;
    float h_[16];
    #pragma unroll
    for (int e = 0; e < 16; e++) { float p = a_[e] * inv; h_[e] = -p * __logf(p + 1e-6f); }

    float sma = 0.f, sma2 = 0.f, shh = 0.f, amx = 0.f;
    #pragma unroll
    for (int e = 0; e < 16; e++) {
        sma += m[e]; sma2 += m[e] * m[e]; shh += h_[e]; amx = fmaxf(amx, fabsf(m[e]));
    }
    sma = warpSum(sma); sma2 = warpSum(sma2); shh = warpSum(shh); amx = warpMax(amx);

    float hmx = -1e30f;
    #pragma unroll
    for (int e = 0; e < 16; e++) hmx = fmaxf(hmx, h_[e]);
    hmx = warpMax(hmx) * 3.f;
    float fsum = 0.f;
    #pragma unroll
    for (int e = 0; e < 16; e++) { h_[e] = __expf(3.f * h_[e] - hmx); fsum += h_[e]; }
    fsum = warpSum(fsum);
    float finv = 1.f / fsum;

    float sa[16], acc[16];
    #pragma unroll
    for (int e = 0; e < 16; e++) {
        sa[e] = clipf(clipf(m[e], -8.f, 8.f) * 0.05f, -10.f, 10.f);
        acc[e] = 0.f;
    }
    #pragma unroll 4
    for (int c = 0; c < CC; c++) {
        float wv = w1s[c], bb = b1s[c], w2v = w2s[c];
        #pragma unroll
        for (int e = 0; e < 16; e++)
            acc[e] += fminf(fmaxf(sa[e] * wv + bb, 0.f), 5.f) * w2v;
    }
    float b2v = b2[0];
    float stt = 0.f, st2 = 0.f;
    #pragma unroll
    for (int e = 0; e < 16; e++) {
        float ap = clipf(acc[e] + b2v, -5.f, 5.f);
        float ty = clipf(1.f + 2.5f * ap, 0.5f, 1.5f);
        float sg = 1.f / (1.f + __expf(-ty));
        float F = h_[e] * finv;
        float tv = sg * F;
        tprow[lane + 32 * e] = tv;
        stt += tv; st2 += tv * tv;
    }
    stt = warpSum(stt); st2 = warpSum(st2);

    if (lane == 0) {
        atomicAdd(&g_acc[b * 5 + 0], (double)sma);
        atomicAdd(&g_acc[b * 5 + 1], (double)sma2);
        atomicAdd(&g_acc[b * 5 + 2], (double)shh);
        atomicAdd(&g_acc[b * 5 + 3], (double)stt);
        atomicAdd(&g_acc[b * 5 + 4], (double)st2);
        atomicMax(&g_amax[b], __float_as_int(amx));
    }
}

__global__ void finalize_kernel()
{
    int b = threadIdx.x;
    if (b < BB) {
        const double N = (double)SS * (double)SS;
        double sma  = g_acc[b * 5 + 0];
        double sma2 = g_acc[b * 5 + 1];
        double sh   = g_acc[b * 5 + 2];
        double st   = g_acc[b * 5 + 3];
        double st2  = g_acc[b * 5 + 4];
        float amaxv = __int_as_float(g_amax[b]);

        float eo = sqrtf((float)sma2) + 1e-4f;
        float et = sqrtf((float)st2) + 1e-4f;
        float c  = clipf(eo / et, 0.8f, 1.2f);
        float tm = c * (float)(st / N);
        float tvar = c * c * (float)(st2 / N - (st / N) * (st / N));
        tvar = fmaxf(tvar, 0.01f);
        float ovar = (float)(sma2 / N - (sma / N) * (sma / N));
        ovar = fmaxf(ovar, 0.01f);
        float gd = clipf(sqrtf(ovar) / sqrtf(tvar), 0.8f, 1.2f);
        float ar = clipf(amaxv, 1.f, 10.f);
        float sm = clipf(0.3f / log1pf(ar), 0.1f, 0.5f);
        float ent = (float)(sh / N);
        float ne = ent / logf((float)SS);
        float rr = 0.4f * (1.f - clipf(ne, 0.f, 0.4f));
        float smgd = sm * gd;

        g_coef[b * 3 + 0] = rr * tm * (1.f - smgd);
        g_coef[b * 3 + 1] = rr * smgd * c;
        g_coef[b * 3 + 2] = rr;
    }
}

// ================= softmax + delta (warp-per-row) -> attn bf16 hi/lo =================
__global__ void __launch_bounds__(256) attn_softmax2(
    const float* __restrict__ s, const float* __restrict__ ma,
    const float* __restrict__ tp, const float* __restrict__ tau,
    __nv_bfloat16* __restrict__ ahi, __nv_bfloat16* __restrict__ alo)
{
    int t = threadIdx.x, lane = t & 31, w = t >> 5;
    int row = blockIdx.x * 8 + w;
    int i = row & 511, bh = row >> 9, b = bh >> 3;

    const float* srow = s + (size_t)row * SS;
    const float* marow = ma + ((size_t)b * SS + i) * SS;
    const float* trow  = tp + ((size_t)b * SS + i) * SS;
    float A  = g_coef[b * 3 + 0];
    float Bc = g_coef[b * 3 + 1];
    float Cc = g_coef[b * 3 + 2];
    float itau = 1.f / tau[0];

    float v[16];
    float mx = -1e30f;
    #pragma unroll
    for (int e = 0; e < 16; e++) {
        int j = lane + 32 * e;
        v[e] = (srow[j] + A + Bc * trow[j] - Cc * marow[j]) * itau;
        mx = fmaxf(mx, v[e]);
    }
    mx = warpMax(mx);
    float sum = 0.f;
    #pragma unroll
    for (int e = 0; e < 16; e++) { v[e] = __expf(v[e] - mx); sum += v[e]; }
    sum = warpSum(sum);
    float inv = 1.f / sum;

    __nv_bfloat16* arow_h = ahi + (size_t)row * SS;
    __nv_bfloat16* arow_l = alo + (size_t)row * SS;
    #pragma unroll
    for (int e = 0; e < 16; e++) {
        int j = lane + 32 * e;
        float p = v[e] * inv;
        __nv_bfloat16 hh = __float2bfloat16_rn(p);
        arow_h[j] = hh;
        arow_l[j] = __float2bfloat16_rn(p - __bfloat162float(hh));
    }
}

// ---------------- launch ----------------
extern "C" void kernel_launch(void* const* d_in, const int* in_sizes, int n_in,
                              void* d_out, int out_size)
{
    const float* x  = (const float*)d_in[0];
    const float* Wq = (const float*)d_in[1];
    const float* bq = (const float*)d_in[2];
    const float* Wk = (const float*)d_in[3];
    const float* bk = (const float*)d_in[4];
    const float* Wv = (const float*)d_in[5];
    const float* bv = (const float*)d_in[6];
    const float* Wo = (const float*)d_in[7];
    const float* bo = (const float*)d_in[8];
    const float* w1 = (const float*)d_in[9];
    const float* b1 = (const float*)d_in[10];
    const float* w2 = (const float*)d_in[11];
    const float* b2 = (const float*)d_in[12];
    const float* tau = (const float*)d_in[13];
    float* out = (float*)d_out;

    __nv_bfloat16 *pxhi, *pxlo, *pwthi, *pwtlo, *pqhi, *pqlo, *pkhi, *pklo, *pvthi, *pvtlo;
    __nv_bfloat16 *pahi, *palo, *pohhi, *pohlo;
    float *ps, *pma, *ptp;
    cudaGetSymbolAddress((void**)&pxhi, g_xhi);
    cudaGetSymbolAddress((void**)&pxlo, g_xlo);
    cudaGetSymbolAddress((void**)&pwthi, g_wthi);
    cudaGetSymbolAddress((void**)&pwtlo, g_wtlo);
    cudaGetSymbolAddress((void**)&pqhi, g_qhi);
    cudaGetSymbolAddress((void**)&pqlo, g_qlo);
    cudaGetSymbolAddress((void**)&pkhi, g_khi);
    cudaGetSymbolAddress((void**)&pklo, g_klo);
    cudaGetSymbolAddress((void**)&pvthi, g_vthi);
    cudaGetSymbolAddress((void**)&pvtlo, g_vtlo);
    cudaGetSymbolAddress((void**)&pahi, g_ahi);
    cudaGetSymbolAddress((void**)&palo, g_alo);
    cudaGetSymbolAddress((void**)&pohhi, g_ohhi);
    cudaGetSymbolAddress((void**)&pohlo, g_ohlo);
    cudaGetSymbolAddress((void**)&ps, g_s);
    cudaGetSymbolAddress((void**)&pma, g_ma);
    cudaGetSymbolAddress((void**)&ptp, g_tp);

    // 1) conversions
    conv_split<<<(NROW * EE / 4) / 256, 256>>>(x, pxhi, pxlo, NROW * EE);
    conv_w4<<<dim3(16, 16, 4), dim3(32, 8)>>>(Wq, Wk, Wv, Wo, pwthi, pwtlo);

    // 2) fused QKV projection (128x64 tiles, 2 CTA/SM)
    proj_qkv<<<dim3(8, 16, 3), 256>>>(pxhi, pxlo, pwthi, pwtlo, bq, bk, bv,
                                      pqhi, pqlo, pkhi, pklo, pvthi, pvtlo);

    // 3) QK^T (128x64 tiles, 2 CTA/SM)
    qk_mma<<<dim3(8, 4, BB * HH), 256>>>(pqhi, pqlo, pkhi, pklo, ps);

    // 4) fused head-mean + transform + stats
    init_acc<<<1, 32>>>();
    row_transform_fused<<<256, 256>>>(ps, pma, ptp, w1, b1, w2, b2);
    finalize_kernel<<<1, 32>>>();

    // 5) softmax -> attn hi/lo
    attn_softmax2<<<2048, 256>>>(ps, pma, ptp, tau, pahi, palo);

    // 6) attn @ V
    av_mma<<<dim3(4, BB * HH), 256>>>(pahi, palo, pvthi, pvtlo, pohhi, pohlo);

    // 7) output projection (128x64 tiles, 2 CTA/SM) -> fp32 out
    proj_out<<<dim3(8, 16), 256>>>(pohhi, pohlo, pwthi, pwtlo, bo, out);
}

// round 10
// speedup vs baseline: 1.5509x; 1.1041x over previous
#include <cuda_runtime.h>
#include <cuda_bf16.h>
#include <math.h>
#include <stdint.h>

#define BB 4
#define SS 512
#define EE 512
#define HH 8
#define HD 64
#define CC 128
#define NROW (BB*SS)          // 2048
#define PSTR 40               // smem row stride in bf16 (80B) -> conflict-free ldmatrix

// ---------------- scratch (static device globals; no allocation) ----------------
__device__ __nv_bfloat16 g_xhi[NROW*EE], g_xlo[NROW*EE];
__device__ __nv_bfloat16 g_wthi[4*EE*EE], g_wtlo[4*EE*EE];           // transposed [n][k]
__device__ __nv_bfloat16 g_qhi[BB*HH*SS*HD], g_qlo[BB*HH*SS*HD];     // [bh][s][d]
__device__ __nv_bfloat16 g_khi[BB*HH*SS*HD], g_klo[BB*HH*SS*HD];     // [bh][s][d]
__device__ __nv_bfloat16 g_vthi[BB*HH*HD*SS], g_vtlo[BB*HH*HD*SS];   // [bh][d][s]
__device__ float g_s[(size_t)BB*HH*SS*SS];                           // 32MB
__device__ float g_ma[BB*SS*SS];
__device__ float g_tp[BB*SS*SS];
__device__ __nv_bfloat16 g_ahi[(size_t)BB*HH*SS*SS], g_alo[(size_t)BB*HH*SS*SS];
__device__ __nv_bfloat16 g_ohhi[NROW*EE], g_ohlo[NROW*EE];           // [B,S,E]
__device__ double g_acc[BB*5];
__device__ int    g_amax[BB];
__device__ float  g_coef[BB*3];

// ---------------- helpers ----------------
__device__ __forceinline__ float clipf(float v, float lo, float hi) {
    return fminf(fmaxf(v, lo), hi);
}
__device__ __forceinline__ uint32_t smem_u32(const void* p) {
    uint32_t a;
    asm("{ .reg .u64 t; cvta.to.shared.u64 t, %1; cvt.u32.u64 %0, t; }" : "=r"(a) : "l"(p));
    return a;
}
__device__ __forceinline__ void ldsm4(uint32_t* a, uint32_t addr) {
    asm volatile("ldmatrix.sync.aligned.m8n8.x4.shared.b16 {%0,%1,%2,%3}, [%4];"
        : "=r"(a[0]), "=r"(a[1]), "=r"(a[2]), "=r"(a[3]) : "r"(addr));
}
__device__ __forceinline__ void ldsm2(uint32_t* a, uint32_t addr) {
    asm volatile("ldmatrix.sync.aligned.m8n8.x2.shared.b16 {%0,%1}, [%2];"
        : "=r"(a[0]), "=r"(a[1]) : "r"(addr));
}
__device__ __forceinline__ void mma_bf16(float* d, const uint32_t* a, const uint32_t* b) {
    asm volatile("mma.sync.aligned.m16n8k16.row.col.f32.bf16.bf16.f32 "
        "{%0,%1,%2,%3}, {%4,%5,%6,%7}, {%8,%9}, {%0,%1,%2,%3};"
        : "+f"(d[0]), "+f"(d[1]), "+f"(d[2]), "+f"(d[3])
        : "r"(a[0]), "r"(a[1]), "r"(a[2]), "r"(a[3]), "r"(b[0]), "r"(b[1]));
}
__device__ __forceinline__ float warpSum(float v) {
    #pragma unroll
    for (int o = 16; o > 0; o >>= 1) v += __shfl_xor_sync(0xffffffffu, v, o);
    return v;
}
__device__ __forceinline__ float warpMax(float v) {
    #pragma unroll
    for (int o = 16; o > 0; o >>= 1) v = fmaxf(v, __shfl_xor_sync(0xffffffffu, v, o));
    return v;
}
__device__ __forceinline__ uint32_t pack_bf162(float a, float b) {
    __nv_bfloat162 r(__float2bfloat16_rn(a), __float2bfloat16_rn(b));
    return *(uint32_t*)&r;
}

// ================= conversion kernels =================
__global__ void conv_split(const float* __restrict__ in, __nv_bfloat16* __restrict__ hi,
                           __nv_bfloat16* __restrict__ lo, int n)
{
    int i = (blockIdx.x * 256 + threadIdx.x) * 4;
    if (i < n) {
        float4 v = *(const float4*)(in + i);
        __nv_bfloat16 h0 = __float2bfloat16_rn(v.x);
        __nv_bfloat16 h1 = __float2bfloat16_rn(v.y);
        __nv_bfloat16 h2 = __float2bfloat16_rn(v.z);
        __nv_bfloat16 h3 = __float2bfloat16_rn(v.w);
        __nv_bfloat162 H0(h0, h1), H1(h2, h3);
        __nv_bfloat162 L0(__float2bfloat16_rn(v.x - __bfloat162float(h0)),
                          __float2bfloat16_rn(v.y - __bfloat162float(h1)));
        __nv_bfloat162 L1(__float2bfloat16_rn(v.z - __bfloat162float(h2)),
                          __float2bfloat16_rn(v.w - __bfloat162float(h3)));
        *(__nv_bfloat162*)(hi + i)     = H0;
        *(__nv_bfloat162*)(hi + i + 2) = H1;
        *(__nv_bfloat162*)(lo + i)     = L0;
        *(__nv_bfloat162*)(lo + i + 2) = L1;
    }
}

// transpose + split: wt[n][k] = W[k][n]; grid.z selects which W
__global__ void conv_w4(const float* __restrict__ Wq, const float* __restrict__ Wk,
                        const float* __restrict__ Wv, const float* __restrict__ Wo,
                        __nv_bfloat16* __restrict__ thi, __nv_bfloat16* __restrict__ tlo)
{
    __shared__ float tile[32][33];
    int z = blockIdx.z;
    const float* W = (z == 0) ? Wq : (z == 1) ? Wk : (z == 2) ? Wv : Wo;
    __nv_bfloat16* th = thi + (size_t)z * EE * EE;
    __nv_bfloat16* tl = tlo + (size_t)z * EE * EE;
    int bx = blockIdx.x * 32, by = blockIdx.y * 32;
    int x = threadIdx.x, y = threadIdx.y;
    #pragma unroll
    for (int j = 0; j < 4; j++)
        tile[y + j * 8][x] = W[(size_t)(by + y + j * 8) * EE + bx + x];
    __syncthreads();
    #pragma unroll
    for (int j = 0; j < 4; j++) {
        float v = tile[x][y + j * 8];
        __nv_bfloat16 h = __float2bfloat16_rn(v);
        size_t dst = (size_t)(bx + y + j * 8) * EE + by + x;
        th[dst] = h;
        tl[dst] = __float2bfloat16_rn(v - __bfloat162float(h));
    }
}

// ================= fused QKV projection: 128x64 tiles, 2 CTA/SM =================
__global__ void __launch_bounds__(256, 2) proj_qkv(
    const __nv_bfloat16* __restrict__ xhi, const __nv_bfloat16* __restrict__ xlo,
    const __nv_bfloat16* __restrict__ wthi, const __nv_bfloat16* __restrict__ wtlo,
    const float* __restrict__ bq, const float* __restrict__ bk, const float* __restrict__ bv,
    __nv_bfloat16* __restrict__ qhi, __nv_bfloat16* __restrict__ qlo,
    __nv_bfloat16* __restrict__ khi, __nv_bfloat16* __restrict__ klo,
    __nv_bfloat16* __restrict__ vthi, __nv_bfloat16* __restrict__ vtlo)
{
    __shared__ __nv_bfloat16 sAh[128*PSTR], sAl[128*PSTR], sBh[64*PSTR], sBl[64*PSTR];
    int t = threadIdx.x, lane = t & 31, wid = t >> 5;
    int wm = wid >> 1, wn = wid & 1;
    int z = blockIdx.z;
    int n0 = blockIdx.x * 64, m0 = blockIdx.y * 128;
    const __nv_bfloat16* Bh = wthi + (size_t)z * EE * EE;
    const __nv_bfloat16* Bl = wtlo + (size_t)z * EE * EE;
    const float* bias = (z == 0) ? bq : ((z == 1) ? bk : bv);

    uint32_t bAh = smem_u32(sAh), bAl = smem_u32(sAl), bBh = smem_u32(sBh), bBl = smem_u32(sBl);
    float acc[2][4][4] = {};
    int mat = lane >> 3, r8 = lane & 7;

    for (int kc = 0; kc < 16; kc++) {
        #pragma unroll
        for (int i = t; i < 512; i += 256) {
            int row = i >> 2, seg = i & 3;
            size_t ga = (size_t)(m0 + row) * EE + kc * 32 + seg * 8;
            *(uint4*)&sAh[row * PSTR + seg * 8] = *(const uint4*)&xhi[ga];
            *(uint4*)&sAl[row * PSTR + seg * 8] = *(const uint4*)&xlo[ga];
        }
        {
            int row = t >> 2, seg = t & 3;
            size_t gb = (size_t)(n0 + row) * EE + kc * 32 + seg * 8;
            *(uint4*)&sBh[row * PSTR + seg * 8] = *(const uint4*)&Bh[gb];
            *(uint4*)&sBl[row * PSTR + seg * 8] = *(const uint4*)&Bl[gb];
        }
        __syncthreads();
        #pragma unroll
        for (int kk = 0; kk < 2; kk++) {
            uint32_t ah[2][4], al[2][4], bhf[4][2], blf[4][2];
            uint32_t aoff = (uint32_t)((wm * 32 + r8 + (mat & 1) * 8) * PSTR + kk * 16 + (mat >> 1) * 8) * 2;
            #pragma unroll
            for (int fm = 0; fm < 2; fm++) {
                uint32_t o = aoff + fm * 16 * PSTR * 2;
                ldsm4(ah[fm], bAh + o);
                ldsm4(al[fm], bAl + o);
            }
            uint32_t boff = (uint32_t)((wn * 32 + r8) * PSTR + kk * 16 + (mat & 1) * 8) * 2;
            #pragma unroll
            for (int fn = 0; fn < 4; fn++) {
                uint32_t o = boff + fn * 8 * PSTR * 2;
                ldsm2(bhf[fn], bBh + o);
                ldsm2(blf[fn], bBl + o);
            }
            #pragma unroll
            for (int fm = 0; fm < 2; fm++)
                #pragma unroll
                for (int fn = 0; fn < 4; fn++) {
                    mma_bf16(acc[fm][fn], ah[fm], bhf[fn]);
                    mma_bf16(acc[fm][fn], ah[fm], blf[fn]);
                    mma_bf16(acc[fm][fn], al[fm], bhf[fn]);
                }
        }
        __syncthreads();
    }

    #pragma unroll
    for (int fm = 0; fm < 2; fm++)
        #pragma unroll
        for (int fn = 0; fn < 4; fn++)
            #pragma unroll
            for (int drp = 0; drp < 2; drp++) {
                int m = m0 + wm * 32 + fm * 16 + (lane >> 2) + drp * 8;
                int n = n0 + wn * 32 + fn * 8 + (lane & 3) * 2;
                float v0 = acc[fm][fn][drp * 2 + 0] + bias[n];
                float v1 = acc[fm][fn][drp * 2 + 1] + bias[n + 1];
                int b = m >> 9, s = m & 511;
                int h = n >> 6, d = n & 63;
                __nv_bfloat16 h0 = __float2bfloat16_rn(v0);
                __nv_bfloat16 h1 = __float2bfloat16_rn(v1);
                float l0 = v0 - __bfloat162float(h0);
                float l1 = v1 - __bfloat162float(h1);
                if (z == 0) {
                    size_t dst = (((size_t)(b * HH + h) * SS) + s) * HD + d;
                    *(__nv_bfloat162*)&qhi[dst] = __nv_bfloat162(h0, h1);
                    *(__nv_bfloat162*)&qlo[dst] = __nv_bfloat162(__float2bfloat16_rn(l0), __float2bfloat16_rn(l1));
                } else if (z == 1) {
                    size_t dst = (((size_t)(b * HH + h) * SS) + s) * HD + d;
                    *(__nv_bfloat162*)&khi[dst] = __nv_bfloat162(h0, h1);
                    *(__nv_bfloat162*)&klo[dst] = __nv_bfloat162(__float2bfloat16_rn(l0), __float2bfloat16_rn(l1));
                } else {
                    size_t dst0 = (((size_t)(b * HH + h) * HD) + d) * SS + s;
                    vthi[dst0] = h0; vtlo[dst0] = __float2bfloat16_rn(l0);
                    size_t dst1 = dst0 + SS;
                    vthi[dst1] = h1; vtlo[dst1] = __float2bfloat16_rn(l1);
                }
            }
}

// ================= output projection: 128x64 tiles, 2 CTA/SM, fp32 result =================
__global__ void __launch_bounds__(256, 2) proj_out(
    const __nv_bfloat16* __restrict__ ahi, const __nv_bfloat16* __restrict__ alo,
    const __nv_bfloat16* __restrict__ wthi, const __nv_bfloat16* __restrict__ wtlo,
    const float* __restrict__ bias, float* __restrict__ out)
{
    __shared__ __nv_bfloat16 sAh[128*PSTR], sAl[128*PSTR], sBh[64*PSTR], sBl[64*PSTR];
    int t = threadIdx.x, lane = t & 31, wid = t >> 5;
    int wm = wid >> 1, wn = wid & 1;
    int n0 = blockIdx.x * 64, m0 = blockIdx.y * 128;
    const __nv_bfloat16* Bh = wthi + (size_t)3 * EE * EE;
    const __nv_bfloat16* Bl = wtlo + (size_t)3 * EE * EE;

    uint32_t bAh = smem_u32(sAh), bAl = smem_u32(sAl), bBh = smem_u32(sBh), bBl = smem_u32(sBl);
    float acc[2][4][4] = {};
    int mat = lane >> 3, r8 = lane & 7;

    for (int kc = 0; kc < 16; kc++) {
        #pragma unroll
        for (int i = t; i < 512; i += 256) {
            int row = i >> 2, seg = i & 3;
            size_t ga = (size_t)(m0 + row) * EE + kc * 32 + seg * 8;
            *(uint4*)&sAh[row * PSTR + seg * 8] = *(const uint4*)&ahi[ga];
            *(uint4*)&sAl[row * PSTR + seg * 8] = *(const uint4*)&alo[ga];
        }
        {
            int row = t >> 2, seg = t & 3;
            size_t gb = (size_t)(n0 + row) * EE + kc * 32 + seg * 8;
            *(uint4*)&sBh[row * PSTR + seg * 8] = *(const uint4*)&Bh[gb];
            *(uint4*)&sBl[row * PSTR + seg * 8] = *(const uint4*)&Bl[gb];
        }
        __syncthreads();
        #pragma unroll
        for (int kk = 0; kk < 2; kk++) {
            uint32_t ah[2][4], al[2][4], bhf[4][2], blf[4][2];
            uint32_t aoff = (uint32_t)((wm * 32 + r8 + (mat & 1) * 8) * PSTR + kk * 16 + (mat >> 1) * 8) * 2;
            #pragma unroll
            for (int fm = 0; fm < 2; fm++) {
                uint32_t o = aoff + fm * 16 * PSTR * 2;
                ldsm4(ah[fm], bAh + o);
                ldsm4(al[fm], bAl + o);
            }
            uint32_t boff = (uint32_t)((wn * 32 + r8) * PSTR + kk * 16 + (mat & 1) * 8) * 2;
            #pragma unroll
            for (int fn = 0; fn < 4; fn++) {
                uint32_t o = boff + fn * 8 * PSTR * 2;
                ldsm2(bhf[fn], bBh + o);
                ldsm2(blf[fn], bBl + o);
            }
            #pragma unroll
            for (int fm = 0; fm < 2; fm++)
                #pragma unroll
                for (int fn = 0; fn < 4; fn++) {
                    mma_bf16(acc[fm][fn], ah[fm], bhf[fn]);
                    mma_bf16(acc[fm][fn], ah[fm], blf[fn]);
                    mma_bf16(acc[fm][fn], al[fm], bhf[fn]);
                }
        }
        __syncthreads();
    }

    #pragma unroll
    for (int fm = 0; fm < 2; fm++)
        #pragma unroll
        for (int fn = 0; fn < 4; fn++)
            #pragma unroll
            for (int drp = 0; drp < 2; drp++) {
                int m = m0 + wm * 32 + fm * 16 + (lane >> 2) + drp * 8;
                int n = n0 + wn * 32 + fn * 8 + (lane & 3) * 2;
                float2 v;
                v.x = acc[fm][fn][drp * 2 + 0] + bias[n];
                v.y = acc[fm][fn][drp * 2 + 1] + bias[n + 1];
                *(float2*)&out[(size_t)m * EE + n] = v;
            }
}

// ================= batched QK^T: 128x64 tiles, 2 CTA/SM =================
__global__ void __launch_bounds__(256, 2) qk_mma(
    const __nv_bfloat16* __restrict__ qhi, const __nv_bfloat16* __restrict__ qlo,
    const __nv_bfloat16* __restrict__ khi, const __nv_bfloat16* __restrict__ klo,
    float* __restrict__ s)
{
    __shared__ __nv_bfloat16 sAh[128*PSTR], sAl[128*PSTR], sBh[64*PSTR], sBl[64*PSTR];
    int t = threadIdx.x, lane = t & 31, wid = t >> 5;
    int wm = wid >> 1, wn = wid & 1;
    int j0 = blockIdx.x * 64, i0 = blockIdx.y * 128, bh = blockIdx.z;

    uint32_t bAh = smem_u32(sAh), bAl = smem_u32(sAl), bBh = smem_u32(sBh), bBl = smem_u32(sBl);
    float acc[2][4][4] = {};
    int mat = lane >> 3, r8 = lane & 7;

    for (int kc = 0; kc < 2; kc++) {
        #pragma unroll
        for (int i = t; i < 512; i += 256) {
            int row = i >> 2, seg = i & 3;
            size_t ga = ((size_t)bh * SS + i0 + row) * HD + kc * 32 + seg * 8;
            *(uint4*)&sAh[row * PSTR + seg * 8] = *(const uint4*)&qhi[ga];
            *(uint4*)&sAl[row * PSTR + seg * 8] = *(const uint4*)&qlo[ga];
        }
        {
            int row = t >> 2, seg = t & 3;
            size_t gb = ((size_t)bh * SS + j0 + row) * HD + kc * 32 + seg * 8;
            *(uint4*)&sBh[row * PSTR + seg * 8] = *(const uint4*)&khi[gb];
            *(uint4*)&sBl[row * PSTR + seg * 8] = *(const uint4*)&klo[gb];
        }
        __syncthreads();
        #pragma unroll
        for (int kk = 0; kk < 2; kk++) {
            uint32_t ah[2][4], al[2][4], bhf[4][2], blf[4][2];
            uint32_t aoff = (uint32_t)((wm * 32 + r8 + (mat & 1) * 8) * PSTR + kk * 16 + (mat >> 1) * 8) * 2;
            #pragma unroll
            for (int fm = 0; fm < 2; fm++) {
                uint32_t o = aoff + fm * 16 * PSTR * 2;
                ldsm4(ah[fm], bAh + o);
                ldsm4(al[fm], bAl + o);
            }
            uint32_t boff = (uint32_t)((wn * 32 + r8) * PSTR + kk * 16 + (mat & 1) * 8) * 2;
            #pragma unroll
            for (int fn = 0; fn < 4; fn++) {
                uint32_t o = boff + fn * 8 * PSTR * 2;
                ldsm2(bhf[fn], bBh + o);
                ldsm2(blf[fn], bBl + o);
            }
            #pragma unroll
            for (int fm = 0; fm < 2; fm++)
                #pragma unroll
                for (int fn = 0; fn < 4; fn++) {
                    mma_bf16(acc[fm][fn], ah[fm], bhf[fn]);
                    mma_bf16(acc[fm][fn], ah[fm], blf[fn]);
                    mma_bf16(acc[fm][fn], al[fm], bhf[fn]);
                }
        }
        __syncthreads();
    }

    float* sbase = s + (size_t)bh * SS * SS;
    #pragma unroll
    for (int fm = 0; fm < 2; fm++)
        #pragma unroll
        for (int fn = 0; fn < 4; fn++)
            #pragma unroll
            for (int drp = 0; drp < 2; drp++) {
                int mi = i0 + wm * 32 + fm * 16 + (lane >> 2) + drp * 8;
                int nj = j0 + wn * 32 + fn * 8 + (lane & 3) * 2;
                float2 o;
                float v0 = acc[fm][fn][drp * 2 + 0] * 0.125f;
                float v1 = acc[fm][fn][drp * 2 + 1] * 0.125f;
                if (isnan(v0)) v0 = 0.f; else if (isinf(v0)) v0 = v0 > 0.f ? 10.f : -10.f;
                if (isnan(v1)) v1 = 0.f; else if (isinf(v1)) v1 = v1 > 0.f ? 10.f : -10.f;
                o.x = clipf(v0, -15.f, 15.f);
                o.y = clipf(v1, -15.f, 15.f);
                *(float2*)&sbase[(size_t)mi * SS + nj] = o;
            }
}

// ================= batched attn @ V (128x64, 2 CTA/SM) =================
__global__ void __launch_bounds__(256, 2) av_mma(
    const __nv_bfloat16* __restrict__ ahi, const __nv_bfloat16* __restrict__ alo,
    const __nv_bfloat16* __restrict__ vthi, const __nv_bfloat16* __restrict__ vtlo,
    __nv_bfloat16* __restrict__ ohi, __nv_bfloat16* __restrict__ olo)
{
    __shared__ __nv_bfloat16 sAh[128*PSTR], sAl[128*PSTR], sBh[64*PSTR], sBl[64*PSTR];
    int t = threadIdx.x, lane = t & 31, wid = t >> 5;
    int wm = wid >> 2, wn = wid & 3;
    int i0 = blockIdx.x * 128, bh = blockIdx.y;
    int b = bh >> 3, h = bh & 7;

    uint32_t bAh = smem_u32(sAh), bAl = smem_u32(sAl), bBh = smem_u32(sBh), bBl = smem_u32(sBl);
    float acc[4][2][4] = {};
    int mat = lane >> 3, r8 = lane & 7;

    for (int kc = 0; kc < 16; kc++) {
        #pragma unroll
        for (int i = t; i < 512; i += 256) {
            int row = i >> 2, seg = i & 3;
            size_t ga = (size_t)bh * SS * SS + (size_t)(i0 + row) * SS + kc * 32 + seg * 8;
            *(uint4*)&sAh[row * PSTR + seg * 8] = *(const uint4*)&ahi[ga];
            *(uint4*)&sAl[row * PSTR + seg * 8] = *(const uint4*)&alo[ga];
        }
        {
            int row = t >> 2, seg = t & 3;
            size_t gb = ((size_t)bh * HD + row) * SS + kc * 32 + seg * 8;
            *(uint4*)&sBh[row * PSTR + seg * 8] = *(const uint4*)&vthi[gb];
            *(uint4*)&sBl[row * PSTR + seg * 8] = *(const uint4*)&vtlo[gb];
        }
        __syncthreads();
        #pragma unroll
        for (int kk = 0; kk < 2; kk++) {
            uint32_t ah[4][4], al[4][4], bhf[2][2], blf[2][2];
            uint32_t aoff = (uint32_t)((wm * 64 + r8 + (mat & 1) * 8) * PSTR + kk * 16 + (mat >> 1) * 8) * 2;
            #pragma unroll
            for (int fm = 0; fm < 4; fm++) {
                uint32_t o = aoff + fm * 16 * PSTR * 2;
                ldsm4(ah[fm], bAh + o);
                ldsm4(al[fm], bAl + o);
            }
            uint32_t boff = (uint32_t)((wn * 16 + r8) * PSTR + kk * 16 + (mat & 1) * 8) * 2;
            #pragma unroll
            for (int fn = 0; fn < 2; fn++) {
                uint32_t o = boff + fn * 8 * PSTR * 2;
                ldsm2(bhf[fn], bBh + o);
                ldsm2(blf[fn], bBl + o);
            }
            #pragma unroll
            for (int fm = 0; fm < 4; fm++)
                #pragma unroll
                for (int fn = 0; fn < 2; fn++) {
                    mma_bf16(acc[fm][fn], ah[fm], bhf[fn]);
                    mma_bf16(acc[fm][fn], ah[fm], blf[fn]);
                    mma_bf16(acc[fm][fn], al[fm], bhf[fn]);
                }
        }
        __syncthreads();
    }

    #pragma unroll
    for (int fm = 0; fm < 4; fm++)
        #pragma unroll
        for (int fn = 0; fn < 2; fn++)
            #pragma unroll
            for (int drp = 0; drp < 2; drp++) {
                int si = i0 + wm * 64 + fm * 16 + (lane >> 2) + drp * 8;
                int d  = wn * 16 + fn * 8 + (lane & 3) * 2;
                float v0 = acc[fm][fn][drp * 2 + 0];
                float v1 = acc[fm][fn][drp * 2 + 1];
                size_t dst = ((size_t)b * SS + si) * EE + h * HD + d;
                __nv_bfloat16 h0 = __float2bfloat16_rn(v0);
                __nv_bfloat16 h1 = __float2bfloat16_rn(v1);
                *(__nv_bfloat162*)&ohi[dst] = __nv_bfloat162(h0, h1);
                *(__nv_bfloat162*)&olo[dst] = __nv_bfloat162(
                    __float2bfloat16_rn(v0 - __bfloat162float(h0)),
                    __float2bfloat16_rn(v1 - __bfloat162float(h1)));
            }
}

// ================= init accumulators =================
__global__ void init_acc()
{
    int t = threadIdx.x;
    if (t < BB * 5) g_acc[t] = 0.0;
    if (t < BB) g_amax[t] = 0;
}

// ================= fused head-mean + row transform (warp-per-row, float4) =================
__global__ void __launch_bounds__(256) row_transform_fused(
    const float* __restrict__ s, float* __restrict__ ma, float* __restrict__ tp,
    const float* __restrict__ w1, const float* __restrict__ b1,
    const float* __restrict__ w2, const float* __restrict__ b2)
{
    __shared__ float w1s[CC], b1s[CC], w2s[CC];
    int t = threadIdx.x, lane = t & 31, w = t >> 5;
    if (t < CC) { w1s[t] = w1[t]; b1s[t] = b1[t]; w2s[t] = w2[t]; }
    __syncthreads();

    int row = blockIdx.x * 8 + w;
    int b = row >> 9, i = row & 511;
    const float* sb = s + ((size_t)b * HH * SS + i) * SS;
    float* marow = ma + ((size_t)b * SS + i) * SS;
    float* tprow = tp + ((size_t)b * SS + i) * SS;

    // head mean via float4 (16 elems/lane as 4 float4s)
    float m[16];
    #pragma unroll
    for (int e2 = 0; e2 < 4; e2++) {
        int f = lane + 32 * e2;
        float4 acc4 = make_float4(0.f, 0.f, 0.f, 0.f);
        #pragma unroll
        for (int hh = 0; hh < HH; hh++) {
            float4 v = ((const float4*)(sb + (size_t)hh * SS * SS))[f];
            acc4.x += v.x; acc4.y += v.y; acc4.z += v.z; acc4.w += v.w;
        }
        acc4.x *= 0.125f; acc4.y *= 0.125f; acc4.z *= 0.125f; acc4.w *= 0.125f;
        ((float4*)marow)[f] = acc4;
        m[e2 * 4 + 0] = acc4.x; m[e2 * 4 + 1] = acc4.y;
        m[e2 * 4 + 2] = acc4.z; m[e2 * 4 + 3] = acc4.w;
    }

    float mx = -1e30f;
    #pragma unroll
    for (int e = 0; e < 16; e++) mx = fmaxf(mx, clipf(m[e], -10.f, 10.f));
    mx = warpMax(mx);
    float a_[16]; float sum = 0.f;
    #pragma unroll
    for (int e = 0; e < 16; e++) { a_[e] = __expf(clipf(m[e], -10.f, 10.f) - mx); sum += a_[e]; }
    sum = warpSum(sum);
    float inv = 1.f / sum;
    float h_[16];
    #pragma unroll
    for (int e = 0; e < 16; e++) { float p = a_[e] * inv; h_[e] = -p * __logf(p + 1e-6f); }

    float sma = 0.f, sma2 = 0.f, shh = 0.f, amx = 0.f;
    #pragma unroll
    for (int e = 0; e < 16; e++) {
        sma += m[e]; sma2 += m[e] * m[e]; shh += h_[e]; amx = fmaxf(amx, fabsf(m[e]));
    }
    sma = warpSum(sma); sma2 = warpSum(sma2); shh = warpSum(shh); amx = warpMax(amx);

    float hmx = -1e30f;
    #pragma unroll
    for (int e = 0; e < 16; e++) hmx = fmaxf(hmx, h_[e]);
    hmx = warpMax(hmx) * 3.f;
    float fsum = 0.f;
    #pragma unroll
    for (int e = 0; e < 16; e++) { h_[e] = __expf(3.f * h_[e] - hmx); fsum += h_[e]; }
    fsum = warpSum(fsum);
    float finv = 1.f / fsum;

    float sa[16], acc[16];
    #pragma unroll
    for (int e = 0; e < 16; e++) {
        sa[e] = clipf(clipf(m[e], -8.f, 8.f) * 0.05f, -10.f, 10.f);
        acc[e] = 0.f;
    }
    #pragma unroll 4
    for (int c = 0; c < CC; c++) {
        float wv = w1s[c], bb = b1s[c], w2v = w2s[c];
        #pragma unroll
        for (int e = 0; e < 16; e++)
            acc[e] += fminf(fmaxf(sa[e] * wv + bb, 0.f), 5.f) * w2v;
    }
    float b2v = b2[0];
    float stt = 0.f, st2 = 0.f;
    #pragma unroll
    for (int e2 = 0; e2 < 4; e2++) {
        float4 o;
        float* op = (float*)&o;
        #pragma unroll
        for (int q = 0; q < 4; q++) {
            int e = e2 * 4 + q;
            float ap = clipf(acc[e] + b2v, -5.f, 5.f);
            float ty = clipf(1.f + 2.5f * ap, 0.5f, 1.5f);
            float sg = 1.f / (1.f + __expf(-ty));
            float tv = sg * (h_[e] * finv);
            op[q] = tv;
            stt += tv; st2 += tv * tv;
        }
        ((float4*)tprow)[lane + 32 * e2] = o;
    }
    stt = warpSum(stt); st2 = warpSum(st2);

    if (lane == 0) {
        atomicAdd(&g_acc[b * 5 + 0], (double)sma);
        atomicAdd(&g_acc[b * 5 + 1], (double)sma2);
        atomicAdd(&g_acc[b * 5 + 2], (double)shh);
        atomicAdd(&g_acc[b * 5 + 3], (double)stt);
        atomicAdd(&g_acc[b * 5 + 4], (double)st2);
        atomicMax(&g_amax[b], __float_as_int(amx));
    }
}

__global__ void finalize_kernel()
{
    int b = threadIdx.x;
    if (b < BB) {
        const double N = (double)SS * (double)SS;
        double sma  = g_acc[b * 5 + 0];
        double sma2 = g_acc[b * 5 + 1];
        double sh   = g_acc[b * 5 + 2];
        double st   = g_acc[b * 5 + 3];
        double st2  = g_acc[b * 5 + 4];
        float amaxv = __int_as_float(g_amax[b]);

        float eo = sqrtf((float)sma2) + 1e-4f;
        float et = sqrtf((float)st2) + 1e-4f;
        float c  = clipf(eo / et, 0.8f, 1.2f);
        float tm = c * (float)(st / N);
        float tvar = c * c * (float)(st2 / N - (st / N) * (st / N));
        tvar = fmaxf(tvar, 0.01f);
        float ovar = (float)(sma2 / N - (sma / N) * (sma / N));
        ovar = fmaxf(ovar, 0.01f);
        float gd = clipf(sqrtf(ovar) / sqrtf(tvar), 0.8f, 1.2f);
        float ar = clipf(amaxv, 1.f, 10.f);
        float sm = clipf(0.3f / log1pf(ar), 0.1f, 0.5f);
        float ent = (float)(sh / N);
        float ne = ent / logf((float)SS);
        float rr = 0.4f * (1.f - clipf(ne, 0.f, 0.4f));
        float smgd = sm * gd;

        g_coef[b * 3 + 0] = rr * tm * (1.f - smgd);
        g_coef[b * 3 + 1] = rr * smgd * c;
        g_coef[b * 3 + 2] = rr;
    }
}

// ================= softmax + delta: CTA per (b,i), smem delta, 8 head-warps =================
// grid B*S = 2048 blocks x 256 threads
__global__ void __launch_bounds__(256) attn_softmax2(
    const float* __restrict__ s, const float* __restrict__ ma,
    const float* __restrict__ tp, const float* __restrict__ tau,
    __nv_bfloat16* __restrict__ ahi, __nv_bfloat16* __restrict__ alo)
{
    __shared__ float delta[SS];
    int t = threadIdx.x, lane = t & 31, w = t >> 5;
    int bi = blockIdx.x;
    int b = bi >> 9;

    float A  = g_coef[b * 3 + 0];
    float Bc = g_coef[b * 3 + 1];
    float Cc = g_coef[b * 3 + 2];
    float itau = 1.f / tau[0];

    // cooperative delta = A + Bc*tp - Cc*ma  (rows shared across 8 heads)
    {
        const float2* ma2 = (const float2*)(ma + (size_t)bi * SS);
        const float2* tp2 = (const float2*)(tp + (size_t)bi * SS);
        float2 mv = ma2[t], tv = tp2[t];
        delta[t * 2 + 0] = A + Bc * tv.x - Cc * mv.x;
        delta[t * 2 + 1] = A + Bc * tv.y - Cc * mv.y;
    }
    __syncthreads();

    // warp w handles head w
    int i = bi & 511;
    size_t row = ((size_t)(b * HH + w) * SS + i);
    const float4* srow4 = (const float4*)(s + row * SS);
    const float4* d4 = (const float4*)delta;

    float v[16];
    float mx = -1e30f;
    #pragma unroll
    for (int e2 = 0; e2 < 4; e2++) {
        int f = lane + 32 * e2;
        float4 sv = srow4[f];
        float4 dv = d4[f];
        v[e2*4+0] = (sv.x + dv.x) * itau;
        v[e2*4+1] = (sv.y + dv.y) * itau;
        v[e2*4+2] = (sv.z + dv.z) * itau;
        v[e2*4+3] = (sv.w + dv.w) * itau;
        mx = fmaxf(mx, fmaxf(fmaxf(v[e2*4+0], v[e2*4+1]), fmaxf(v[e2*4+2], v[e2*4+3])));
    }
    mx = warpMax(mx);
    float sum = 0.f;
    #pragma unroll
    for (int e = 0; e < 16; e++) { v[e] = __expf(v[e] - mx); sum += v[e]; }
    sum = warpSum(sum);
    float inv = 1.f / sum;

    uint2* arow_h = (uint2*)(ahi + row * SS);
    uint2* arow_l = (uint2*)(alo + row * SS);
    #pragma unroll
    for (int e2 = 0; e2 < 4; e2++) {
        int f = lane + 32 * e2;
        float p0 = v[e2*4+0] * inv, p1 = v[e2*4+1] * inv;
        float p2 = v[e2*4+2] * inv, p3 = v[e2*4+3] * inv;
        __nv_bfloat16 h0 = __float2bfloat16_rn(p0), h1 = __float2bfloat16_rn(p1);
        __nv_bfloat16 h2 = __float2bfloat16_rn(p2), h3 = __float2bfloat16_rn(p3);
        uint2 ho, lo2;
        ho.x = pack_bf162(p0, p1); ho.y = pack_bf162(p2, p3);
        lo2.x = pack_bf162(p0 - __bfloat162float(h0), p1 - __bfloat162float(h1));
        lo2.y = pack_bf162(p2 - __bfloat162float(h2), p3 - __bfloat162float(h3));
        arow_h[f] = ho;
        arow_l[f] = lo2;
    }
}

// ---------------- launch ----------------
extern "C" void kernel_launch(void* const* d_in, const int* in_sizes, int n_in,
                              void* d_out, int out_size)
{
    const float* x  = (const float*)d_in[0];
    const float* Wq = (const float*)d_in[1];
    const float* bq = (const float*)d_in[2];
    const float* Wk = (const float*)d_in[3];
    const float* bk = (const float*)d_in[4];
    const float* Wv = (const float*)d_in[5];
    const float* bv = (const float*)d_in[6];
    const float* Wo = (const float*)d_in[7];
    const float* bo = (const float*)d_in[8];
    const float* w1 = (const float*)d_in[9];
    const float* b1 = (const float*)d_in[10];
    const float* w2 = (const float*)d_in[11];
    const float* b2 = (const float*)d_in[12];
    const float* tau = (const float*)d_in[13];
    float* out = (float*)d_out;

    __nv_bfloat16 *pxhi, *pxlo, *pwthi, *pwtlo, *pqhi, *pqlo, *pkhi, *pklo, *pvthi, *pvtlo;
    __nv_bfloat16 *pahi, *palo, *pohhi, *pohlo;
    float *ps, *pma, *ptp;
    cudaGetSymbolAddress((void**)&pxhi, g_xhi);
    cudaGetSymbolAddress((void**)&pxlo, g_xlo);
    cudaGetSymbolAddress((void**)&pwthi, g_wthi);
    cudaGetSymbolAddress((void**)&pwtlo, g_wtlo);
    cudaGetSymbolAddress((void**)&pqhi, g_qhi);
    cudaGetSymbolAddress((void**)&pqlo, g_qlo);
    cudaGetSymbolAddress((void**)&pkhi, g_khi);
    cudaGetSymbolAddress((void**)&pklo, g_klo);
    cudaGetSymbolAddress((void**)&pvthi, g_vthi);
    cudaGetSymbolAddress((void**)&pvtlo, g_vtlo);
    cudaGetSymbolAddress((void**)&pahi, g_ahi);
    cudaGetSymbolAddress((void**)&palo, g_alo);
    cudaGetSymbolAddress((void**)&pohhi, g_ohhi);
    cudaGetSymbolAddress((void**)&pohlo, g_ohlo);
    cudaGetSymbolAddress((void**)&ps, g_s);
    cudaGetSymbolAddress((void**)&pma, g_ma);
    cudaGetSymbolAddress((void**)&ptp, g_tp);

    // 1) conversions
    conv_split<<<(NROW * EE / 4) / 256, 256>>>(x, pxhi, pxlo, NROW * EE);
    conv_w4<<<dim3(16, 16, 4), dim3(32, 8)>>>(Wq, Wk, Wv, Wo, pwthi, pwtlo);

    // 2) fused QKV projection (128x64 tiles, 2 CTA/SM)
    proj_qkv<<<dim3(8, 16, 3), 256>>>(pxhi, pxlo, pwthi, pwtlo, bq, bk, bv,
                                      pqhi, pqlo, pkhi, pklo, pvthi, pvtlo);

    // 3) QK^T (128x64 tiles, 2 CTA/SM)
    qk_mma<<<dim3(8, 4, BB * HH), 256>>>(pqhi, pqlo, pkhi, pklo, ps);

    // 4) fused head-mean + transform + stats
    init_acc<<<1, 32>>>();
    row_transform_fused<<<256, 256>>>(ps, pma, ptp, w1, b1, w2, b2);
    finalize_kernel<<<1, 32>>>();

    // 5) softmax -> attn hi/lo (CTA per (b,i), shared delta)
    attn_softmax2<<<BB * SS, 256>>>(ps, pma, ptp, tau, pahi, palo);

    // 6) attn @ V
    av_mma<<<dim3(4, BB * HH), 256>>>(pahi, palo, pvthi, pvtlo, pohhi, pohlo);

    // 7) output projection (128x64 tiles, 2 CTA/SM) -> fp32 out
    proj_out<<<dim3(8, 16), 256>>>(pohhi, pohlo, pwthi, pwtlo, bo, out);
}

// round 12
// speedup vs baseline: 1.5868x; 1.0232x over previous
#include <cuda_runtime.h>
#include <cuda_bf16.h>
#include <math.h>
#include <stdint.h>

#define BB 4
#define SS 512
#define EE 512
#define HH 8
#define HD 64
#define CC 128
#define NROW (BB*SS)          // 2048
#define PSTR 40               // smem row stride in bf16 (80B) -> conflict-free ldmatrix

// ---------------- scratch (static device globals; no allocation) ----------------
__device__ __nv_bfloat16 g_xhi[NROW*EE], g_xlo[NROW*EE];
__device__ __nv_bfloat16 g_wthi[4*EE*EE], g_wtlo[4*EE*EE];           // transposed [n][k]
__device__ __nv_bfloat16 g_qhi[BB*HH*SS*HD], g_qlo[BB*HH*SS*HD];     // [bh][s][d]
__device__ __nv_bfloat16 g_khi[BB*HH*SS*HD], g_klo[BB*HH*SS*HD];     // [bh][s][d]
__device__ __nv_bfloat16 g_vthi[BB*HH*HD*SS], g_vtlo[BB*HH*HD*SS];   // [bh][d][s]
__device__ float g_s[(size_t)BB*HH*SS*SS];                           // 32MB
__device__ float g_ma[BB*SS*SS];
__device__ float g_tp[BB*SS*SS];
__device__ __nv_bfloat16 g_ahi[(size_t)BB*HH*SS*SS], g_alo[(size_t)BB*HH*SS*SS];
__device__ __nv_bfloat16 g_ohhi[NROW*EE], g_ohlo[NROW*EE];           // [B,S,E]
__device__ double g_acc[BB*5];
__device__ int    g_amax[BB];
__device__ float  g_coef[BB*3];

// ---------------- helpers ----------------
__device__ __forceinline__ float clipf(float v, float lo, float hi) {
    return fminf(fmaxf(v, lo), hi);
}
__device__ __forceinline__ uint32_t smem_u32(const void* p) {
    uint32_t a;
    asm("{ .reg .u64 t; cvta.to.shared.u64 t, %1; cvt.u32.u64 %0, t; }" : "=r"(a) : "l"(p));
    return a;
}
__device__ __forceinline__ void ldsm4(uint32_t* a, uint32_t addr) {
    asm volatile("ldmatrix.sync.aligned.m8n8.x4.shared.b16 {%0,%1,%2,%3}, [%4];"
        : "=r"(a[0]), "=r"(a[1]), "=r"(a[2]), "=r"(a[3]) : "r"(addr));
}
__device__ __forceinline__ void ldsm2(uint32_t* a, uint32_t addr) {
    asm volatile("ldmatrix.sync.aligned.m8n8.x2.shared.b16 {%0,%1}, [%2];"
        : "=r"(a[0]), "=r"(a[1]) : "r"(addr));
}
__device__ __forceinline__ void mma_bf16(float* d, const uint32_t* a, const uint32_t* b) {
    asm volatile("mma.sync.aligned.m16n8k16.row.col.f32.bf16.bf16.f32 "
        "{%0,%1,%2,%3}, {%4,%5,%6,%7}, {%8,%9}, {%0,%1,%2,%3};"
        : "+f"(d[0]), "+f"(d[1]), "+f"(d[2]), "+f"(d[3])
        : "r"(a[0]), "r"(a[1]), "r"(a[2]), "r"(a[3]), "r"(b[0]), "r"(b[1]));
}
__device__ __forceinline__ float warpSum(float v) {
    #pragma unroll
    for (int o = 16; o > 0; o >>= 1) v += __shfl_xor_sync(0xffffffffu, v, o);
    return v;
}
__device__ __forceinline__ float warpMax(float v) {
    #pragma unroll
    for (int o = 16; o > 0; o >>= 1) v = fmaxf(v, __shfl_xor_sync(0xffffffffu, v, o));
    return v;
}
__device__ __forceinline__ uint32_t pack_bf162(float a, float b) {
    __nv_bfloat162 r(__float2bfloat16_rn(a), __float2bfloat16_rn(b));
    return *(uint32_t*)&r;
}

// ================= conversion kernels =================
// also zero-inits the per-batch accumulators (block 0) to save a launch
__global__ void conv_split(const float* __restrict__ in, __nv_bfloat16* __restrict__ hi,
                           __nv_bfloat16* __restrict__ lo, int n)
{
    if (blockIdx.x == 0 && threadIdx.x < 32) {
        int t = threadIdx.x;
        if (t < BB * 5) g_acc[t] = 0.0;
        if (t < BB) g_amax[t] = 0;
    }
    int i = (blockIdx.x * 256 + threadIdx.x) * 4;
    if (i < n) {
        float4 v = *(const float4*)(in + i);
        __nv_bfloat16 h0 = __float2bfloat16_rn(v.x);
        __nv_bfloat16 h1 = __float2bfloat16_rn(v.y);
        __nv_bfloat16 h2 = __float2bfloat16_rn(v.z);
        __nv_bfloat16 h3 = __float2bfloat16_rn(v.w);
        __nv_bfloat162 H0(h0, h1), H1(h2, h3);
        __nv_bfloat162 L0(__float2bfloat16_rn(v.x - __bfloat162float(h0)),
                          __float2bfloat16_rn(v.y - __bfloat162float(h1)));
        __nv_bfloat162 L1(__float2bfloat16_rn(v.z - __bfloat162float(h2)),
                          __float2bfloat16_rn(v.w - __bfloat162float(h3)));
        *(__nv_bfloat162*)(hi + i)     = H0;
        *(__nv_bfloat162*)(hi + i + 2) = H1;
        *(__nv_bfloat162*)(lo + i)     = L0;
        *(__nv_bfloat162*)(lo + i + 2) = L1;
    }
}

// transpose + split: wt[n][k] = W[k][n]; grid.z selects which W
__global__ void conv_w4(const float* __restrict__ Wq, const float* __restrict__ Wk,
                        const float* __restrict__ Wv, const float* __restrict__ Wo,
                        __nv_bfloat16* __restrict__ thi, __nv_bfloat16* __restrict__ tlo)
{
    __shared__ float tile[32][33];
    int z = blockIdx.z;
    const float* W = (z == 0) ? Wq : (z == 1) ? Wk : (z == 2) ? Wv : Wo;
    __nv_bfloat16* th = thi + (size_t)z * EE * EE;
    __nv_bfloat16* tl = tlo + (size_t)z * EE * EE;
    int bx = blockIdx.x * 32, by = blockIdx.y * 32;
    int x = threadIdx.x, y = threadIdx.y;
    #pragma unroll
    for (int j = 0; j < 4; j++)
        tile[y + j * 8][x] = W[(size_t)(by + y + j * 8) * EE + bx + x];
    __syncthreads();
    #pragma unroll
    for (int j = 0; j < 4; j++) {
        float v = tile[x][y + j * 8];
        __nv_bfloat16 h = __float2bfloat16_rn(v);
        size_t dst = (size_t)(bx + y + j * 8) * EE + by + x;
        th[dst] = h;
        tl[dst] = __float2bfloat16_rn(v - __bfloat162float(h));
    }
}

// ================= fused QKV projection: 128x64 tiles, 2 CTA/SM =================
__global__ void __launch_bounds__(256, 2) proj_qkv(
    const __nv_bfloat16* __restrict__ xhi, const __nv_bfloat16* __restrict__ xlo,
    const __nv_bfloat16* __restrict__ wthi, const __nv_bfloat16* __restrict__ wtlo,
    const float* __restrict__ bq, const float* __restrict__ bk, const float* __restrict__ bv,
    __nv_bfloat16* __restrict__ qhi, __nv_bfloat16* __restrict__ qlo,
    __nv_bfloat16* __restrict__ khi, __nv_bfloat16* __restrict__ klo,
    __nv_bfloat16* __restrict__ vthi, __nv_bfloat16* __restrict__ vtlo)
{
    __shared__ __nv_bfloat16 sAh[128*PSTR], sAl[128*PSTR], sBh[64*PSTR], sBl[64*PSTR];
    int t = threadIdx.x, lane = t & 31, wid = t >> 5;
    int wm = wid >> 1, wn = wid & 1;
    int z = blockIdx.z;
    int n0 = blockIdx.x * 64, m0 = blockIdx.y * 128;
    const __nv_bfloat16* Bh = wthi + (size_t)z * EE * EE;
    const __nv_bfloat16* Bl = wtlo + (size_t)z * EE * EE;
    const float* bias = (z == 0) ? bq : ((z == 1) ? bk : bv);

    uint32_t bAh = smem_u32(sAh), bAl = smem_u32(sAl), bBh = smem_u32(sBh), bBl = smem_u32(sBl);
    float acc[2][4][4] = {};
    int mat = lane >> 3, r8 = lane & 7;

    for (int kc = 0; kc < 16; kc++) {
        #pragma unroll
        for (int i = t; i < 512; i += 256) {
            int row = i >> 2, seg = i & 3;
            size_t ga = (size_t)(m0 + row) * EE + kc * 32 + seg * 8;
            *(uint4*)&sAh[row * PSTR + seg * 8] = *(const uint4*)&xhi[ga];
            *(uint4*)&sAl[row * PSTR + seg * 8] = *(const uint4*)&xlo[ga];
        }
        {
            int row = t >> 2, seg = t & 3;
            size_t gb = (size_t)(n0 + row) * EE + kc * 32 + seg * 8;
            *(uint4*)&sBh[row * PSTR + seg * 8] = *(const uint4*)&Bh[gb];
            *(uint4*)&sBl[row * PSTR + seg * 8] = *(const uint4*)&Bl[gb];
        }
        __syncthreads();
        #pragma unroll
        for (int kk = 0; kk < 2; kk++) {
            uint32_t ah[2][4], al[2][4], bhf[4][2], blf[4][2];
            uint32_t aoff = (uint32_t)((wm * 32 + r8 + (mat & 1) * 8) * PSTR + kk * 16 + (mat >> 1) * 8) * 2;
            #pragma unroll
            for (int fm = 0; fm < 2; fm++) {
                uint32_t o = aoff + fm * 16 * PSTR * 2;
                ldsm4(ah[fm], bAh + o);
                ldsm4(al[fm], bAl + o);
            }
            uint32_t boff = (uint32_t)((wn * 32 + r8) * PSTR + kk * 16 + (mat & 1) * 8) * 2;
            #pragma unroll
            for (int fn = 0; fn < 4; fn++) {
                uint32_t o = boff + fn * 8 * PSTR * 2;
                ldsm2(bhf[fn], bBh + o);
                ldsm2(blf[fn], bBl + o);
            }
            #pragma unroll
            for (int fm = 0; fm < 2; fm++)
                #pragma unroll
                for (int fn = 0; fn < 4; fn++) {
                    mma_bf16(acc[fm][fn], ah[fm], bhf[fn]);
                    mma_bf16(acc[fm][fn], ah[fm], blf[fn]);
                    mma_bf16(acc[fm][fn], al[fm], bhf[fn]);
                }
        }
        __syncthreads();
    }

    #pragma unroll
    for (int fm = 0; fm < 2; fm++)
        #pragma unroll
        for (int fn = 0; fn < 4; fn++)
            #pragma unroll
            for (int drp = 0; drp < 2; drp++) {
                int m = m0 + wm * 32 + fm * 16 + (lane >> 2) + drp * 8;
                int n = n0 + wn * 32 + fn * 8 + (lane & 3) * 2;
                float v0 = acc[fm][fn][drp * 2 + 0] + bias[n];
                float v1 = acc[fm][fn][drp * 2 + 1] + bias[n + 1];
                int b = m >> 9, s = m & 511;
                int h = n >> 6, d = n & 63;
                __nv_bfloat16 h0 = __float2bfloat16_rn(v0);
                __nv_bfloat16 h1 = __float2bfloat16_rn(v1);
                float l0 = v0 - __bfloat162float(h0);
                float l1 = v1 - __bfloat162float(h1);
                if (z == 0) {
                    size_t dst = (((size_t)(b * HH + h) * SS) + s) * HD + d;
                    *(__nv_bfloat162*)&qhi[dst] = __nv_bfloat162(h0, h1);
                    *(__nv_bfloat162*)&qlo[dst] = __nv_bfloat162(__float2bfloat16_rn(l0), __float2bfloat16_rn(l1));
                } else if (z == 1) {
                    size_t dst = (((size_t)(b * HH + h) * SS) + s) * HD + d;
                    *(__nv_bfloat162*)&khi[dst] = __nv_bfloat162(h0, h1);
                    *(__nv_bfloat162*)&klo[dst] = __nv_bfloat162(__float2bfloat16_rn(l0), __float2bfloat16_rn(l1));
                } else {
                    size_t dst0 = (((size_t)(b * HH + h) * HD) + d) * SS + s;
                    vthi[dst0] = h0; vtlo[dst0] = __float2bfloat16_rn(l0);
                    size_t dst1 = dst0 + SS;
                    vthi[dst1] = h1; vtlo[dst1] = __float2bfloat16_rn(l1);
                }
            }
}

// ================= output projection: 64x64 tiles (grid fill), fp32 result =================
// grid (8 n, 32 m); warps 4x2; warp tile 16x32
__global__ void __launch_bounds__(256, 2) proj_out(
    const __nv_bfloat16* __restrict__ ahi, const __nv_bfloat16* __restrict__ alo,
    const __nv_bfloat16* __restrict__ wthi, const __nv_bfloat16* __restrict__ wtlo,
    const float* __restrict__ bias, float* __restrict__ out)
{
    __shared__ __nv_bfloat16 sAh[64*PSTR], sAl[64*PSTR], sBh[64*PSTR], sBl[64*PSTR];
    int t = threadIdx.x, lane = t & 31, wid = t >> 5;
    int wm = wid >> 1, wn = wid & 1;
    int n0 = blockIdx.x * 64, m0 = blockIdx.y * 64;
    const __nv_bfloat16* Bh = wthi + (size_t)3 * EE * EE;
    const __nv_bfloat16* Bl = wtlo + (size_t)3 * EE * EE;

    uint32_t bAh = smem_u32(sAh), bAl = smem_u32(sAl), bBh = smem_u32(sBh), bBl = smem_u32(sBl);
    float acc[4][4] = {};
    int mat = lane >> 3, r8 = lane & 7;

    for (int kc = 0; kc < 16; kc++) {
        {
            int row = t >> 2, seg = t & 3;   // 64 rows x 4 segs
            size_t ga = (size_t)(m0 + row) * EE + kc * 32 + seg * 8;
            *(uint4*)&sAh[row * PSTR + seg * 8] = *(const uint4*)&ahi[ga];
            *(uint4*)&sAl[row * PSTR + seg * 8] = *(const uint4*)&alo[ga];
            size_t gb = (size_t)(n0 + row) * EE + kc * 32 + seg * 8;
            *(uint4*)&sBh[row * PSTR + seg * 8] = *(const uint4*)&Bh[gb];
            *(uint4*)&sBl[row * PSTR + seg * 8] = *(const uint4*)&Bl[gb];
        }
        __syncthreads();
        #pragma unroll
        for (int kk = 0; kk < 2; kk++) {
            uint32_t ah[4], al[4], bhf[4][2], blf[4][2];
            uint32_t aoff = (uint32_t)((wm * 16 + r8 + (mat & 1) * 8) * PSTR + kk * 16 + (mat >> 1) * 8) * 2;
            ldsm4(ah, bAh + aoff);
            ldsm4(al, bAl + aoff);
            uint32_t boff = (uint32_t)((wn * 32 + r8) * PSTR + kk * 16 + (mat & 1) * 8) * 2;
            #pragma unroll
            for (int fn = 0; fn < 4; fn++) {
                uint32_t o = boff + fn * 8 * PSTR * 2;
                ldsm2(bhf[fn], bBh + o);
                ldsm2(blf[fn], bBl + o);
            }
            #pragma unroll
            for (int fn = 0; fn < 4; fn++) {
                mma_bf16(acc[fn], ah, bhf[fn]);
                mma_bf16(acc[fn], ah, blf[fn]);
                mma_bf16(acc[fn], al, bhf[fn]);
            }
        }
        __syncthreads();
    }

    #pragma unroll
    for (int fn = 0; fn < 4; fn++)
        #pragma unroll
        for (int drp = 0; drp < 2; drp++) {
            int m = m0 + wm * 16 + (lane >> 2) + drp * 8;
            int n = n0 + wn * 32 + fn * 8 + (lane & 3) * 2;
            float2 v;
            v.x = acc[fn][drp * 2 + 0] + bias[n];
            v.y = acc[fn][drp * 2 + 1] + bias[n + 1];
            *(float2*)&out[(size_t)m * EE + n] = v;
        }
}

// ================= batched QK^T: 128x64 tiles, 2 CTA/SM =================
__global__ void __launch_bounds__(256, 2) qk_mma(
    const __nv_bfloat16* __restrict__ qhi, const __nv_bfloat16* __restrict__ qlo,
    const __nv_bfloat16* __restrict__ khi, const __nv_bfloat16* __restrict__ klo,
    float* __restrict__ s)
{
    __shared__ __nv_bfloat16 sAh[128*PSTR], sAl[128*PSTR], sBh[64*PSTR], sBl[64*PSTR];
    int t = threadIdx.x, lane = t & 31, wid = t >> 5;
    int wm = wid >> 1, wn = wid & 1;
    int j0 = blockIdx.x * 64, i0 = blockIdx.y * 128, bh = blockIdx.z;

    uint32_t bAh = smem_u32(sAh), bAl = smem_u32(sAl), bBh = smem_u32(sBh), bBl = smem_u32(sBl);
    float acc[2][4][4] = {};
    int mat = lane >> 3, r8 = lane & 7;

    for (int kc = 0; kc < 2; kc++) {
        #pragma unroll
        for (int i = t; i < 512; i += 256) {
            int row = i >> 2, seg = i & 3;
            size_t ga = ((size_t)bh * SS + i0 + row) * HD + kc * 32 + seg * 8;
            *(uint4*)&sAh[row * PSTR + seg * 8] = *(const uint4*)&qhi[ga];
            *(uint4*)&sAl[row * PSTR + seg * 8] = *(const uint4*)&qlo[ga];
        }
        {
            int row = t >> 2, seg = t & 3;
            size_t gb = ((size_t)bh * SS + j0 + row) * HD + kc * 32 + seg * 8;
            *(uint4*)&sBh[row * PSTR + seg * 8] = *(const uint4*)&khi[gb];
            *(uint4*)&sBl[row * PSTR + seg * 8] = *(const uint4*)&klo[gb];
        }
        __syncthreads();
        #pragma unroll
        for (int kk = 0; kk < 2; kk++) {
            uint32_t ah[2][4], al[2][4], bhf[4][2], blf[4][2];
            uint32_t aoff = (uint32_t)((wm * 32 + r8 + (mat & 1) * 8) * PSTR + kk * 16 + (mat >> 1) * 8) * 2;
            #pragma unroll
            for (int fm = 0; fm < 2; fm++) {
                uint32_t o = aoff + fm * 16 * PSTR * 2;
                ldsm4(ah[fm], bAh + o);
                ldsm4(al[fm], bAl + o);
            }
            uint32_t boff = (uint32_t)((wn * 32 + r8) * PSTR + kk * 16 + (mat & 1) * 8) * 2;
            #pragma unroll
            for (int fn = 0; fn < 4; fn++) {
                uint32_t o = boff + fn * 8 * PSTR * 2;
                ldsm2(bhf[fn], bBh + o);
                ldsm2(blf[fn], bBl + o);
            }
            #pragma unroll
            for (int fm = 0; fm < 2; fm++)
                #pragma unroll
                for (int fn = 0; fn < 4; fn++) {
                    mma_bf16(acc[fm][fn], ah[fm], bhf[fn]);
                    mma_bf16(acc[fm][fn], ah[fm], blf[fn]);
                    mma_bf16(acc[fm][fn], al[fm], bhf[fn]);
                }
        }
        __syncthreads();
    }

    float* sbase = s + (size_t)bh * SS * SS;
    #pragma unroll
    for (int fm = 0; fm < 2; fm++)
        #pragma unroll
        for (int fn = 0; fn < 4; fn++)
            #pragma unroll
            for (int drp = 0; drp < 2; drp++) {
                int mi = i0 + wm * 32 + fm * 16 + (lane >> 2) + drp * 8;
                int nj = j0 + wn * 32 + fn * 8 + (lane & 3) * 2;
                float2 o;
                float v0 = acc[fm][fn][drp * 2 + 0] * 0.125f;
                float v1 = acc[fm][fn][drp * 2 + 1] * 0.125f;
                if (isnan(v0)) v0 = 0.f; else if (isinf(v0)) v0 = v0 > 0.f ? 10.f : -10.f;
                if (isnan(v1)) v1 = 0.f; else if (isinf(v1)) v1 = v1 > 0.f ? 10.f : -10.f;
                o.x = clipf(v0, -15.f, 15.f);
                o.y = clipf(v1, -15.f, 15.f);
                *(float2*)&sbase[(size_t)mi * SS + nj] = o;
            }
}

// ================= batched attn @ V: 64x64 tiles (grid fill) =================
// grid (8 i, 32 bh); warps 4x2; warp tile 16x32
__global__ void __launch_bounds__(256, 2) av_mma(
    const __nv_bfloat16* __restrict__ ahi, const __nv_bfloat16* __restrict__ alo,
    const __nv_bfloat16* __restrict__ vthi, const __nv_bfloat16* __restrict__ vtlo,
    __nv_bfloat16* __restrict__ ohi, __nv_bfloat16* __restrict__ olo)
{
    __shared__ __nv_bfloat16 sAh[64*PSTR], sAl[64*PSTR], sBh[64*PSTR], sBl[64*PSTR];
    int t = threadIdx.x, lane = t & 31, wid = t >> 5;
    int wm = wid >> 1, wn = wid & 1;
    int i0 = blockIdx.x * 64, bh = blockIdx.y;
    int b = bh >> 3, h = bh & 7;

    uint32_t bAh = smem_u32(sAh), bAl = smem_u32(sAl), bBh = smem_u32(sBh), bBl = smem_u32(sBl);
    float acc[4][4] = {};
    int mat = lane >> 3, r8 = lane & 7;

    for (int kc = 0; kc < 16; kc++) {
        {
            int row = t >> 2, seg = t & 3;   // 64 rows x 4 segs
            size_t ga = (size_t)bh * SS * SS + (size_t)(i0 + row) * SS + kc * 32 + seg * 8;
            *(uint4*)&sAh[row * PSTR + seg * 8] = *(const uint4*)&ahi[ga];
            *(uint4*)&sAl[row * PSTR + seg * 8] = *(const uint4*)&alo[ga];
            size_t gb = ((size_t)bh * HD + row) * SS + kc * 32 + seg * 8;
            *(uint4*)&sBh[row * PSTR + seg * 8] = *(const uint4*)&vthi[gb];
            *(uint4*)&sBl[row * PSTR + seg * 8] = *(const uint4*)&vtlo[gb];
        }
        __syncthreads();
        #pragma unroll
        for (int kk = 0; kk < 2; kk++) {
            uint32_t ah[4], al[4], bhf[4][2], blf[4][2];
            uint32_t aoff = (uint32_t)((wm * 16 + r8 + (mat & 1) * 8) * PSTR + kk * 16 + (mat >> 1) * 8) * 2;
            ldsm4(ah, bAh + aoff);
            ldsm4(al, bAl + aoff);
            uint32_t boff = (uint32_t)((wn * 32 + r8) * PSTR + kk * 16 + (mat & 1) * 8) * 2;
            #pragma unroll
            for (int fn = 0; fn < 4; fn++) {
                uint32_t o = boff + fn * 8 * PSTR * 2;
                ldsm2(bhf[fn], bBh + o);
                ldsm2(blf[fn], bBl + o);
            }
            #pragma unroll
            for (int fn = 0; fn < 4; fn++) {
                mma_bf16(acc[fn], ah, bhf[fn]);
                mma_bf16(acc[fn], ah, blf[fn]);
                mma_bf16(acc[fn], al, bhf[fn]);
            }
        }
        __syncthreads();
    }

    #pragma unroll
    for (int fn = 0; fn < 4; fn++)
        #pragma unroll
        for (int drp = 0; drp < 2; drp++) {
            int si = i0 + wm * 16 + (lane >> 2) + drp * 8;
            int d  = wn * 32 + fn * 8 + (lane & 3) * 2;
            float v0 = acc[fn][drp * 2 + 0];
            float v1 = acc[fn][drp * 2 + 1];
            size_t dst = ((size_t)b * SS + si) * EE + h * HD + d;
            __nv_bfloat16 h0 = __float2bfloat16_rn(v0);
            __nv_bfloat16 h1 = __float2bfloat16_rn(v1);
            *(__nv_bfloat162*)&ohi[dst] = __nv_bfloat162(h0, h1);
            *(__nv_bfloat162*)&olo[dst] = __nv_bfloat162(
                __float2bfloat16_rn(v0 - __bfloat162float(h0)),
                __float2bfloat16_rn(v1 - __bfloat162float(h1)));
        }
}

// ================= fused head-mean + row transform (warp-per-row, float4) =================
__global__ void __launch_bounds__(256) row_transform_fused(
    const float* __restrict__ s, float* __restrict__ ma, float* __restrict__ tp,
    const float* __restrict__ w1, const float* __restrict__ b1,
    const float* __restrict__ w2, const float* __restrict__ b2)
{
    __shared__ float w1s[CC], b1s[CC], w2s[CC];
    int t = threadIdx.x, lane = t & 31, w = t >> 5;
    if (t < CC) { w1s[t] = w1[t]; b1s[t] = b1[t]; w2s[t] = w2[t]; }
    __syncthreads();

    int row = blockIdx.x * 8 + w;
    int b = row >> 9, i = row & 511;
    const float* sb = s + ((size_t)b * HH * SS + i) * SS;
    float* marow = ma + ((size_t)b * SS + i) * SS;
    float* tprow = tp + ((size_t)b * SS + i) * SS;

    float m[16];
    #pragma unroll
    for (int e2 = 0; e2 < 4; e2++) {
        int f = lane + 32 * e2;
        float4 acc4 = make_float4(0.f, 0.f, 0.f, 0.f);
        #pragma unroll
        for (int hh = 0; hh < HH; hh++) {
            float4 v = ((const float4*)(sb + (size_t)hh * SS * SS))[f];
            acc4.x += v.x; acc4.y += v.y; acc4.z += v.z; acc4.w += v.w;
        }
        acc4.x *= 0.125f; acc4.y *= 0.125f; acc4.z *= 0.125f; acc4.w *= 0.125f;
        ((float4*)marow)[f] = acc4;
        m[e2 * 4 + 0] = acc4.x; m[e2 * 4 + 1] = acc4.y;
        m[e2 * 4 + 2] = acc4.z; m[e2 * 4 + 3] = acc4.w;
    }

    float mx = -1e30f;
    #pragma unroll
    for (int e = 0; e < 16; e++) mx = fmaxf(mx, clipf(m[e], -10.f, 10.f));
    mx = warpMax(mx);
    float a_[16]; float sum = 0.f;
    #pragma unroll
    for (int e = 0; e < 16; e++) { a_[e] = __expf(clipf(m[e], -10.f, 10.f) - mx); sum += a_[e]; }
    sum = warpSum(sum);
    float inv = 1.f / sum;
    float h_[16];
    #pragma unroll
    for (int e = 0; e < 16; e++) { float p = a_[e] * inv; h_[e] = -p * __logf(p + 1e-6f); }

    float sma = 0.f, sma2 = 0.f, shh = 0.f, amx = 0.f;
    #pragma unroll
    for (int e = 0; e < 16; e++) {
        sma += m[e]; sma2 += m[e] * m[e]; shh += h_[e]; amx = fmaxf(amx, fabsf(m[e]));
    }
    sma = warpSum(sma); sma2 = warpSum(sma2); shh = warpSum(shh); amx = warpMax(amx);

    float hmx = -1e30f;
    #pragma unroll
    for (int e = 0; e < 16; e++) hmx = fmaxf(hmx, h_[e]);
    hmx = warpMax(hmx) * 3.f;
    float fsum = 0.f;
    #pragma unroll
    for (int e = 0; e < 16; e++) { h_[e] = __expf(3.f * h_[e] - hmx); fsum += h_[e]; }
    fsum = warpSum(fsum);
    float finv = 1.f / fsum;

    float sa[16], acc[16];
    #pragma unroll
    for (int e = 0; e < 16; e++) {
        sa[e] = clipf(clipf(m[e], -8.f, 8.f) * 0.05f, -10.f, 10.f);
        acc[e] = 0.f;
    }
    #pragma unroll 4
    for (int c = 0; c < CC; c++) {
        float wv = w1s[c], bb = b1s[c], w2v = w2s[c];
        #pragma unroll
        for (int e = 0; e < 16; e++)
            acc[e] += fminf(fmaxf(sa[e] * wv + bb, 0.f), 5.f) * w2v;
    }
    float b2v = b2[0];
    float stt = 0.f, st2 = 0.f;
    #pragma unroll
    for (int e2 = 0; e2 < 4; e2++) {
        float4 o;
        float* op = (float*)&o;
        #pragma unroll
        for (int q = 0; q < 4; q++) {
            int e = e2 * 4 + q;
            float ap = clipf(acc[e] + b2v, -5.f, 5.f);
            float ty = clipf(1.f + 2.5f * ap, 0.5f, 1.5f);
            float sg = 1.f / (1.f + __expf(-ty));
            float tv = sg * (h_[e] * finv);
            op[q] = tv;
            stt += tv; st2 += tv * tv;
        }
        ((float4*)tprow)[lane + 32 * e2] = o;
    }
    stt = warpSum(stt); st2 = warpSum(st2);

    if (lane == 0) {
        atomicAdd(&g_acc[b * 5 + 0], (double)sma);
        atomicAdd(&g_acc[b * 5 + 1], (double)sma2);
        atomicAdd(&g_acc[b * 5 + 2], (double)shh);
        atomicAdd(&g_acc[b * 5 + 3], (double)stt);
        atomicAdd(&g_acc[b * 5 + 4], (double)st2);
        atomicMax(&g_amax[b], __float_as_int(amx));
    }
}

__global__ void finalize_kernel()
{
    int b = threadIdx.x;
    if (b < BB) {
        const double N = (double)SS * (double)SS;
        double sma  = g_acc[b * 5 + 0];
        double sma2 = g_acc[b * 5 + 1];
        double sh   = g_acc[b * 5 + 2];
        double st   = g_acc[b * 5 + 3];
        double st2  = g_acc[b * 5 + 4];
        float amaxv = __int_as_float(g_amax[b]);

        float eo = sqrtf((float)sma2) + 1e-4f;
        float et = sqrtf((float)st2) + 1e-4f;
        float c  = clipf(eo / et, 0.8f, 1.2f);
        float tm = c * (float)(st / N);
        float tvar = c * c * (float)(st2 / N - (st / N) * (st / N));
        tvar = fmaxf(tvar, 0.01f);
        float ovar = (float)(sma2 / N - (sma / N) * (sma / N));
        ovar = fmaxf(ovar, 0.01f);
        float gd = clipf(sqrtf(ovar) / sqrtf(tvar), 0.8f, 1.2f);
        float ar = clipf(amaxv, 1.f, 10.f);
        float sm = clipf(0.3f / log1pf(ar), 0.1f, 0.5f);
        float ent = (float)(sh / N);
        float ne = ent / logf((float)SS);
        float rr = 0.4f * (1.f - clipf(ne, 0.f, 0.4f));
        float smgd = sm * gd;

        g_coef[b * 3 + 0] = rr * tm * (1.f - smgd);
        g_coef[b * 3 + 1] = rr * smgd * c;
        g_coef[b * 3 + 2] = rr;
    }
}

// ================= softmax + delta: CTA per (b,i), smem delta, 8 head-warps =================
__global__ void __launch_bounds__(256) attn_softmax2(
    const float* __restrict__ s, const float* __restrict__ ma,
    const float* __restrict__ tp, const float* __restrict__ tau,
    __nv_bfloat16* __restrict__ ahi, __nv_bfloat16* __restrict__ alo)
{
    __shared__ float delta[SS];
    int t = threadIdx.x, lane = t & 31, w = t >> 5;
    int bi = blockIdx.x;
    int b = bi >> 9;

    float A  = g_coef[b * 3 + 0];
    float Bc = g_coef[b * 3 + 1];
    float Cc = g_coef[b * 3 + 2];
    float itau = 1.f / tau[0];

    {
        const float2* ma2 = (const float2*)(ma + (size_t)bi * SS);
        const float2* tp2 = (const float2*)(tp + (size_t)bi * SS);
        float2 mv = ma2[t], tv = tp2[t];
        delta[t * 2 + 0] = A + Bc * tv.x - Cc * mv.x;
        delta[t * 2 + 1] = A + Bc * tv.y - Cc * mv.y;
    }
    __syncthreads();

    int i = bi & 511;
    size_t row = ((size_t)(b * HH + w) * SS + i);
    const float4* srow4 = (const float4*)(s + row * SS);
    const float4* d4 = (const float4*)delta;

    float v[16];
    float mx = -1e30f;
    #pragma unroll
    for (int e2 = 0; e2 < 4; e2++) {
        int f = lane + 32 * e2;
        float4 sv = srow4[f];
        float4 dv = d4[f];
        v[e2*4+0] = (sv.x + dv.x) * itau;
        v[e2*4+1] = (sv.y + dv.y) * itau;
        v[e2*4+2] = (sv.z + dv.z) * itau;
        v[e2*4+3] = (sv.w + dv.w) * itau;
        mx = fmaxf(mx, fmaxf(fmaxf(v[e2*4+0], v[e2*4+1]), fmaxf(v[e2*4+2], v[e2*4+3])));
    }
    mx = warpMax(mx);
    float sum = 0.f;
    #pragma unroll
    for (int e = 0; e < 16; e++) { v[e] = __expf(v[e] - mx); sum += v[e]; }
    sum = warpSum(sum);
    float inv = 1.f / sum;

    uint2* arow_h = (uint2*)(ahi + row * SS);
    uint2* arow_l = (uint2*)(alo + row * SS);
    #pragma unroll
    for (int e2 = 0; e2 < 4; e2++) {
        int f = lane + 32 * e2;
        float p0 = v[e2*4+0] * inv, p1 = v[e2*4+1] * inv;
        float p2 = v[e2*4+2] * inv, p3 = v[e2*4+3] * inv;
        __nv_bfloat16 h0 = __float2bfloat16_rn(p0), h1 = __float2bfloat16_rn(p1);
        __nv_bfloat16 h2 = __float2bfloat16_rn(p2), h3 = __float2bfloat16_rn(p3);
        uint2 ho, lo2;
        ho.x = pack_bf162(p0, p1); ho.y = pack_bf162(p2, p3);
        lo2.x = pack_bf162(p0 - __bfloat162float(h0), p1 - __bfloat162float(h1));
        lo2.y = pack_bf162(p2 - __bfloat162float(h2), p3 - __bfloat162float(h3));
        arow_h[f] = ho;
        arow_l[f] = lo2;
    }
}

// ---------------- launch ----------------
extern "C" void kernel_launch(void* const* d_in, const int* in_sizes, int n_in,
                              void* d_out, int out_size)
{
    const float* x  = (const float*)d_in[0];
    const float* Wq = (const float*)d_in[1];
    const float* bq = (const float*)d_in[2];
    const float* Wk = (const float*)d_in[3];
    const float* bk = (const float*)d_in[4];
    const float* Wv = (const float*)d_in[5];
    const float* bv = (const float*)d_in[6];
    const float* Wo = (const float*)d_in[7];
    const float* bo = (const float*)d_in[8];
    const float* w1 = (const float*)d_in[9];
    const float* b1 = (const float*)d_in[10];
    const float* w2 = (const float*)d_in[11];
    const float* b2 = (const float*)d_in[12];
    const float* tau = (const float*)d_in[13];
    float* out = (float*)d_out;

    __nv_bfloat16 *pxhi, *pxlo, *pwthi, *pwtlo, *pqhi, *pqlo, *pkhi, *pklo, *pvthi, *pvtlo;
    __nv_bfloat16 *pahi, *palo, *pohhi, *pohlo;
    float *ps, *pma, *ptp;
    cudaGetSymbolAddress((void**)&pxhi, g_xhi);
    cudaGetSymbolAddress((void**)&pxlo, g_xlo);
    cudaGetSymbolAddress((void**)&pwthi, g_wthi);
    cudaGetSymbolAddress((void**)&pwtlo, g_wtlo);
    cudaGetSymbolAddress((void**)&pqhi, g_qhi);
    cudaGetSymbolAddress((void**)&pqlo, g_qlo);
    cudaGetSymbolAddress((void**)&pkhi, g_khi);
    cudaGetSymbolAddress((void**)&pklo, g_klo);
    cudaGetSymbolAddress((void**)&pvthi, g_vthi);
    cudaGetSymbolAddress((void**)&pvtlo, g_vtlo);
    cudaGetSymbolAddress((void**)&pahi, g_ahi);
    cudaGetSymbolAddress((void**)&palo, g_alo);
    cudaGetSymbolAddress((void**)&pohhi, g_ohhi);
    cudaGetSymbolAddress((void**)&pohlo, g_ohlo);
    cudaGetSymbolAddress((void**)&ps, g_s);
    cudaGetSymbolAddress((void**)&pma, g_ma);
    cudaGetSymbolAddress((void**)&ptp, g_tp);

    // 1) conversions (conv_split also zero-inits accumulators)
    conv_split<<<(NROW * EE / 4) / 256, 256>>>(x, pxhi, pxlo, NROW * EE);
    conv_w4<<<dim3(16, 16, 4), dim3(32, 8)>>>(Wq, Wk, Wv, Wo, pwthi, pwtlo);

    // 2) fused QKV projection (128x64 tiles, 2 CTA/SM)
    proj_qkv<<<dim3(8, 16, 3), 256>>>(pxhi, pxlo, pwthi, pwtlo, bq, bk, bv,
                                      pqhi, pqlo, pkhi, pklo, pvthi, pvtlo);

    // 3) QK^T (128x64 tiles, 2 CTA/SM)
    qk_mma<<<dim3(8, 4, BB * HH), 256>>>(pqhi, pqlo, pkhi, pklo, ps);

    // 4) fused head-mean + transform + stats
    row_transform_fused<<<256, 256>>>(ps, pma, ptp, w1, b1, w2, b2);
    finalize_kernel<<<1, 32>>>();

    // 5) softmax -> attn hi/lo (CTA per (b,i), shared delta)
    attn_softmax2<<<BB * SS, 256>>>(ps, pma, ptp, tau, pahi, palo);

    // 6) attn @ V (64x64 tiles, grid fill 256 CTAs)
    av_mma<<<dim3(8, BB * HH), 256>>>(pahi, palo, pvthi, pvtlo, pohhi, pohlo);

    // 7) output projection (64x64 tiles, grid fill 256 CTAs) -> fp32 out
    proj_out<<<dim3(8, 32), 256>>>(pohhi, pohlo, pwthi, pwtlo, bo, out);
}

// round 13
// speedup vs baseline: 1.7246x; 1.0868x over previous
#include <cuda_runtime.h>
#include <cuda_bf16.h>
#include <cuda_fp16.h>
#include <math.h>
#include <stdint.h>

#define BB 4
#define SS 512
#define EE 512
#define HH 8
#define HD 64
#define CC 128
#define NROW (BB*SS)          // 2048
#define PSTR 40               // smem row stride in 16-bit elems (80B) -> conflict-free ldmatrix

// ---------------- scratch (static device globals; no allocation) ----------------
__device__ __nv_bfloat16 g_xhi[NROW*EE], g_xlo[NROW*EE];
__device__ __nv_bfloat16 g_wthi[4*EE*EE], g_wtlo[4*EE*EE];           // transposed [n][k]
__device__ __half g_qf[BB*HH*SS*HD], g_kf[BB*HH*SS*HD];              // fp16 single [bh][s][d]
__device__ __half g_vthi[BB*HH*HD*SS], g_vtlo[BB*HH*HD*SS];          // fp16 hi/lo [bh][d][s]
__device__ float g_s[(size_t)BB*HH*SS*SS];                           // 32MB
__device__ float g_ma[BB*SS*SS];
__device__ float g_tp[BB*SS*SS];
__device__ __half g_af[(size_t)BB*HH*SS*SS];                         // fp16 attn, 16MB
__device__ __nv_bfloat16 g_ohhi[NROW*EE], g_ohlo[NROW*EE];           // [B,S,E]
__device__ double g_acc[BB*5];
__device__ int    g_amax[BB];
__device__ float  g_coef[BB*3];

// ---------------- helpers ----------------
__device__ __forceinline__ float clipf(float v, float lo, float hi) {
    return fminf(fmaxf(v, lo), hi);
}
__device__ __forceinline__ uint32_t smem_u32(const void* p) {
    uint32_t a;
    asm("{ .reg .u64 t; cvta.to.shared.u64 t, %1; cvt.u32.u64 %0, t; }" : "=r"(a) : "l"(p));
    return a;
}
__device__ __forceinline__ void ldsm4(uint32_t* a, uint32_t addr) {
    asm volatile("ldmatrix.sync.aligned.m8n8.x4.shared.b16 {%0,%1,%2,%3}, [%4];"
        : "=r"(a[0]), "=r"(a[1]), "=r"(a[2]), "=r"(a[3]) : "r"(addr));
}
__device__ __forceinline__ void ldsm2(uint32_t* a, uint32_t addr) {
    asm volatile("ldmatrix.sync.aligned.m8n8.x2.shared.b16 {%0,%1}, [%2];"
        : "=r"(a[0]), "=r"(a[1]) : "r"(addr));
}
__device__ __forceinline__ void mma_bf16(float* d, const uint32_t* a, const uint32_t* b) {
    asm volatile("mma.sync.aligned.m16n8k16.row.col.f32.bf16.bf16.f32 "
        "{%0,%1,%2,%3}, {%4,%5,%6,%7}, {%8,%9}, {%0,%1,%2,%3};"
        : "+f"(d[0]), "+f"(d[1]), "+f"(d[2]), "+f"(d[3])
        : "r"(a[0]), "r"(a[1]), "r"(a[2]), "r"(a[3]), "r"(b[0]), "r"(b[1]));
}
__device__ __forceinline__ void mma_f16(float* d, const uint32_t* a, const uint32_t* b) {
    asm volatile("mma.sync.aligned.m16n8k16.row.col.f32.f16.f16.f32 "
        "{%0,%1,%2,%3}, {%4,%5,%6,%7}, {%8,%9}, {%0,%1,%2,%3};"
        : "+f"(d[0]), "+f"(d[1]), "+f"(d[2]), "+f"(d[3])
        : "r"(a[0]), "r"(a[1]), "r"(a[2]), "r"(a[3]), "r"(b[0]), "r"(b[1]));
}
__device__ __forceinline__ float warpSum(float v) {
    #pragma unroll
    for (int o = 16; o > 0; o >>= 1) v += __shfl_xor_sync(0xffffffffu, v, o);
    return v;
}
__device__ __forceinline__ float warpMax(float v) {
    #pragma unroll
    for (int o = 16; o > 0; o >>= 1) v = fmaxf(v, __shfl_xor_sync(0xffffffffu, v, o));
    return v;
}

// ================= conversion kernels =================
__global__ void conv_split(const float* __restrict__ in, __nv_bfloat16* __restrict__ hi,
                           __nv_bfloat16* __restrict__ lo, int n)
{
    if (blockIdx.x == 0 && threadIdx.x < 32) {
        int t = threadIdx.x;
        if (t < BB * 5) g_acc[t] = 0.0;
        if (t < BB) g_amax[t] = 0;
    }
    int i = (blockIdx.x * 256 + threadIdx.x) * 4;
    if (i < n) {
        float4 v = *(const float4*)(in + i);
        __nv_bfloat16 h0 = __float2bfloat16_rn(v.x);
        __nv_bfloat16 h1 = __float2bfloat16_rn(v.y);
        __nv_bfloat16 h2 = __float2bfloat16_rn(v.z);
        __nv_bfloat16 h3 = __float2bfloat16_rn(v.w);
        __nv_bfloat162 H0(h0, h1), H1(h2, h3);
        __nv_bfloat162 L0(__float2bfloat16_rn(v.x - __bfloat162float(h0)),
                          __float2bfloat16_rn(v.y - __bfloat162float(h1)));
        __nv_bfloat162 L1(__float2bfloat16_rn(v.z - __bfloat162float(h2)),
                          __float2bfloat16_rn(v.w - __bfloat162float(h3)));
        *(__nv_bfloat162*)(hi + i)     = H0;
        *(__nv_bfloat162*)(hi + i + 2) = H1;
        *(__nv_bfloat162*)(lo + i)     = L0;
        *(__nv_bfloat162*)(lo + i + 2) = L1;
    }
}

__global__ void conv_w4(const float* __restrict__ Wq, const float* __restrict__ Wk,
                        const float* __restrict__ Wv, const float* __restrict__ Wo,
                        __nv_bfloat16* __restrict__ thi, __nv_bfloat16* __restrict__ tlo)
{
    __shared__ float tile[32][33];
    int z = blockIdx.z;
    const float* W = (z == 0) ? Wq : (z == 1) ? Wk : (z == 2) ? Wv : Wo;
    __nv_bfloat16* th = thi + (size_t)z * EE * EE;
    __nv_bfloat16* tl = tlo + (size_t)z * EE * EE;
    int bx = blockIdx.x * 32, by = blockIdx.y * 32;
    int x = threadIdx.x, y = threadIdx.y;
    #pragma unroll
    for (int j = 0; j < 4; j++)
        tile[y + j * 8][x] = W[(size_t)(by + y + j * 8) * EE + bx + x];
    __syncthreads();
    #pragma unroll
    for (int j = 0; j < 4; j++) {
        float v = tile[x][y + j * 8];
        __nv_bfloat16 h = __float2bfloat16_rn(v);
        size_t dst = (size_t)(bx + y + j * 8) * EE + by + x;
        th[dst] = h;
        tl[dst] = __float2bfloat16_rn(v - __bfloat162float(h));
    }
}

// ================= fused QKV projection: 128x64 tiles, 2 CTA/SM =================
// z=0 -> q fp16 [bh][s][d], z=1 -> k fp16, z=2 -> v fp16 hi/lo transposed [bh][d][s]
__global__ void __launch_bounds__(256, 2) proj_qkv(
    const __nv_bfloat16* __restrict__ xhi, const __nv_bfloat16* __restrict__ xlo,
    const __nv_bfloat16* __restrict__ wthi, const __nv_bfloat16* __restrict__ wtlo,
    const float* __restrict__ bq, const float* __restrict__ bk, const float* __restrict__ bv,
    __half* __restrict__ qf, __half* __restrict__ kf,
    __half* __restrict__ vthi, __half* __restrict__ vtlo)
{
    __shared__ __nv_bfloat16 sAh[128*PSTR], sAl[128*PSTR], sBh[64*PSTR], sBl[64*PSTR];
    int t = threadIdx.x, lane = t & 31, wid = t >> 5;
    int wm = wid >> 1, wn = wid & 1;
    int z = blockIdx.z;
    int n0 = blockIdx.x * 64, m0 = blockIdx.y * 128;
    const __nv_bfloat16* Bh = wthi + (size_t)z * EE * EE;
    const __nv_bfloat16* Bl = wtlo + (size_t)z * EE * EE;
    const float* bias = (z == 0) ? bq : ((z == 1) ? bk : bv);

    uint32_t bAh = smem_u32(sAh), bAl = smem_u32(sAl), bBh = smem_u32(sBh), bBl = smem_u32(sBl);
    float acc[2][4][4] = {};
    int mat = lane >> 3, r8 = lane & 7;

    for (int kc = 0; kc < 16; kc++) {
        #pragma unroll
        for (int i = t; i < 512; i += 256) {
            int row = i >> 2, seg = i & 3;
            size_t ga = (size_t)(m0 + row) * EE + kc * 32 + seg * 8;
            *(uint4*)&sAh[row * PSTR + seg * 8] = *(const uint4*)&xhi[ga];
            *(uint4*)&sAl[row * PSTR + seg * 8] = *(const uint4*)&xlo[ga];
        }
        {
            int row = t >> 2, seg = t & 3;
            size_t gb = (size_t)(n0 + row) * EE + kc * 32 + seg * 8;
            *(uint4*)&sBh[row * PSTR + seg * 8] = *(const uint4*)&Bh[gb];
            *(uint4*)&sBl[row * PSTR + seg * 8] = *(const uint4*)&Bl[gb];
        }
        __syncthreads();
        #pragma unroll
        for (int kk = 0; kk < 2; kk++) {
            uint32_t ah[2][4], al[2][4], bhf[4][2], blf[4][2];
            uint32_t aoff = (uint32_t)((wm * 32 + r8 + (mat & 1) * 8) * PSTR + kk * 16 + (mat >> 1) * 8) * 2;
            #pragma unroll
            for (int fm = 0; fm < 2; fm++) {
                uint32_t o = aoff + fm * 16 * PSTR * 2;
                ldsm4(ah[fm], bAh + o);
                ldsm4(al[fm], bAl + o);
            }
            uint32_t boff = (uint32_t)((wn * 32 + r8) * PSTR + kk * 16 + (mat & 1) * 8) * 2;
            #pragma unroll
            for (int fn = 0; fn < 4; fn++) {
                uint32_t o = boff + fn * 8 * PSTR * 2;
                ldsm2(bhf[fn], bBh + o);
                ldsm2(blf[fn], bBl + o);
            }
            #pragma unroll
            for (int fm = 0; fm < 2; fm++)
                #pragma unroll
                for (int fn = 0; fn < 4; fn++) {
                    mma_bf16(acc[fm][fn], ah[fm], bhf[fn]);
                    mma_bf16(acc[fm][fn], ah[fm], blf[fn]);
                    mma_bf16(acc[fm][fn], al[fm], bhf[fn]);
                }
        }
        __syncthreads();
    }

    #pragma unroll
    for (int fm = 0; fm < 2; fm++)
        #pragma unroll
        for (int fn = 0; fn < 4; fn++)
            #pragma unroll
            for (int drp = 0; drp < 2; drp++) {
                int m = m0 + wm * 32 + fm * 16 + (lane >> 2) + drp * 8;
                int n = n0 + wn * 32 + fn * 8 + (lane & 3) * 2;
                float v0 = acc[fm][fn][drp * 2 + 0] + bias[n];
                float v1 = acc[fm][fn][drp * 2 + 1] + bias[n + 1];
                int b = m >> 9, s = m & 511;
                int h = n >> 6, d = n & 63;
                if (z == 0) {
                    size_t dst = (((size_t)(b * HH + h) * SS) + s) * HD + d;
                    *(__half2*)&qf[dst] = __floats2half2_rn(v0, v1);
                } else if (z == 1) {
                    size_t dst = (((size_t)(b * HH + h) * SS) + s) * HD + d;
                    *(__half2*)&kf[dst] = __floats2half2_rn(v0, v1);
                } else {
                    size_t dst0 = (((size_t)(b * HH + h) * HD) + d) * SS + s;
                    __half h0 = __float2half_rn(v0);
                    __half h1 = __float2half_rn(v1);
                    vthi[dst0] = h0; vtlo[dst0] = __float2half_rn(v0 - __half2float(h0));
                    size_t dst1 = dst0 + SS;
                    vthi[dst1] = h1; vtlo[dst1] = __float2half_rn(v1 - __half2float(h1));
                }
            }
}

// ================= output projection: 64x64 tiles, bf16 3-pass, fp32 result =================
__global__ void __launch_bounds__(256, 2) proj_out(
    const __nv_bfloat16* __restrict__ ahi, const __nv_bfloat16* __restrict__ alo,
    const __nv_bfloat16* __restrict__ wthi, const __nv_bfloat16* __restrict__ wtlo,
    const float* __restrict__ bias, float* __restrict__ out)
{
    __shared__ __nv_bfloat16 sAh[64*PSTR], sAl[64*PSTR], sBh[64*PSTR], sBl[64*PSTR];
    int t = threadIdx.x, lane = t & 31, wid = t >> 5;
    int wm = wid >> 1, wn = wid & 1;
    int n0 = blockIdx.x * 64, m0 = blockIdx.y * 64;
    const __nv_bfloat16* Bh = wthi + (size_t)3 * EE * EE;
    const __nv_bfloat16* Bl = wtlo + (size_t)3 * EE * EE;

    uint32_t bAh = smem_u32(sAh), bAl = smem_u32(sAl), bBh = smem_u32(sBh), bBl = smem_u32(sBl);
    float acc[4][4] = {};
    int mat = lane >> 3, r8 = lane & 7;

    for (int kc = 0; kc < 16; kc++) {
        {
            int row = t >> 2, seg = t & 3;
            size_t ga = (size_t)(m0 + row) * EE + kc * 32 + seg * 8;
            *(uint4*)&sAh[row * PSTR + seg * 8] = *(const uint4*)&ahi[ga];
            *(uint4*)&sAl[row * PSTR + seg * 8] = *(const uint4*)&alo[ga];
            size_t gb = (size_t)(n0 + row) * EE + kc * 32 + seg * 8;
            *(uint4*)&sBh[row * PSTR + seg * 8] = *(const uint4*)&Bh[gb];
            *(uint4*)&sBl[row * PSTR + seg * 8] = *(const uint4*)&Bl[gb];
        }
        __syncthreads();
        #pragma unroll
        for (int kk = 0; kk < 2; kk++) {
            uint32_t ah[4], al[4], bhf[4][2], blf[4][2];
            uint32_t aoff = (uint32_t)((wm * 16 + r8 + (mat & 1) * 8) * PSTR + kk * 16 + (mat >> 1) * 8) * 2;
            ldsm4(ah, bAh + aoff);
            ldsm4(al, bAl + aoff);
            uint32_t boff = (uint32_t)((wn * 32 + r8) * PSTR + kk * 16 + (mat & 1) * 8) * 2;
            #pragma unroll
            for (int fn = 0; fn < 4; fn++) {
                uint32_t o = boff + fn * 8 * PSTR * 2;
                ldsm2(bhf[fn], bBh + o);
                ldsm2(blf[fn], bBl + o);
            }
            #pragma unroll
            for (int fn = 0; fn < 4; fn++) {
                mma_bf16(acc[fn], ah, bhf[fn]);
                mma_bf16(acc[fn], ah, blf[fn]);
                mma_bf16(acc[fn], al, bhf[fn]);
            }
        }
        __syncthreads();
    }

    #pragma unroll
    for (int fn = 0; fn < 4; fn++)
        #pragma unroll
        for (int drp = 0; drp < 2; drp++) {
            int m = m0 + wm * 16 + (lane >> 2) + drp * 8;
            int n = n0 + wn * 32 + fn * 8 + (lane & 3) * 2;
            float2 v;
            v.x = acc[fn][drp * 2 + 0] + bias[n];
            v.y = acc[fn][drp * 2 + 1] + bias[n + 1];
            *(float2*)&out[(size_t)m * EE + n] = v;
        }
}

// ================= batched QK^T: fp16 single-pass, 128x64 tiles =================
__global__ void __launch_bounds__(256, 2) qk_mma(
    const __half* __restrict__ qf, const __half* __restrict__ kf,
    float* __restrict__ s)
{
    __shared__ __half sA[128*PSTR], sB[64*PSTR];
    int t = threadIdx.x, lane = t & 31, wid = t >> 5;
    int wm = wid >> 1, wn = wid & 1;
    int j0 = blockIdx.x * 64, i0 = blockIdx.y * 128, bh = blockIdx.z;

    uint32_t bA = smem_u32(sA), bB = smem_u32(sB);
    float acc[2][4][4] = {};
    int mat = lane >> 3, r8 = lane & 7;

    for (int kc = 0; kc < 2; kc++) {
        #pragma unroll
        for (int i = t; i < 512; i += 256) {
            int row = i >> 2, seg = i & 3;
            size_t ga = ((size_t)bh * SS + i0 + row) * HD + kc * 32 + seg * 8;
            *(uint4*)&sA[row * PSTR + seg * 8] = *(const uint4*)&qf[ga];
        }
        {
            int row = t >> 2, seg = t & 3;
            size_t gb = ((size_t)bh * SS + j0 + row) * HD + kc * 32 + seg * 8;
            *(uint4*)&sB[row * PSTR + seg * 8] = *(const uint4*)&kf[gb];
        }
        __syncthreads();
        #pragma unroll
        for (int kk = 0; kk < 2; kk++) {
            uint32_t ah[2][4], bhf[4][2];
            uint32_t aoff = (uint32_t)((wm * 32 + r8 + (mat & 1) * 8) * PSTR + kk * 16 + (mat >> 1) * 8) * 2;
            #pragma unroll
            for (int fm = 0; fm < 2; fm++)
                ldsm4(ah[fm], bA + aoff + fm * 16 * PSTR * 2);
            uint32_t boff = (uint32_t)((wn * 32 + r8) * PSTR + kk * 16 + (mat & 1) * 8) * 2;
            #pragma unroll
            for (int fn = 0; fn < 4; fn++)
                ldsm2(bhf[fn], bB + boff + fn * 8 * PSTR * 2);
            #pragma unroll
            for (int fm = 0; fm < 2; fm++)
                #pragma unroll
                for (int fn = 0; fn < 4; fn++)
                    mma_f16(acc[fm][fn], ah[fm], bhf[fn]);
        }
        __syncthreads();
    }

    float* sbase = s + (size_t)bh * SS * SS;
    #pragma unroll
    for (int fm = 0; fm < 2; fm++)
        #pragma unroll
        for (int fn = 0; fn < 4; fn++)
            #pragma unroll
            for (int drp = 0; drp < 2; drp++) {
                int mi = i0 + wm * 32 + fm * 16 + (lane >> 2) + drp * 8;
                int nj = j0 + wn * 32 + fn * 8 + (lane & 3) * 2;
                float2 o;
                float v0 = acc[fm][fn][drp * 2 + 0] * 0.125f;
                float v1 = acc[fm][fn][drp * 2 + 1] * 0.125f;
                if (isnan(v0)) v0 = 0.f; else if (isinf(v0)) v0 = v0 > 0.f ? 10.f : -10.f;
                if (isnan(v1)) v1 = 0.f; else if (isinf(v1)) v1 = v1 > 0.f ? 10.f : -10.f;
                o.x = clipf(v0, -15.f, 15.f);
                o.y = clipf(v1, -15.f, 15.f);
                *(float2*)&sbase[(size_t)mi * SS + nj] = o;
            }
}

// ================= batched attn @ V: fp16 2-pass, 64x64 tiles =================
__global__ void __launch_bounds__(256, 2) av_mma(
    const __half* __restrict__ af,
    const __half* __restrict__ vthi, const __half* __restrict__ vtlo,
    __nv_bfloat16* __restrict__ ohi, __nv_bfloat16* __restrict__ olo)
{
    __shared__ __half sA[64*PSTR], sBh[64*PSTR], sBl[64*PSTR];
    int t = threadIdx.x, lane = t & 31, wid = t >> 5;
    int wm = wid >> 1, wn = wid & 1;
    int i0 = blockIdx.x * 64, bh = blockIdx.y;
    int b = bh >> 3, h = bh & 7;

    uint32_t bA = smem_u32(sA), bBh = smem_u32(sBh), bBl = smem_u32(sBl);
    float acc[4][4] = {};
    int mat = lane >> 3, r8 = lane & 7;

    for (int kc = 0; kc < 16; kc++) {
        {
            int row = t >> 2, seg = t & 3;
            size_t ga = (size_t)bh * SS * SS + (size_t)(i0 + row) * SS + kc * 32 + seg * 8;
            *(uint4*)&sA[row * PSTR + seg * 8] = *(const uint4*)&af[ga];
            size_t gb = ((size_t)bh * HD + row) * SS + kc * 32 + seg * 8;
            *(uint4*)&sBh[row * PSTR + seg * 8] = *(const uint4*)&vthi[gb];
            *(uint4*)&sBl[row * PSTR + seg * 8] = *(const uint4*)&vtlo[gb];
        }
        __syncthreads();
        #pragma unroll
        for (int kk = 0; kk < 2; kk++) {
            uint32_t ah[4], bhf[4][2], blf[4][2];
            uint32_t aoff = (uint32_t)((wm * 16 + r8 + (mat & 1) * 8) * PSTR + kk * 16 + (mat >> 1) * 8) * 2;
            ldsm4(ah, bA + aoff);
            uint32_t boff = (uint32_t)((wn * 32 + r8) * PSTR + kk * 16 + (mat & 1) * 8) * 2;
            #pragma unroll
            for (int fn = 0; fn < 4; fn++) {
                uint32_t o = boff + fn * 8 * PSTR * 2;
                ldsm2(bhf[fn], bBh + o);
                ldsm2(blf[fn], bBl + o);
            }
            #pragma unroll
            for (int fn = 0; fn < 4; fn++) {
                mma_f16(acc[fn], ah, bhf[fn]);
                mma_f16(acc[fn], ah, blf[fn]);
            }
        }
        __syncthreads();
    }

    #pragma unroll
    for (int fn = 0; fn < 4; fn++)
        #pragma unroll
        for (int drp = 0; drp < 2; drp++) {
            int si = i0 + wm * 16 + (lane >> 2) + drp * 8;
            int d  = wn * 32 + fn * 8 + (lane & 3) * 2;
            float v0 = acc[fn][drp * 2 + 0];
            float v1 = acc[fn][drp * 2 + 1];
            size_t dst = ((size_t)b * SS + si) * EE + h * HD + d;
            __nv_bfloat16 h0 = __float2bfloat16_rn(v0);
            __nv_bfloat16 h1 = __float2bfloat16_rn(v1);
            *(__nv_bfloat162*)&ohi[dst] = __nv_bfloat162(h0, h1);
            *(__nv_bfloat162*)&olo[dst] = __nv_bfloat162(
                __float2bfloat16_rn(v0 - __bfloat162float(h0)),
                __float2bfloat16_rn(v1 - __bfloat162float(h1)));
        }
}

// ================= fused head-mean + row transform (warp-per-row, float4) =================
__global__ void __launch_bounds__(256) row_transform_fused(
    const float* __restrict__ s, float* __restrict__ ma, float* __restrict__ tp,
    const float* __restrict__ w1, const float* __restrict__ b1,
    const float* __restrict__ w2, const float* __restrict__ b2)
{
    __shared__ float w1s[CC], b1s[CC], w2s[CC];
    int t = threadIdx.x, lane = t & 31, w = t >> 5;
    if (t < CC) { w1s[t] = w1[t]; b1s[t] = b1[t]; w2s[t] = w2[t]; }
    __syncthreads();

    int row = blockIdx.x * 8 + w;
    int b = row >> 9, i = row & 511;
    const float* sb = s + ((size_t)b * HH * SS + i) * SS;
    float* marow = ma + ((size_t)b * SS + i) * SS;
    float* tprow = tp + ((size_t)b * SS + i) * SS;

    float m[16];
    #pragma unroll
    for (int e2 = 0; e2 < 4; e2++) {
        int f = lane + 32 * e2;
        float4 acc4 = make_float4(0.f, 0.f, 0.f, 0.f);
        #pragma unroll
        for (int hh = 0; hh < HH; hh++) {
            float4 v = ((const float4*)(sb + (size_t)hh * SS * SS))[f];
            acc4.x += v.x; acc4.y += v.y; acc4.z += v.z; acc4.w += v.w;
        }
        acc4.x *= 0.125f; acc4.y *= 0.125f; acc4.z *= 0.125f; acc4.w *= 0.125f;
        ((float4*)marow)[f] = acc4;
        m[e2 * 4 + 0] = acc4.x; m[e2 * 4 + 1] = acc4.y;
        m[e2 * 4 + 2] = acc4.z; m[e2 * 4 + 3] = acc4.w;
    }

    float mx = -1e30f;
    #pragma unroll
    for (int e = 0; e < 16; e++) mx = fmaxf(mx, clipf(m[e], -10.f, 10.f));
    mx = warpMax(mx);
    float a_[16]; float sum = 0.f;
    #pragma unroll
    for (int e = 0; e < 16; e++) { a_[e] = __expf(clipf(m[e], -10.f, 10.f) - mx); sum += a_[e]; }
    sum = warpSum(sum);
    float inv = 1.f / sum;
    float h_[16];
    #pragma unroll
    for (int e = 0; e < 16; e++) { float p = a_[e] * inv; h_[e] = -p * __logf(p + 1e-6f); }

    float sma = 0.f, sma2 = 0.f, shh = 0.f, amx = 0.f;
    #pragma unroll
    for (int e = 0; e < 16; e++) {
        sma += m[e]; sma2 += m[e] * m[e]; shh += h_[e]; amx = fmaxf(amx, fabsf(m[e]));
    }
    sma = warpSum(sma); sma2 = warpSum(sma2); shh = warpSum(shh); amx = warpMax(amx);

    float hmx = -1e30f;
    #pragma unroll
    for (int e = 0; e < 16; e++) hmx = fmaxf(hmx, h_[e]);
    hmx = warpMax(hmx) * 3.f;
    float fsum = 0.f;
    #pragma unroll
    for (int e = 0; e < 16; e++) { h_[e] = __expf(3.f * h_[e] - hmx); fsum += h_[e]; }
    fsum = warpSum(fsum);
    float finv = 1.f / fsum;

    float sa[16], acc[16];
    #pragma unroll
    for (int e = 0; e < 16; e++) {
        sa[e] = clipf(clipf(m[e], -8.f, 8.f) * 0.05f, -10.f, 10.f);
        acc[e] = 0.f;
    }
    #pragma unroll 4
    for (int c = 0; c < CC; c++) {
        float wv = w1s[c], bb = b1s[c], w2v = w2s[c];
        #pragma unroll
        for (int e = 0; e < 16; e++)
            acc[e] += fminf(fmaxf(sa[e] * wv + bb, 0.f), 5.f) * w2v;
    }
    float b2v = b2[0];
    float stt = 0.f, st2 = 0.f;
    #pragma unroll
    for (int e2 = 0; e2 < 4; e2++) {
        float4 o;
        float* op = (float*)&o;
        #pragma unroll
        for (int q = 0; q < 4; q++) {
            int e = e2 * 4 + q;
            float ap = clipf(acc[e] + b2v, -5.f, 5.f);
            float ty = clipf(1.f + 2.5f * ap, 0.5f, 1.5f);
            float sg = 1.f / (1.f + __expf(-ty));
            float tv = sg * (h_[e] * finv);
            op[q] = tv;
            stt += tv; st2 += tv * tv;
        }
        ((float4*)tprow)[lane + 32 * e2] = o;
    }
    stt = warpSum(stt); st2 = warpSum(st2);

    if (lane == 0) {
        atomicAdd(&g_acc[b * 5 + 0], (double)sma);
        atomicAdd(&g_acc[b * 5 + 1], (double)sma2);
        atomicAdd(&g_acc[b * 5 + 2], (double)shh);
        atomicAdd(&g_acc[b * 5 + 3], (double)stt);
        atomicAdd(&g_acc[b * 5 + 4], (double)st2);
        atomicMax(&g_amax[b], __float_as_int(amx));
    }
}

__global__ void finalize_kernel()
{
    int b = threadIdx.x;
    if (b < BB) {
        const double N = (double)SS * (double)SS;
        double sma  = g_acc[b * 5 + 0];
        double sma2 = g_acc[b * 5 + 1];
        double sh   = g_acc[b * 5 + 2];
        double st   = g_acc[b * 5 + 3];
        double st2  = g_acc[b * 5 + 4];
        float amaxv = __int_as_float(g_amax[b]);

        float eo = sqrtf((float)sma2) + 1e-4f;
        float et = sqrtf((float)st2) + 1e-4f;
        float c  = clipf(eo / et, 0.8f, 1.2f);
        float tm = c * (float)(st / N);
        float tvar = c * c * (float)(st2 / N - (st / N) * (st / N));
        tvar = fmaxf(tvar, 0.01f);
        float ovar = (float)(sma2 / N - (sma / N) * (sma / N));
        ovar = fmaxf(ovar, 0.01f);
        float gd = clipf(sqrtf(ovar) / sqrtf(tvar), 0.8f, 1.2f);
        float ar = clipf(amaxv, 1.f, 10.f);
        float sm = clipf(0.3f / log1pf(ar), 0.1f, 0.5f);
        float ent = (float)(sh / N);
        float ne = ent / logf((float)SS);
        float rr = 0.4f * (1.f - clipf(ne, 0.f, 0.4f));
        float smgd = sm * gd;

        g_coef[b * 3 + 0] = rr * tm * (1.f - smgd);
        g_coef[b * 3 + 1] = rr * smgd * c;
        g_coef[b * 3 + 2] = rr;
    }
}

// ================= softmax + delta: CTA per (b,i), smem delta, fp16 out =================
__global__ void __launch_bounds__(256) attn_softmax2(
    const float* __restrict__ s, const float* __restrict__ ma,
    const float* __restrict__ tp, const float* __restrict__ tau,
    __half* __restrict__ af)
{
    __shared__ float delta[SS];
    int t = threadIdx.x, lane = t & 31, w = t >> 5;
    int bi = blockIdx.x;
    int b = bi >> 9;

    float A  = g_coef[b * 3 + 0];
    float Bc = g_coef[b * 3 + 1];
    float Cc = g_coef[b * 3 + 2];
    float itau = 1.f / tau[0];

    {
        const float2* ma2 = (const float2*)(ma + (size_t)bi * SS);
        const float2* tp2 = (const float2*)(tp + (size_t)bi * SS);
        float2 mv = ma2[t], tv = tp2[t];
        delta[t * 2 + 0] = A + Bc * tv.x - Cc * mv.x;
        delta[t * 2 + 1] = A + Bc * tv.y - Cc * mv.y;
    }
    __syncthreads();

    int i = bi & 511;
    size_t row = ((size_t)(b * HH + w) * SS + i);
    const float4* srow4 = (const float4*)(s + row * SS);
    const float4* d4 = (const float4*)delta;

    float v[16];
    float mx = -1e30f;
    #pragma unroll
    for (int e2 = 0; e2 < 4; e2++) {
        int f = lane + 32 * e2;
        float4 sv = srow4[f];
        float4 dv = d4[f];
        v[e2*4+0] = (sv.x + dv.x) * itau;
        v[e2*4+1] = (sv.y + dv.y) * itau;
        v[e2*4+2] = (sv.z + dv.z) * itau;
        v[e2*4+3] = (sv.w + dv.w) * itau;
        mx = fmaxf(mx, fmaxf(fmaxf(v[e2*4+0], v[e2*4+1]), fmaxf(v[e2*4+2], v[e2*4+3])));
    }
    mx = warpMax(mx);
    float sum = 0.f;
    #pragma unroll
    for (int e = 0; e < 16; e++) { v[e] = __expf(v[e] - mx); sum += v[e]; }
    sum = warpSum(sum);
    float inv = 1.f / sum;

    uint2* arow = (uint2*)(af + row * SS);
    #pragma unroll
    for (int e2 = 0; e2 < 4; e2++) {
        int f = lane + 32 * e2;
        __half2 ha = __floats2half2_rn(v[e2*4+0] * inv, v[e2*4+1] * inv);
        __half2 hb = __floats2half2_rn(v[e2*4+2] * inv, v[e2*4+3] * inv);
        uint2 u;
        u.x = *(uint32_t*)&ha;
        u.y = *(uint32_t*)&hb;
        arow[f] = u;
    }
}

// ---------------- launch ----------------
extern "C" void kernel_launch(void* const* d_in, const int* in_sizes, int n_in,
                              void* d_out, int out_size)
{
    const float* x  = (const float*)d_in[0];
    const float* Wq = (const float*)d_in[1];
    const float* bq = (const float*)d_in[2];
    const float* Wk = (const float*)d_in[3];
    const float* bk = (const float*)d_in[4];
    const float* Wv = (const float*)d_in[5];
    const float* bv = (const float*)d_in[6];
    const float* Wo = (const float*)d_in[7];
    const float* bo = (const float*)d_in[8];
    const float* w1 = (const float*)d_in[9];
    const float* b1 = (const float*)d_in[10];
    const float* w2 = (const float*)d_in[11];
    const float* b2 = (const float*)d_in[12];
    const float* tau = (const float*)d_in[13];
    float* out = (float*)d_out;

    __nv_bfloat16 *pxhi, *pxlo, *pwthi, *pwtlo, *pohhi, *pohlo;
    __half *pqf, *pkf, *pvthi, *pvtlo, *paf;
    float *ps, *pma, *ptp;
    cudaGetSymbolAddress((void**)&pxhi, g_xhi);
    cudaGetSymbolAddress((void**)&pxlo, g_xlo);
    cudaGetSymbolAddress((void**)&pwthi, g_wthi);
    cudaGetSymbolAddress((void**)&pwtlo, g_wtlo);
    cudaGetSymbolAddress((void**)&pqf, g_qf);
    cudaGetSymbolAddress((void**)&pkf, g_kf);
    cudaGetSymbolAddress((void**)&pvthi, g_vthi);
    cudaGetSymbolAddress((void**)&pvtlo, g_vtlo);
    cudaGetSymbolAddress((void**)&paf, g_af);
    cudaGetSymbolAddress((void**)&pohhi, g_ohhi);
    cudaGetSymbolAddress((void**)&pohlo, g_ohlo);
    cudaGetSymbolAddress((void**)&ps, g_s);
    cudaGetSymbolAddress((void**)&pma, g_ma);
    cudaGetSymbolAddress((void**)&ptp, g_tp);

    // 1) conversions (conv_split also zero-inits accumulators)
    conv_split<<<(NROW * EE / 4) / 256, 256>>>(x, pxhi, pxlo, NROW * EE);
    conv_w4<<<dim3(16, 16, 4), dim3(32, 8)>>>(Wq, Wk, Wv, Wo, pwthi, pwtlo);

    // 2) fused QKV projection (q/k fp16, v fp16 hi/lo transposed)
    proj_qkv<<<dim3(8, 16, 3), 256>>>(pxhi, pxlo, pwthi, pwtlo, bq, bk, bv,
                                      pqf, pkf, pvthi, pvtlo);

    // 3) QK^T (fp16 single-pass)
    qk_mma<<<dim3(8, 4, BB * HH), 256>>>(pqf, pkf, ps);

    // 4) fused head-mean + transform + stats
    row_transform_fused<<<256, 256>>>(ps, pma, ptp, w1, b1, w2, b2);
    finalize_kernel<<<1, 32>>>();

    // 5) softmax -> attn fp16
    attn_softmax2<<<BB * SS, 256>>>(ps, pma, ptp, tau, paf);

    // 6) attn @ V (fp16 2-pass)
    av_mma<<<dim3(8, BB * HH), 256>>>(paf, pvthi, pvtlo, pohhi, pohlo);

    // 7) output projection (bf16 3-pass) -> fp32 out
    proj_out<<<dim3(8, 32), 256>>>(pohhi, pohlo, pwthi, pwtlo, bo, out);
}

// round 15
// speedup vs baseline: 1.9111x; 1.1081x over previous
#include <cuda_runtime.h>
#include <cuda_bf16.h>
#include <cuda_fp16.h>
#include <math.h>
#include <stdint.h>

#define BB 4
#define SS 512
#define EE 512
#define HH 8
#define HD 64
#define CC 128
#define NROW (BB*SS)          // 2048
#define PSTR 40               // smem row stride in 16-bit elems (80B) -> conflict-free ldmatrix

// ---------------- scratch (static device globals; no allocation) ----------------
__device__ __nv_bfloat16 g_xhi[NROW*EE], g_xlo[NROW*EE];
__device__ __nv_bfloat16 g_wthi[4*EE*EE], g_wtlo[4*EE*EE];           // transposed [n][k]
__device__ __half g_qf[BB*HH*SS*HD], g_kf[BB*HH*SS*HD];              // fp16 single [bh][s][d]
__device__ __half g_vthi[BB*HH*HD*SS], g_vtlo[BB*HH*HD*SS];          // fp16 hi/lo [bh][d][s]
__device__ float g_s[(size_t)BB*HH*SS*SS];                           // 32MB
__device__ float g_ma[BB*SS*SS];
__device__ float g_tp[BB*SS*SS];
__device__ __half g_af[(size_t)BB*HH*SS*SS];                         // fp16 attn, 16MB
__device__ __nv_bfloat16 g_ohhi[NROW*EE], g_ohlo[NROW*EE];           // [B,S,E]
__device__ double g_acc[BB*5];
__device__ int    g_amax[BB];
__device__ float  g_coef[BB*3];
__device__ float  g_mlp[3];   // P, N, flag (1 = fast path valid)

// ---------------- helpers ----------------
__device__ __forceinline__ float clipf(float v, float lo, float hi) {
    return fminf(fmaxf(v, lo), hi);
}
__device__ __forceinline__ uint32_t smem_u32(const void* p) {
    uint32_t a;
    asm("{ .reg .u64 t; cvta.to.shared.u64 t, %1; cvt.u32.u64 %0, t; }" : "=r"(a) : "l"(p));
    return a;
}
__device__ __forceinline__ void ldsm4(uint32_t* a, uint32_t addr) {
    asm volatile("ldmatrix.sync.aligned.m8n8.x4.shared.b16 {%0,%1,%2,%3}, [%4];"
        : "=r"(a[0]), "=r"(a[1]), "=r"(a[2]), "=r"(a[3]) : "r"(addr));
}
__device__ __forceinline__ void ldsm2(uint32_t* a, uint32_t addr) {
    asm volatile("ldmatrix.sync.aligned.m8n8.x2.shared.b16 {%0,%1}, [%2];"
        : "=r"(a[0]), "=r"(a[1]) : "r"(addr));
}
__device__ __forceinline__ void mma_bf16(float* d, const uint32_t* a, const uint32_t* b) {
    asm volatile("mma.sync.aligned.m16n8k16.row.col.f32.bf16.bf16.f32 "
        "{%0,%1,%2,%3}, {%4,%5,%6,%7}, {%8,%9}, {%0,%1,%2,%3};"
        : "+f"(d[0]), "+f"(d[1]), "+f"(d[2]), "+f"(d[3])
        : "r"(a[0]), "r"(a[1]), "r"(a[2]), "r"(a[3]), "r"(b[0]), "r"(b[1]));
}
__device__ __forceinline__ void mma_f16(float* d, const uint32_t* a, const uint32_t* b) {
    asm volatile("mma.sync.aligned.m16n8k16.row.col.f32.f16.f16.f32 "
        "{%0,%1,%2,%3}, {%4,%5,%6,%7}, {%8,%9}, {%0,%1,%2,%3};"
        : "+f"(d[0]), "+f"(d[1]), "+f"(d[2]), "+f"(d[3])
        : "r"(a[0]), "r"(a[1]), "r"(a[2]), "r"(a[3]), "r"(b[0]), "r"(b[1]));
}
__device__ __forceinline__ float warpSum(float v) {
    #pragma unroll
    for (int o = 16; o > 0; o >>= 1) v += __shfl_xor_sync(0xffffffffu, v, o);
    return v;
}
__device__ __forceinline__ float warpMax(float v) {
    #pragma unroll
    for (int o = 16; o > 0; o >>= 1) v = fmaxf(v, __shfl_xor_sync(0xffffffffu, v, o));
    return v;
}

// ================= conversion kernels =================
__global__ void conv_split(const float* __restrict__ in, __nv_bfloat16* __restrict__ hi,
                           __nv_bfloat16* __restrict__ lo, int n)
{
    if (blockIdx.x == 0 && threadIdx.x < 32) {
        int t = threadIdx.x;
        if (t < BB * 5) g_acc[t] = 0.0;
        if (t < BB) g_amax[t] = 0;
    }
    int i = (blockIdx.x * 256 + threadIdx.x) * 4;
    if (i < n) {
        float4 v = *(const float4*)(in + i);
        __nv_bfloat16 h0 = __float2bfloat16_rn(v.x);
        __nv_bfloat16 h1 = __float2bfloat16_rn(v.y);
        __nv_bfloat16 h2 = __float2bfloat16_rn(v.z);
        __nv_bfloat16 h3 = __float2bfloat16_rn(v.w);
        __nv_bfloat162 H0(h0, h1), H1(h2, h3);
        __nv_bfloat162 L0(__float2bfloat16_rn(v.x - __bfloat162float(h0)),
                          __float2bfloat16_rn(v.y - __bfloat162float(h1)));
        __nv_bfloat162 L1(__float2bfloat16_rn(v.z - __bfloat162float(h2)),
                          __float2bfloat16_rn(v.w - __bfloat162float(h3)));
        *(__nv_bfloat162*)(hi + i)     = H0;
        *(__nv_bfloat162*)(hi + i + 2) = H1;
        *(__nv_bfloat162*)(lo + i)     = L0;
        *(__nv_bfloat162*)(lo + i + 2) = L1;
    }
}

__global__ void conv_w4(const float* __restrict__ Wq, const float* __restrict__ Wk,
                        const float* __restrict__ Wv, const float* __restrict__ Wo,
                        __nv_bfloat16* __restrict__ thi, __nv_bfloat16* __restrict__ tlo)
{
    __shared__ float tile[32][33];
    int z = blockIdx.z;
    const float* W = (z == 0) ? Wq : (z == 1) ? Wk : (z == 2) ? Wv : Wo;
    __nv_bfloat16* th = thi + (size_t)z * EE * EE;
    __nv_bfloat16* tl = tlo + (size_t)z * EE * EE;
    int bx = blockIdx.x * 32, by = blockIdx.y * 32;
    int x = threadIdx.x, y = threadIdx.y;
    #pragma unroll
    for (int j = 0; j < 4; j++)
        tile[y + j * 8][x] = W[(size_t)(by + y + j * 8) * EE + bx + x];
    __syncthreads();
    #pragma unroll
    for (int j = 0; j < 4; j++) {
        float v = tile[x][y + j * 8];
        __nv_bfloat16 h = __float2bfloat16_rn(v);
        size_t dst = (size_t)(bx + y + j * 8) * EE + by + x;
        th[dst] = h;
        tl[dst] = __float2bfloat16_rn(v - __bfloat162float(h));
    }
}

// ================= MLP collapse prep: P = sum_{w1>0} w1*w2, N = sum_{w1<0} w1*w2 =====
// Fast path valid iff b1 == 0 exactly for all channels AND |w1|*0.4+|b1| < 5 (clip never binds).
__global__ void mlp_prep(const float* __restrict__ w1, const float* __restrict__ b1,
                         const float* __restrict__ w2)
{
    int lane = threadIdx.x;   // 32 threads
    float P = 0.f, N = 0.f;
    int ok = 1;
    for (int c = lane; c < CC; c += 32) {
        float a = w1[c], b = b1[c], d = w2[c];
        if (b != 0.f) ok = 0;
        if (fabsf(a) * 0.4f + fabsf(b) >= 5.f) ok = 0;
        if (a > 0.f) P += a * d; else N += a * d;
    }
    P = warpSum(P); N = warpSum(N);
    #pragma unroll
    for (int o = 16; o > 0; o >>= 1) ok = min(ok, __shfl_xor_sync(0xffffffffu, ok, o));
    if (lane == 0) { g_mlp[0] = P; g_mlp[1] = N; g_mlp[2] = (float)ok; }
}

// ================= fused QKV projection: 128x64 tiles, 2 CTA/SM =================
__global__ void __launch_bounds__(256, 2) proj_qkv(
    const __nv_bfloat16* __restrict__ xhi, const __nv_bfloat16* __restrict__ xlo,
    const __nv_bfloat16* __restrict__ wthi, const __nv_bfloat16* __restrict__ wtlo,
    const float* __restrict__ bq, const float* __restrict__ bk, const float* __restrict__ bv,
    __half* __restrict__ qf, __half* __restrict__ kf,
    __half* __restrict__ vthi, __half* __restrict__ vtlo)
{
    __shared__ __nv_bfloat16 sAh[128*PSTR], sAl[128*PSTR], sBh[64*PSTR], sBl[64*PSTR];
    int t = threadIdx.x, lane = t & 31, wid = t >> 5;
    int wm = wid >> 1, wn = wid & 1;
    int z = blockIdx.z;
    int n0 = blockIdx.x * 64, m0 = blockIdx.y * 128;
    const __nv_bfloat16* Bh = wthi + (size_t)z * EE * EE;
    const __nv_bfloat16* Bl = wtlo + (size_t)z * EE * EE;
    const float* bias = (z == 0) ? bq : ((z == 1) ? bk : bv);

    uint32_t bAh = smem_u32(sAh), bAl = smem_u32(sAl), bBh = smem_u32(sBh), bBl = smem_u32(sBl);
    float acc[2][4][4] = {};
    int mat = lane >> 3, r8 = lane & 7;

    for (int kc = 0; kc < 16; kc++) {
        #pragma unroll
        for (int i = t; i < 512; i += 256) {
            int row = i >> 2, seg = i & 3;
            size_t ga = (size_t)(m0 + row) * EE + kc * 32 + seg * 8;
            *(uint4*)&sAh[row * PSTR + seg * 8] = *(const uint4*)&xhi[ga];
            *(uint4*)&sAl[row * PSTR + seg * 8] = *(const uint4*)&xlo[ga];
        }
        {
            int row = t >> 2, seg = t & 3;
            size_t gb = (size_t)(n0 + row) * EE + kc * 32 + seg * 8;
            *(uint4*)&sBh[row * PSTR + seg * 8] = *(const uint4*)&Bh[gb];
            *(uint4*)&sBl[row * PSTR + seg * 8] = *(const uint4*)&Bl[gb];
        }
        __syncthreads();
        #pragma unroll
        for (int kk = 0; kk < 2; kk++) {
            uint32_t ah[2][4], al[2][4], bhf[4][2], blf[4][2];
            uint32_t aoff = (uint32_t)((wm * 32 + r8 + (mat & 1) * 8) * PSTR + kk * 16 + (mat >> 1) * 8) * 2;
            #pragma unroll
            for (int fm = 0; fm < 2; fm++) {
                uint32_t o = aoff + fm * 16 * PSTR * 2;
                ldsm4(ah[fm], bAh + o);
                ldsm4(al[fm], bAl + o);
            }
            uint32_t boff = (uint32_t)((wn * 32 + r8) * PSTR + kk * 16 + (mat & 1) * 8) * 2;
            #pragma unroll
            for (int fn = 0; fn < 4; fn++) {
                uint32_t o = boff + fn * 8 * PSTR * 2;
                ldsm2(bhf[fn], bBh + o);
                ldsm2(blf[fn], bBl + o);
            }
            #pragma unroll
            for (int fm = 0; fm < 2; fm++)
                #pragma unroll
                for (int fn = 0; fn < 4; fn++) {
                    mma_bf16(acc[fm][fn], ah[fm], bhf[fn]);
                    mma_bf16(acc[fm][fn], ah[fm], blf[fn]);
                    mma_bf16(acc[fm][fn], al[fm], bhf[fn]);
                }
        }
        __syncthreads();
    }

    #pragma unroll
    for (int fm = 0; fm < 2; fm++)
        #pragma unroll
        for (int fn = 0; fn < 4; fn++)
            #pragma unroll
            for (int drp = 0; drp < 2; drp++) {
                int m = m0 + wm * 32 + fm * 16 + (lane >> 2) + drp * 8;
                int n = n0 + wn * 32 + fn * 8 + (lane & 3) * 2;
                float v0 = acc[fm][fn][drp * 2 + 0] + bias[n];
                float v1 = acc[fm][fn][drp * 2 + 1] + bias[n + 1];
                int b = m >> 9, s = m & 511;
                int h = n >> 6, d = n & 63;
                if (z == 0) {
                    size_t dst = (((size_t)(b * HH + h) * SS) + s) * HD + d;
                    *(__half2*)&qf[dst] = __floats2half2_rn(v0, v1);
                } else if (z == 1) {
                    size_t dst = (((size_t)(b * HH + h) * SS) + s) * HD + d;
                    *(__half2*)&kf[dst] = __floats2half2_rn(v0, v1);
                } else {
                    size_t dst0 = (((size_t)(b * HH + h) * HD) + d) * SS + s;
                    __half h0 = __float2half_rn(v0);
                    __half h1 = __float2half_rn(v1);
                    vthi[dst0] = h0; vtlo[dst0] = __float2half_rn(v0 - __half2float(h0));
                    size_t dst1 = dst0 + SS;
                    vthi[dst1] = h1; vtlo[dst1] = __float2half_rn(v1 - __half2float(h1));
                }
            }
}

// ================= output projection: 64x64 tiles, bf16 3-pass, fp32 result =================
__global__ void __launch_bounds__(256, 2) proj_out(
    const __nv_bfloat16* __restrict__ ahi, const __nv_bfloat16* __restrict__ alo,
    const __nv_bfloat16* __restrict__ wthi, const __nv_bfloat16* __restrict__ wtlo,
    const float* __restrict__ bias, float* __restrict__ out)
{
    __shared__ __nv_bfloat16 sAh[64*PSTR], sAl[64*PSTR], sBh[64*PSTR], sBl[64*PSTR];
    int t = threadIdx.x, lane = t & 31, wid = t >> 5;
    int wm = wid >> 1, wn = wid & 1;
    int n0 = blockIdx.x * 64, m0 = blockIdx.y * 64;
    const __nv_bfloat16* Bh = wthi + (size_t)3 * EE * EE;
    const __nv_bfloat16* Bl = wtlo + (size_t)3 * EE * EE;

    uint32_t bAh = smem_u32(sAh), bAl = smem_u32(sAl), bBh = smem_u32(sBh), bBl = smem_u32(sBl);
    float acc[4][4] = {};
    int mat = lane >> 3, r8 = lane & 7;

    for (int kc = 0; kc < 16; kc++) {
        {
            int row = t >> 2, seg = t & 3;
            size_t ga = (size_t)(m0 + row) * EE + kc * 32 + seg * 8;
            *(uint4*)&sAh[row * PSTR + seg * 8] = *(const uint4*)&ahi[ga];
            *(uint4*)&sAl[row * PSTR + seg * 8] = *(const uint4*)&alo[ga];
            size_t gb = (size_t)(n0 + row) * EE + kc * 32 + seg * 8;
            *(uint4*)&sBh[row * PSTR + seg * 8] = *(const uint4*)&Bh[gb];
            *(uint4*)&sBl[row * PSTR + seg * 8] = *(const uint4*)&Bl[gb];
        }
        __syncthreads();
        #pragma unroll
        for (int kk = 0; kk < 2; kk++) {
            uint32_t ah[4], al[4], bhf[4][2], blf[4][2];
            uint32_t aoff = (uint32_t)((wm * 16 + r8 + (mat & 1) * 8) * PSTR + kk * 16 + (mat >> 1) * 8) * 2;
            ldsm4(ah, bAh + aoff);
            ldsm4(al, bAl + aoff);
            uint32_t boff = (uint32_t)((wn * 32 + r8) * PSTR + kk * 16 + (mat & 1) * 8) * 2;
            #pragma unroll
            for (int fn = 0; fn < 4; fn++) {
                uint32_t o = boff + fn * 8 * PSTR * 2;
                ldsm2(bhf[fn], bBh + o);
                ldsm2(blf[fn], bBl + o);
            }
            #pragma unroll
            for (int fn = 0; fn < 4; fn++) {
                mma_bf16(acc[fn], ah, bhf[fn]);
                mma_bf16(acc[fn], ah, blf[fn]);
                mma_bf16(acc[fn], al, bhf[fn]);
            }
        }
        __syncthreads();
    }

    #pragma unroll
    for (int fn = 0; fn < 4; fn++)
        #pragma unroll
        for (int drp = 0; drp < 2; drp++) {
            int m = m0 + wm * 16 + (lane >> 2) + drp * 8;
            int n = n0 + wn * 32 + fn * 8 + (lane & 3) * 2;
            float2 v;
            v.x = acc[fn][drp * 2 + 0] + bias[n];
            v.y = acc[fn][drp * 2 + 1] + bias[n + 1];
            *(float2*)&out[(size_t)m * EE + n] = v;
        }
}

// ================= batched QK^T: fp16 single-pass, 128x64 tiles, 3 CTA/SM =================
__global__ void __launch_bounds__(256, 3) qk_mma(
    const __half* __restrict__ qf, const __half* __restrict__ kf,
    float* __restrict__ s)
{
    __shared__ __half sA[128*PSTR], sB[64*PSTR];
    int t = threadIdx.x, lane = t & 31, wid = t >> 5;
    int wm = wid >> 1, wn = wid & 1;
    int j0 = blockIdx.x * 64, i0 = blockIdx.y * 128, bh = blockIdx.z;

    uint32_t bA = smem_u32(sA), bB = smem_u32(sB);
    float acc[2][4][4] = {};
    int mat = lane >> 3, r8 = lane & 7;

    for (int kc = 0; kc < 2; kc++) {
        #pragma unroll
        for (int i = t; i < 512; i += 256) {
            int row = i >> 2, seg = i & 3;
            size_t ga = ((size_t)bh * SS + i0 + row) * HD + kc * 32 + seg * 8;
            *(uint4*)&sA[row * PSTR + seg * 8] = *(const uint4*)&qf[ga];
        }
        {
            int row = t >> 2, seg = t & 3;
            size_t gb = ((size_t)bh * SS + j0 + row) * HD + kc * 32 + seg * 8;
            *(uint4*)&sB[row * PSTR + seg * 8] = *(const uint4*)&kf[gb];
        }
        __syncthreads();
        #pragma unroll
        for (int kk = 0; kk < 2; kk++) {
            uint32_t ah[2][4], bhf[4][2];
            uint32_t aoff = (uint32_t)((wm * 32 + r8 + (mat & 1) * 8) * PSTR + kk * 16 + (mat >> 1) * 8) * 2;
            #pragma unroll
            for (int fm = 0; fm < 2; fm++)
                ldsm4(ah[fm], bA + aoff + fm * 16 * PSTR * 2);
            uint32_t boff = (uint32_t)((wn * 32 + r8) * PSTR + kk * 16 + (mat & 1) * 8) * 2;
            #pragma unroll
            for (int fn = 0; fn < 4; fn++)
                ldsm2(bhf[fn], bB + boff + fn * 8 * PSTR * 2);
            #pragma unroll
            for (int fm = 0; fm < 2; fm++)
                #pragma unroll
                for (int fn = 0; fn < 4; fn++)
                    mma_f16(acc[fm][fn], ah[fm], bhf[fn]);
        }
        __syncthreads();
    }

    float* sbase = s + (size_t)bh * SS * SS;
    #pragma unroll
    for (int fm = 0; fm < 2; fm++)
        #pragma unroll
        for (int fn = 0; fn < 4; fn++)
            #pragma unroll
            for (int drp = 0; drp < 2; drp++) {
                int mi = i0 + wm * 32 + fm * 16 + (lane >> 2) + drp * 8;
                int nj = j0 + wn * 32 + fn * 8 + (lane & 3) * 2;
                float2 o;
                float v0 = acc[fm][fn][drp * 2 + 0] * 0.125f;
                float v1 = acc[fm][fn][drp * 2 + 1] * 0.125f;
                if (isnan(v0)) v0 = 0.f; else if (isinf(v0)) v0 = v0 > 0.f ? 10.f : -10.f;
                if (isnan(v1)) v1 = 0.f; else if (isinf(v1)) v1 = v1 > 0.f ? 10.f : -10.f;
                o.x = clipf(v0, -15.f, 15.f);
                o.y = clipf(v1, -15.f, 15.f);
                *(float2*)&sbase[(size_t)mi * SS + nj] = o;
            }
}

// ================= batched attn @ V: fp16 2-pass, 64x64 tiles =================
__global__ void __launch_bounds__(256, 2) av_mma(
    const __half* __restrict__ af,
    const __half* __restrict__ vthi, const __half* __restrict__ vtlo,
    __nv_bfloat16* __restrict__ ohi, __nv_bfloat16* __restrict__ olo)
{
    __shared__ __half sA[64*PSTR], sBh[64*PSTR], sBl[64*PSTR];
    int t = threadIdx.x, lane = t & 31, wid = t >> 5;
    int wm = wid >> 1, wn = wid & 1;
    int i0 = blockIdx.x * 64, bh = blockIdx.y;
    int b = bh >> 3, h = bh & 7;

    uint32_t bA = smem_u32(sA), bBh = smem_u32(sBh), bBl = smem_u32(sBl);
    float acc[4][4] = {};
    int mat = lane >> 3, r8 = lane & 7;

    for (int kc = 0; kc < 16; kc++) {
        {
            int row = t >> 2, seg = t & 3;
            size_t ga = (size_t)bh * SS * SS + (size_t)(i0 + row) * SS + kc * 32 + seg * 8;
            *(uint4*)&sA[row * PSTR + seg * 8] = *(const uint4*)&af[ga];
            size_t gb = ((size_t)bh * HD + row) * SS + kc * 32 + seg * 8;
            *(uint4*)&sBh[row * PSTR + seg * 8] = *(const uint4*)&vthi[gb];
            *(uint4*)&sBl[row * PSTR + seg * 8] = *(const uint4*)&vtlo[gb];
        }
        __syncthreads();
        #pragma unroll
        for (int kk = 0; kk < 2; kk++) {
            uint32_t ah[4], bhf[4][2], blf[4][2];
            uint32_t aoff = (uint32_t)((wm * 16 + r8 + (mat & 1) * 8) * PSTR + kk * 16 + (mat >> 1) * 8) * 2;
            ldsm4(ah, bA + aoff);
            uint32_t boff = (uint32_t)((wn * 32 + r8) * PSTR + kk * 16 + (mat & 1) * 8) * 2;
            #pragma unroll
            for (int fn = 0; fn < 4; fn++) {
                uint32_t o = boff + fn * 8 * PSTR * 2;
                ldsm2(bhf[fn], bBh + o);
                ldsm2(blf[fn], bBl + o);
            }
            #pragma unroll
            for (int fn = 0; fn < 4; fn++) {
                mma_f16(acc[fn], ah, bhf[fn]);
                mma_f16(acc[fn], ah, blf[fn]);
            }
        }
        __syncthreads();
    }

    #pragma unroll
    for (int fn = 0; fn < 4; fn++)
        #pragma unroll
        for (int drp = 0; drp < 2; drp++) {
            int si = i0 + wm * 16 + (lane >> 2) + drp * 8;
            int d  = wn * 32 + fn * 8 + (lane & 3) * 2;
            float v0 = acc[fn][drp * 2 + 0];
            float v1 = acc[fn][drp * 2 + 1];
            size_t dst = ((size_t)b * SS + si) * EE + h * HD + d;
            __nv_bfloat16 h0 = __float2bfloat16_rn(v0);
            __nv_bfloat16 h1 = __float2bfloat16_rn(v1);
            *(__nv_bfloat162*)&ohi[dst] = __nv_bfloat162(h0, h1);
            *(__nv_bfloat162*)&olo[dst] = __nv_bfloat162(
                __float2bfloat16_rn(v0 - __bfloat162float(h0)),
                __float2bfloat16_rn(v1 - __bfloat162float(h1)));
        }
}

// ================= fused head-mean + row transform (warp-per-row, float4) =================
__global__ void __launch_bounds__(256) row_transform_fused(
    const float* __restrict__ s, float* __restrict__ ma, float* __restrict__ tp,
    const float* __restrict__ w1, const float* __restrict__ b1,
    const float* __restrict__ w2, const float* __restrict__ b2)
{
    __shared__ float w1s[CC], b1s[CC], w2s[CC];
    int t = threadIdx.x, lane = t & 31, w = t >> 5;
    float mlpP = g_mlp[0], mlpN = g_mlp[1];
    int fast = (g_mlp[2] != 0.f);
    if (!fast && t < CC) { w1s[t] = w1[t]; b1s[t] = b1[t]; w2s[t] = w2[t]; }
    __syncthreads();

    int row = blockIdx.x * 8 + w;
    int b = row >> 9, i = row & 511;
    const float* sb = s + ((size_t)b * HH * SS + i) * SS;
    float* marow = ma + ((size_t)b * SS + i) * SS;
    float* tprow = tp + ((size_t)b * SS + i) * SS;

    float m[16];
    #pragma unroll
    for (int e2 = 0; e2 < 4; e2++) {
        int f = lane + 32 * e2;
        float4 acc4 = make_float4(0.f, 0.f, 0.f, 0.f);
        #pragma unroll
        for (int hh = 0; hh < HH; hh++) {
            float4 v = ((const float4*)(sb + (size_t)hh * SS * SS))[f];
            acc4.x += v.x; acc4.y += v.y; acc4.z += v.z; acc4.w += v.w;
        }
        acc4.x *= 0.125f; acc4.y *= 0.125f; acc4.z *= 0.125f; acc4.w *= 0.125f;
        ((float4*)marow)[f] = acc4;
        m[e2 * 4 + 0] = acc4.x; m[e2 * 4 + 1] = acc4.y;
        m[e2 * 4 + 2] = acc4.z; m[e2 * 4 + 3] = acc4.w;
    }

    float mx = -1e30f;
    #pragma unroll
    for (int e = 0; e < 16; e++) mx = fmaxf(mx, clipf(m[e], -10.f, 10.f));
    mx = warpMax(mx);
    float a_[16]; float sum = 0.f;
    #pragma unroll
    for (int e = 0; e < 16; e++) { a_[e] = __expf(clipf(m[e], -10.f, 10.f) - mx); sum += a_[e]; }
    sum = warpSum(sum);
    float inv = 1.f / sum;
    float h_[16];
    #pragma unroll
    for (int e = 0; e < 16; e++) { float p = a_[e] * inv; h_[e] = -p * __logf(p + 1e-6f); }

    float sma = 0.f, sma2 = 0.f, shh = 0.f, amx = 0.f;
    #pragma unroll
    for (int e = 0; e < 16; e++) {
        sma += m[e]; sma2 += m[e] * m[e]; shh += h_[e]; amx = fmaxf(amx, fabsf(m[e]));
    }
    sma = warpSum(sma); sma2 = warpSum(sma2); shh = warpSum(shh); amx = warpMax(amx);

    float hmx = -1e30f;
    #pragma unroll
    for (int e = 0; e < 16; e++) hmx = fmaxf(hmx, h_[e]);
    hmx = warpMax(hmx) * 3.f;
    float fsum = 0.f;
    #pragma unroll
    for (int e = 0; e < 16; e++) { h_[e] = __expf(3.f * h_[e] - hmx); fsum += h_[e]; }
    fsum = warpSum(fsum);
    float finv = 1.f / fsum;

    float acc[16];
    if (fast) {
        // MLP collapse: b1==0, clip(+-5) never binds ->
        //   ap_pre = sa * (sa>0 ? P : N)
        #pragma unroll
        for (int e = 0; e < 16; e++) {
            float sa = clipf(clipf(m[e], -8.f, 8.f) * 0.05f, -10.f, 10.f);
            acc[e] = sa * (sa > 0.f ? mlpP : mlpN);
        }
    } else {
        float sa[16];
        #pragma unroll
        for (int e = 0; e < 16; e++) {
            sa[e] = clipf(clipf(m[e], -8.f, 8.f) * 0.05f, -10.f, 10.f);
            acc[e] = 0.f;
        }
        #pragma unroll 4
        for (int c = 0; c < CC; c++) {
            float wv = w1s[c], bb = b1s[c], w2v = w2s[c];
            #pragma unroll
            for (int e = 0; e < 16; e++)
                acc[e] += fminf(fmaxf(fminf(fmaxf(sa[e] * wv + bb, -5.f), 5.f), 0.f), 5.f) * w2v;
        }
    }
    float b2v = b2[0];
    float stt = 0.f, st2 = 0.f;
    #pragma unroll
    for (int e2 = 0; e2 < 4; e2++) {
        float4 o;
        float* op = (float*)&o;
        #pragma unroll
        for (int q = 0; q < 4; q++) {
            int e = e2 * 4 + q;
            float ap = clipf(acc[e] + b2v, -5.f, 5.f);
            float ty = clipf(1.f + 2.5f * ap, 0.5f, 1.5f);
            float sg = 1.f / (1.f + __expf(-ty));
            float tv = sg * (h_[e] * finv);
            op[q] = tv;
            stt += tv; st2 += tv * tv;
        }
        ((float4*)tprow)[lane + 32 * e2] = o;
    }
    stt = warpSum(stt); st2 = warpSum(st2);

    if (lane == 0) {
        atomicAdd(&g_acc[b * 5 + 0], (double)sma);
        atomicAdd(&g_acc[b * 5 + 1], (double)sma2);
        atomicAdd(&g_acc[b * 5 + 2], (double)shh);
        atomicAdd(&g_acc[b * 5 + 3], (double)stt);
        atomicAdd(&g_acc[b * 5 + 4], (double)st2);
        atomicMax(&g_amax[b], __float_as_int(amx));
    }
}

__global__ void finalize_kernel()
{
    int b = threadIdx.x;
    if (b < BB) {
        const double N = (double)SS * (double)SS;
        double sma  = g_acc[b * 5 + 0];
        double sma2 = g_acc[b * 5 + 1];
        double sh   = g_acc[b * 5 + 2];
        double st   = g_acc[b * 5 + 3];
        double st2  = g_acc[b * 5 + 4];
        float amaxv = __int_as_float(g_amax[b]);

        float eo = sqrtf((float)sma2) + 1e-4f;
        float et = sqrtf((float)st2) + 1e-4f;
        float c  = clipf(eo / et, 0.8f, 1.2f);
        float tm = c * (float)(st / N);
        float tvar = c * c * (float)(st2 / N - (st / N) * (st / N));
        tvar = fmaxf(tvar, 0.01f);
        float ovar = (float)(sma2 / N - (sma / N) * (sma / N));
        ovar = fmaxf(ovar, 0.01f);
        float gd = clipf(sqrtf(ovar) / sqrtf(tvar), 0.8f, 1.2f);
        float ar = clipf(amaxv, 1.f, 10.f);
        float sm = clipf(0.3f / log1pf(ar), 0.1f, 0.5f);
        float ent = (float)(sh / N);
        float ne = ent / logf((float)SS);
        float rr = 0.4f * (1.f - clipf(ne, 0.f, 0.4f));
        float smgd = sm * gd;

        g_coef[b * 3 + 0] = rr * tm * (1.f - smgd);
        g_coef[b * 3 + 1] = rr * smgd * c;
        g_coef[b * 3 + 2] = rr;
    }
}

// ================= softmax + delta: CTA per (b,i), smem delta, fp16 out =================
__global__ void __launch_bounds__(256) attn_softmax2(
    const float* __restrict__ s, const float* __restrict__ ma,
    const float* __restrict__ tp, const float* __restrict__ tau,
    __half* __restrict__ af)
{
    __shared__ float delta[SS];
    int t = threadIdx.x, lane = t & 31, w = t >> 5;
    int bi = blockIdx.x;
    int b = bi >> 9;

    float A  = g_coef[b * 3 + 0];
    float Bc = g_coef[b * 3 + 1];
    float Cc = g_coef[b * 3 + 2];
    float itau = 1.f / tau[0];

    {
        const float2* ma2 = (const float2*)(ma + (size_t)bi * SS);
        const float2* tp2 = (const float2*)(tp + (size_t)bi * SS);
        float2 mv = ma2[t], tv = tp2[t];
        delta[t * 2 + 0] = A + Bc * tv.x - Cc * mv.x;
        delta[t * 2 + 1] = A + Bc * tv.y - Cc * mv.y;
    }
    __syncthreads();

    int i = bi & 511;
    size_t row = ((size_t)(b * HH + w) * SS + i);
    const float4* srow4 = (const float4*)(s + row * SS);
    const float4* d4 = (const float4*)delta;

    float v[16];
    float mx = -1e30f;
    #pragma unroll
    for (int e2 = 0; e2 < 4; e2++) {
        int f = lane + 32 * e2;
        float4 sv = srow4[f];
        float4 dv = d4[f];
        v[e2*4+0] = (sv.x + dv.x) * itau;
        v[e2*4+1] = (sv.y + dv.y) * itau;
        v[e2*4+2] = (sv.z + dv.z) * itau;
        v[e2*4+3] = (sv.w + dv.w) * itau;
        mx = fmaxf(mx, fmaxf(fmaxf(v[e2*4+0], v[e2*4+1]), fmaxf(v[e2*4+2], v[e2*4+3])));
    }
    mx = warpMax(mx);
    float sum = 0.f;
    #pragma unroll
    for (int e = 0; e < 16; e++) { v[e] = __expf(v[e] - mx); sum += v[e]; }
    sum = warpSum(sum);
    float inv = 1.f / sum;

    uint2* arow = (uint2*)(af + row * SS);
    #pragma unroll
    for (int e2 = 0; e2 < 4; e2++) {
        int f = lane + 32 * e2;
        __half2 ha = __floats2half2_rn(v[e2*4+0] * inv, v[e2*4+1] * inv);
        __half2 hb = __floats2half2_rn(v[e2*4+2] * inv, v[e2*4+3] * inv);
        uint2 u;
        u.x = *(uint32_t*)&ha;
        u.y = *(uint32_t*)&hb;
        arow[f] = u;
    }
}

// ---------------- launch ----------------
extern "C" void kernel_launch(void* const* d_in, const int* in_sizes, int n_in,
                              void* d_out, int out_size)
{
    const float* x  = (const float*)d_in[0];
    const float* Wq = (const float*)d_in[1];
    const float* bq = (const float*)d_in[2];
    const float* Wk = (const float*)d_in[3];
    const float* bk = (const float*)d_in[4];
    const float* Wv = (const float*)d_in[5];
    const float* bv = (const float*)d_in[6];
    const float* Wo = (const float*)d_in[7];
    const float* bo = (const float*)d_in[8];
    const float* w1 = (const float*)d_in[9];
    const float* b1 = (const float*)d_in[10];
    const float* w2 = (const float*)d_in[11];
    const float* b2 = (const float*)d_in[12];
    const float* tau = (const float*)d_in[13];
    float* out = (float*)d_out;

    __nv_bfloat16 *pxhi, *pxlo, *pwthi, *pwtlo, *pohhi, *pohlo;
    __half *pqf, *pkf, *pvthi, *pvtlo, *paf;
    float *ps, *pma, *ptp;
    cudaGetSymbolAddress((void**)&pxhi, g_xhi);
    cudaGetSymbolAddress((void**)&pxlo, g_xlo);
    cudaGetSymbolAddress((void**)&pwthi, g_wthi);
    cudaGetSymbolAddress((void**)&pwtlo, g_wtlo);
    cudaGetSymbolAddress((void**)&pqf, g_qf);
    cudaGetSymbolAddress((void**)&pkf, g_kf);
    cudaGetSymbolAddress((void**)&pvthi, g_vthi);
    cudaGetSymbolAddress((void**)&pvtlo, g_vtlo);
    cudaGetSymbolAddress((void**)&paf, g_af);
    cudaGetSymbolAddress((void**)&pohhi, g_ohhi);
    cudaGetSymbolAddress((void**)&pohlo, g_ohlo);
    cudaGetSymbolAddress((void**)&ps, g_s);
    cudaGetSymbolAddress((void**)&pma, g_ma);
    cudaGetSymbolAddress((void**)&ptp, g_tp);

    // 1) conversions + MLP prep
    conv_split<<<(NROW * EE / 4) / 256, 256>>>(x, pxhi, pxlo, NROW * EE);
    conv_w4<<<dim3(16, 16, 4), dim3(32, 8)>>>(Wq, Wk, Wv, Wo, pwthi, pwtlo);
    mlp_prep<<<1, 32>>>(w1, b1, w2);

    // 2) fused QKV projection (q/k fp16, v fp16 hi/lo transposed)
    proj_qkv<<<dim3(8, 16, 3), 256>>>(pxhi, pxlo, pwthi, pwtlo, bq, bk, bv,
                                      pqf, pkf, pvthi, pvtlo);

    // 3) QK^T (fp16 single-pass, 3 CTA/SM)
    qk_mma<<<dim3(8, 4, BB * HH), 256>>>(pqf, pkf, ps);

    // 4) fused head-mean + transform + stats (MLP fast path)
    row_transform_fused<<<256, 256>>>(ps, pma, ptp, w1, b1, w2, b2);
    finalize_kernel<<<1, 32>>>();

    // 5) softmax -> attn fp16
    attn_softmax2<<<BB * SS, 256>>>(ps, pma, ptp, tau, paf);

    // 6) attn @ V (fp16 2-pass)
    av_mma<<<dim3(8, BB * HH), 256>>>(paf, pvthi, pvtlo, pohhi, pohlo);

    // 7) output projection (bf16 3-pass) -> fp32 out
    proj_out<<<dim3(8, 32), 256>>>(pohhi, pohlo, pwthi, pwtlo, bo, out);
}

// round 17
// speedup vs baseline: 2.2876x; 1.1970x over previous
#include <cuda_runtime.h>
#include <cuda_bf16.h>
#include <cuda_fp16.h>
#include <math.h>
#include <stdint.h>

#define BB 4
#define SS 512
#define EE 512
#define HH 8
#define HD 64
#define CC 128
#define NROW (BB*SS)          // 2048
#define PSTR 40               // smem row stride in 16-bit elems (80B) -> conflict-free ldmatrix

// ---------------- scratch (static device globals; no allocation) ----------------
__device__ __half g_xhi[NROW*EE], g_xlo[NROW*EE];                    // fp16 hi/lo input
__device__ __half g_wf[4*EE*EE];                                     // fp16 single, transposed [n][k]
__device__ __nv_bfloat16 g_wthi[4*EE*EE], g_wtlo[4*EE*EE];           // bf16 hi/lo (only z=3 used)
__device__ __half g_qf[BB*HH*SS*HD], g_kf[BB*HH*SS*HD];              // fp16 single [bh][s][d]
__device__ __half g_vthi[BB*HH*HD*SS], g_vtlo[BB*HH*HD*SS];          // fp16 hi/lo [bh][d][s]
__device__ float g_s[(size_t)BB*HH*SS*SS];                           // 32MB
__device__ float g_ma[BB*SS*SS];
__device__ float g_tp[BB*SS*SS];
__device__ __half g_af[(size_t)BB*HH*SS*SS];                         // fp16 attn, 16MB
__device__ __nv_bfloat16 g_ohhi[NROW*EE], g_ohlo[NROW*EE];           // [B,S,E]
__device__ double g_acc[BB*5];
__device__ int    g_amax[BB];
__device__ float  g_coef[BB*3];
__device__ float  g_mlp[3];   // P, N, flag (1 = fast path valid)

// ---------------- helpers ----------------
__device__ __forceinline__ float clipf(float v, float lo, float hi) {
    return fminf(fmaxf(v, lo), hi);
}
__device__ __forceinline__ uint32_t smem_u32(const void* p) {
    uint32_t a;
    asm("{ .reg .u64 t; cvta.to.shared.u64 t, %1; cvt.u32.u64 %0, t; }" : "=r"(a) : "l"(p));
    return a;
}
__device__ __forceinline__ void ldsm4(uint32_t* a, uint32_t addr) {
    asm volatile("ldmatrix.sync.aligned.m8n8.x4.shared.b16 {%0,%1,%2,%3}, [%4];"
        : "=r"(a[0]), "=r"(a[1]), "=r"(a[2]), "=r"(a[3]) : "r"(addr));
}
__device__ __forceinline__ void ldsm2(uint32_t* a, uint32_t addr) {
    asm volatile("ldmatrix.sync.aligned.m8n8.x2.shared.b16 {%0,%1}, [%2];"
        : "=r"(a[0]), "=r"(a[1]) : "r"(addr));
}
__device__ __forceinline__ void mma_bf16(float* d, const uint32_t* a, const uint32_t* b) {
    asm volatile("mma.sync.aligned.m16n8k16.row.col.f32.bf16.bf16.f32 "
        "{%0,%1,%2,%3}, {%4,%5,%6,%7}, {%8,%9}, {%0,%1,%2,%3};"
        : "+f"(d[0]), "+f"(d[1]), "+f"(d[2]), "+f"(d[3])
        : "r"(a[0]), "r"(a[1]), "r"(a[2]), "r"(a[3]), "r"(b[0]), "r"(b[1]));
}
__device__ __forceinline__ void mma_f16(float* d, const uint32_t* a, const uint32_t* b) {
    asm volatile("mma.sync.aligned.m16n8k16.row.col.f32.f16.f16.f32 "
        "{%0,%1,%2,%3}, {%4,%5,%6,%7}, {%8,%9}, {%0,%1,%2,%3};"
        : "+f"(d[0]), "+f"(d[1]), "+f"(d[2]), "+f"(d[3])
        : "r"(a[0]), "r"(a[1]), "r"(a[2]), "r"(a[3]), "r"(b[0]), "r"(b[1]));
}
__device__ __forceinline__ float warpSum(float v) {
    #pragma unroll
    for (int o = 16; o > 0; o >>= 1) v += __shfl_xor_sync(0xffffffffu, v, o);
    return v;
}
__device__ __forceinline__ float warpMax(float v) {
    #pragma unroll
    for (int o = 16; o > 0; o >>= 1) v = fmaxf(v, __shfl_xor_sync(0xffffffffu, v, o));
    return v;
}

// ================= conversion kernels =================
__global__ void conv_split(const float* __restrict__ in, __half* __restrict__ hi,
                           __half* __restrict__ lo, int n)
{
    if (blockIdx.x == 0 && threadIdx.x < 32) {
        int t = threadIdx.x;
        if (t < BB * 5) g_acc[t] = 0.0;
        if (t < BB) g_amax[t] = 0;
    }
    int i = (blockIdx.x * 256 + threadIdx.x) * 4;
    if (i < n) {
        float4 v = *(const float4*)(in + i);
        __half h0 = __float2half_rn(v.x);
        __half h1 = __float2half_rn(v.y);
        __half h2 = __float2half_rn(v.z);
        __half h3 = __float2half_rn(v.w);
        __half2 H0(h0, h1), H1(h2, h3);
        __half2 L0(__float2half_rn(v.x - __half2float(h0)),
                   __float2half_rn(v.y - __half2float(h1)));
        __half2 L1(__float2half_rn(v.z - __half2float(h2)),
                   __float2half_rn(v.w - __half2float(h3)));
        *(__half2*)(hi + i)     = H0;
        *(__half2*)(hi + i + 2) = H1;
        *(__half2*)(lo + i)     = L0;
        *(__half2*)(lo + i + 2) = L1;
    }
}

// transpose; fp16 single for all z, bf16 hi/lo additionally for z==3 (Wo)
__global__ void conv_w4(const float* __restrict__ Wq, const float* __restrict__ Wk,
                        const float* __restrict__ Wv, const float* __restrict__ Wo,
                        __half* __restrict__ wf,
                        __nv_bfloat16* __restrict__ thi, __nv_bfloat16* __restrict__ tlo)
{
    __shared__ float tile[32][33];
    int z = blockIdx.z;
    const float* W = (z == 0) ? Wq : (z == 1) ? Wk : (z == 2) ? Wv : Wo;
    int bx = blockIdx.x * 32, by = blockIdx.y * 32;
    int x = threadIdx.x, y = threadIdx.y;
    #pragma unroll
    for (int j = 0; j < 4; j++)
        tile[y + j * 8][x] = W[(size_t)(by + y + j * 8) * EE + bx + x];
    __syncthreads();
    #pragma unroll
    for (int j = 0; j < 4; j++) {
        float v = tile[x][y + j * 8];
        size_t dst = (size_t)z * EE * EE + (size_t)(bx + y + j * 8) * EE + by + x;
        wf[dst] = __float2half_rn(v);
        if (z == 3) {
            __nv_bfloat16 h = __float2bfloat16_rn(v);
            thi[dst] = h;
            tlo[dst] = __float2bfloat16_rn(v - __bfloat162float(h));
        }
    }
}

// ================= MLP collapse prep =================
__global__ void mlp_prep(const float* __restrict__ w1, const float* __restrict__ b1,
                         const float* __restrict__ w2)
{
    int lane = threadIdx.x;
    float P = 0.f, N = 0.f;
    int ok = 1;
    for (int c = lane; c < CC; c += 32) {
        float a = w1[c], b = b1[c], d = w2[c];
        if (b != 0.f) ok = 0;
        if (fabsf(a) * 0.4f + fabsf(b) >= 5.f) ok = 0;
        if (a > 0.f) P += a * d; else N += a * d;
    }
    P = warpSum(P); N = warpSum(N);
    #pragma unroll
    for (int o = 16; o > 0; o >>= 1) ok = min(ok, __shfl_xor_sync(0xffffffffu, ok, o));
    if (lane == 0) { g_mlp[0] = P; g_mlp[1] = N; g_mlp[2] = (float)ok; }
}

// ================= fused QKV projection: fp16 2-pass, reg-prefetch pipeline =================
// grid (8, 16, 3); 128x64 tiles; warps 4x2 (wm 0..3, wn 0..1); warp tile 32x32
__global__ void __launch_bounds__(256, 2) proj_qkv(
    const __half* __restrict__ xhi, const __half* __restrict__ xlo,
    const __half* __restrict__ wf,
    const float* __restrict__ bq, const float* __restrict__ bk, const float* __restrict__ bv,
    __half* __restrict__ qf, __half* __restrict__ kf,
    __half* __restrict__ vthi, __half* __restrict__ vtlo)
{
    __shared__ __half sAh[128*PSTR], sAl[128*PSTR], sB[64*PSTR];
    int t = threadIdx.x, lane = t & 31, wid = t >> 5;
    int wm = wid >> 1, wn = wid & 1;
    int z = blockIdx.z;
    int n0 = blockIdx.x * 64, m0 = blockIdx.y * 128;
    const __half* Bw = wf + (size_t)z * EE * EE;
    const float* bias = (z == 0) ? bq : ((z == 1) ? bk : bv);

    uint32_t bAh = smem_u32(sAh), bAl = smem_u32(sAl), bB = smem_u32(sB);
    float acc[2][4][4] = {};
    int mat = lane >> 3, r8 = lane & 7;

    // thread's fixed load roles
    int arow0 = t >> 2, aseg0 = t & 3;                 // A part 0 (rows 0..63)
    int arow1 = (t + 256) >> 2, aseg1 = (t + 256) & 3; // A part 1 (rows 64..127)
    int brow = t >> 2, bseg = t & 3;                   // B (64 rows)
    uint32_t sA0 = (uint32_t)(arow0 * PSTR + aseg0 * 8) * 2;
    uint32_t sA1 = (uint32_t)(arow1 * PSTR + aseg1 * 8) * 2;
    uint32_t sB0 = (uint32_t)(brow * PSTR + bseg * 8) * 2;

    uint4 pAh0, pAh1, pAl0, pAl1, pB1;
    {
        size_t ga0 = (size_t)(m0 + arow0) * EE + aseg0 * 8;
        size_t ga1 = (size_t)(m0 + arow1) * EE + aseg1 * 8;
        size_t gb  = (size_t)(n0 + brow) * EE + bseg * 8;
        pAh0 = *(const uint4*)&xhi[ga0]; pAl0 = *(const uint4*)&xlo[ga0];
        pAh1 = *(const uint4*)&xhi[ga1]; pAl1 = *(const uint4*)&xlo[ga1];
        pB1  = *(const uint4*)&Bw[gb];
    }

    for (int kc = 0; kc < 16; kc++) {
        *(uint4*)((char*)sAh + sA0) = pAh0;
        *(uint4*)((char*)sAh + sA1) = pAh1;
        *(uint4*)((char*)sAl + sA0) = pAl0;
        *(uint4*)((char*)sAl + sA1) = pAl1;
        *(uint4*)((char*)sB  + sB0) = pB1;
        __syncthreads();

        if (kc < 15) {
            int kn = (kc + 1) * 32;
            size_t ga0 = (size_t)(m0 + arow0) * EE + kn + aseg0 * 8;
            size_t ga1 = (size_t)(m0 + arow1) * EE + kn + aseg1 * 8;
            size_t gb  = (size_t)(n0 + brow) * EE + kn + bseg * 8;
            pAh0 = *(const uint4*)&xhi[ga0]; pAl0 = *(const uint4*)&xlo[ga0];
            pAh1 = *(const uint4*)&xhi[ga1]; pAl1 = *(const uint4*)&xlo[ga1];
            pB1  = *(const uint4*)&Bw[gb];
        }

        #pragma unroll
        for (int kk = 0; kk < 2; kk++) {
            uint32_t ah[2][4], al[2][4], bf[4][2];
            uint32_t aoff = (uint32_t)((wm * 32 + r8 + (mat & 1) * 8) * PSTR + kk * 16 + (mat >> 1) * 8) * 2;
            #pragma unroll
            for (int fm = 0; fm < 2; fm++) {
                uint32_t o = aoff + fm * 16 * PSTR * 2;
                ldsm4(ah[fm], bAh + o);
                ldsm4(al[fm], bAl + o);
            }
            uint32_t boff = (uint32_t)((wn * 32 + r8) * PSTR + kk * 16 + (mat & 1) * 8) * 2;
            #pragma unroll
            for (int fn = 0; fn < 4; fn++)
                ldsm2(bf[fn], bB + boff + fn * 8 * PSTR * 2);
            #pragma unroll
            for (int fm = 0; fm < 2; fm++)
                #pragma unroll
                for (int fn = 0; fn < 4; fn++) {
                    mma_f16(acc[fm][fn], ah[fm], bf[fn]);
                    mma_f16(acc[fm][fn], al[fm], bf[fn]);
                }
        }
        __syncthreads();
    }

    #pragma unroll
    for (int fm = 0; fm < 2; fm++)
        #pragma unroll
        for (int fn = 0; fn < 4; fn++)
            #pragma unroll
            for (int drp = 0; drp < 2; drp++) {
                int m = m0 + wm * 32 + fm * 16 + (lane >> 2) + drp * 8;
                int n = n0 + wn * 32 + fn * 8 + (lane & 3) * 2;
                float v0 = acc[fm][fn][drp * 2 + 0] + bias[n];
                float v1 = acc[fm][fn][drp * 2 + 1] + bias[n + 1];
                int b = m >> 9, s = m & 511;
                int h = n >> 6, d = n & 63;
                if (z == 0) {
                    size_t dst = (((size_t)(b * HH + h) * SS) + s) * HD + d;
                    *(__half2*)&qf[dst] = __floats2half2_rn(v0, v1);
                } else if (z == 1) {
                    size_t dst = (((size_t)(b * HH + h) * SS) + s) * HD + d;
                    *(__half2*)&kf[dst] = __floats2half2_rn(v0, v1);
                } else {
                    size_t dst0 = (((size_t)(b * HH + h) * HD) + d) * SS + s;
                    __half h0 = __float2half_rn(v0);
                    __half h1 = __float2half_rn(v1);
                    vthi[dst0] = h0; vtlo[dst0] = __float2half_rn(v0 - __half2float(h0));
                    size_t dst1 = dst0 + SS;
                    vthi[dst1] = h1; vtlo[dst1] = __float2half_rn(v1 - __half2float(h1));
                }
            }
}

// ================= output projection: 64x64 tiles, bf16 3-pass, fp32 result =================
__global__ void __launch_bounds__(256, 2) proj_out(
    const __nv_bfloat16* __restrict__ ahi, const __nv_bfloat16* __restrict__ alo,
    const __nv_bfloat16* __restrict__ wthi, const __nv_bfloat16* __restrict__ wtlo,
    const float* __restrict__ bias, float* __restrict__ out)
{
    __shared__ __nv_bfloat16 sAh[64*PSTR], sAl[64*PSTR], sBh[64*PSTR], sBl[64*PSTR];
    int t = threadIdx.x, lane = t & 31, wid = t >> 5;
    int wm = wid >> 1, wn = wid & 1;
    int n0 = blockIdx.x * 64, m0 = blockIdx.y * 64;
    const __nv_bfloat16* Bh = wthi + (size_t)3 * EE * EE;
    const __nv_bfloat16* Bl = wtlo + (size_t)3 * EE * EE;

    uint32_t bAh = smem_u32(sAh), bAl = smem_u32(sAl), bBh = smem_u32(sBh), bBl = smem_u32(sBl);
    float acc[4][4] = {};
    int mat = lane >> 3, r8 = lane & 7;

    for (int kc = 0; kc < 16; kc++) {
        {
            int row = t >> 2, seg = t & 3;
            size_t ga = (size_t)(m0 + row) * EE + kc * 32 + seg * 8;
            *(uint4*)&sAh[row * PSTR + seg * 8] = *(const uint4*)&ahi[ga];
            *(uint4*)&sAl[row * PSTR + seg * 8] = *(const uint4*)&alo[ga];
            size_t gb = (size_t)(n0 + row) * EE + kc * 32 + seg * 8;
            *(uint4*)&sBh[row * PSTR + seg * 8] = *(const uint4*)&Bh[gb];
            *(uint4*)&sBl[row * PSTR + seg * 8] = *(const uint4*)&Bl[gb];
        }
        __syncthreads();
        #pragma unroll
        for (int kk = 0; kk < 2; kk++) {
            uint32_t ah[4], al[4], bhf[4][2], blf[4][2];
            uint32_t aoff = (uint32_t)((wm * 16 + r8 + (mat & 1) * 8) * PSTR + kk * 16 + (mat >> 1) * 8) * 2;
            ldsm4(ah, bAh + aoff);
            ldsm4(al, bAl + aoff);
            uint32_t boff = (uint32_t)((wn * 32 + r8) * PSTR + kk * 16 + (mat & 1) * 8) * 2;
            #pragma unroll
            for (int fn = 0; fn < 4; fn++) {
                uint32_t o = boff + fn * 8 * PSTR * 2;
                ldsm2(bhf[fn], bBh + o);
                ldsm2(blf[fn], bBl + o);
            }
            #pragma unroll
            for (int fn = 0; fn < 4; fn++) {
                mma_bf16(acc[fn], ah, bhf[fn]);
                mma_bf16(acc[fn], ah, blf[fn]);
                mma_bf16(acc[fn], al, bhf[fn]);
            }
        }
        __syncthreads();
    }

    #pragma unroll
    for (int fn = 0; fn < 4; fn++)
        #pragma unroll
        for (int drp = 0; drp < 2; drp++) {
            int m = m0 + wm * 16 + (lane >> 2) + drp * 8;
            int n = n0 + wn * 32 + fn * 8 + (lane & 3) * 2;
            float2 v;
            v.x = acc[fn][drp * 2 + 0] + bias[n];
            v.y = acc[fn][drp * 2 + 1] + bias[n + 1];
            *(float2*)&out[(size_t)m * EE + n] = v;
        }
}

// ================= batched QK^T: fp16 single-pass, 128x64 tiles, 3 CTA/SM =================
__global__ void __launch_bounds__(256, 3) qk_mma(
    const __half* __restrict__ qf, const __half* __restrict__ kf,
    float* __restrict__ s)
{
    __shared__ __half sA[128*PSTR], sB[64*PSTR];
    int t = threadIdx.x, lane = t & 31, wid = t >> 5;
    int wm = wid >> 1, wn = wid & 1;
    int j0 = blockIdx.x * 64, i0 = blockIdx.y * 128, bh = blockIdx.z;

    uint32_t bA = smem_u32(sA), bB = smem_u32(sB);
    float acc[2][4][4] = {};
    int mat = lane >> 3, r8 = lane & 7;

    for (int kc = 0; kc < 2; kc++) {
        #pragma unroll
        for (int i = t; i < 512; i += 256) {
            int row = i >> 2, seg = i & 3;
            size_t ga = ((size_t)bh * SS + i0 + row) * HD + kc * 32 + seg * 8;
            *(uint4*)&sA[row * PSTR + seg * 8] = *(const uint4*)&qf[ga];
        }
        {
            int row = t >> 2, seg = t & 3;
            size_t gb = ((size_t)bh * SS + j0 + row) * HD + kc * 32 + seg * 8;
            *(uint4*)&sB[row * PSTR + seg * 8] = *(const uint4*)&kf[gb];
        }
        __syncthreads();
        #pragma unroll
        for (int kk = 0; kk < 2; kk++) {
            uint32_t ah[2][4], bhf[4][2];
            uint32_t aoff = (uint32_t)((wm * 32 + r8 + (mat & 1) * 8) * PSTR + kk * 16 + (mat >> 1) * 8) * 2;
            #pragma unroll
            for (int fm = 0; fm < 2; fm++)
                ldsm4(ah[fm], bA + aoff + fm * 16 * PSTR * 2);
            uint32_t boff = (uint32_t)((wn * 32 + r8) * PSTR + kk * 16 + (mat & 1) * 8) * 2;
            #pragma unroll
            for (int fn = 0; fn < 4; fn++)
                ldsm2(bhf[fn], bB + boff + fn * 8 * PSTR * 2);
            #pragma unroll
            for (int fm = 0; fm < 2; fm++)
                #pragma unroll
                for (int fn = 0; fn < 4; fn++)
                    mma_f16(acc[fm][fn], ah[fm], bhf[fn]);
        }
        __syncthreads();
    }

    float* sbase = s + (size_t)bh * SS * SS;
    #pragma unroll
    for (int fm = 0; fm < 2; fm++)
        #pragma unroll
        for (int fn = 0; fn < 4; fn++)
            #pragma unroll
            for (int drp = 0; drp < 2; drp++) {
                int mi = i0 + wm * 32 + fm * 16 + (lane >> 2) + drp * 8;
                int nj = j0 + wn * 32 + fn * 8 + (lane & 3) * 2;
                float2 o;
                float v0 = acc[fm][fn][drp * 2 + 0] * 0.125f;
                float v1 = acc[fm][fn][drp * 2 + 1] * 0.125f;
                if (isnan(v0)) v0 = 0.f; else if (isinf(v0)) v0 = v0 > 0.f ? 10.f : -10.f;
                if (isnan(v1)) v1 = 0.f; else if (isinf(v1)) v1 = v1 > 0.f ? 10.f : -10.f;
                o.x = clipf(v0, -15.f, 15.f);
                o.y = clipf(v1, -15.f, 15.f);
                *(float2*)&sbase[(size_t)mi * SS + nj] = o;
            }
}

// ================= batched attn @ V: fp16 2-pass, 64x64 tiles =================
__global__ void __launch_bounds__(256, 2) av_mma(
    const __half* __restrict__ af,
    const __half* __restrict__ vthi, const __half* __restrict__ vtlo,
    __nv_bfloat16* __restrict__ ohi, __nv_bfloat16* __restrict__ olo)
{
    __shared__ __half sA[64*PSTR], sBh[64*PSTR], sBl[64*PSTR];
    int t = threadIdx.x, lane = t & 31, wid = t >> 5;
    int wm = wid >> 1, wn = wid & 1;
    int i0 = blockIdx.x * 64, bh = blockIdx.y;
    int b = bh >> 3, h = bh & 7;

    uint32_t bA = smem_u32(sA), bBh = smem_u32(sBh), bBl = smem_u32(sBl);
    float acc[4][4] = {};
    int mat = lane >> 3, r8 = lane & 7;

    for (int kc = 0; kc < 16; kc++) {
        {
            int row = t >> 2, seg = t & 3;
            size_t ga = (size_t)bh * SS * SS + (size_t)(i0 + row) * SS + kc * 32 + seg * 8;
            *(uint4*)&sA[row * PSTR + seg * 8] = *(const uint4*)&af[ga];
            size_t gb = ((size_t)bh * HD + row) * SS + kc * 32 + seg * 8;
            *(uint4*)&sBh[row * PSTR + seg * 8] = *(const uint4*)&vthi[gb];
            *(uint4*)&sBl[row * PSTR + seg * 8] = *(const uint4*)&vtlo[gb];
        }
        __syncthreads();
        #pragma unroll
        for (int kk = 0; kk < 2; kk++) {
            uint32_t ah[4], bhf[4][2], blf[4][2];
            uint32_t aoff = (uint32_t)((wm * 16 + r8 + (mat & 1) * 8) * PSTR + kk * 16 + (mat >> 1) * 8) * 2;
            ldsm4(ah, bA + aoff);
            uint32_t boff = (uint32_t)((wn * 32 + r8) * PSTR + kk * 16 + (mat & 1) * 8) * 2;
            #pragma unroll
            for (int fn = 0; fn < 4; fn++) {
                uint32_t o = boff + fn * 8 * PSTR * 2;
                ldsm2(bhf[fn], bBh + o);
                ldsm2(blf[fn], bBl + o);
            }
            #pragma unroll
            for (int fn = 0; fn < 4; fn++) {
                mma_f16(acc[fn], ah, bhf[fn]);
                mma_f16(acc[fn], ah, blf[fn]);
            }
        }
        __syncthreads();
    }

    #pragma unroll
    for (int fn = 0; fn < 4; fn++)
        #pragma unroll
        for (int drp = 0; drp < 2; drp++) {
            int si = i0 + wm * 16 + (lane >> 2) + drp * 8;
            int d  = wn * 32 + fn * 8 + (lane & 3) * 2;
            float v0 = acc[fn][drp * 2 + 0];
            float v1 = acc[fn][drp * 2 + 1];
            size_t dst = ((size_t)b * SS + si) * EE + h * HD + d;
            __nv_bfloat16 h0 = __float2bfloat16_rn(v0);
            __nv_bfloat16 h1 = __float2bfloat16_rn(v1);
            *(__nv_bfloat162*)&ohi[dst] = __nv_bfloat162(h0, h1);
            *(__nv_bfloat162*)&olo[dst] = __nv_bfloat162(
                __float2bfloat16_rn(v0 - __bfloat162float(h0)),
                __float2bfloat16_rn(v1 - __bfloat162float(h1)));
        }
}

// ================= fused head-mean + row transform (warp-per-row, float4) =================
__global__ void __launch_bounds__(256) row_transform_fused(
    const float* __restrict__ s, float* __restrict__ ma, float* __restrict__ tp,
    const float* __restrict__ w1, const float* __restrict__ b1,
    const float* __restrict__ w2, const float* __restrict__ b2)
{
    __shared__ float w1s[CC], b1s[CC], w2s[CC];
    int t = threadIdx.x, lane = t & 31, w = t >> 5;
    float mlpP = g_mlp[0], mlpN = g_mlp[1];
    int fast = (g_mlp[2] != 0.f);
    if (!fast && t < CC) { w1s[t] = w1[t]; b1s[t] = b1[t]; w2s[t] = w2[t]; }
    __syncthreads();

    int row = blockIdx.x * 8 + w;
    int b = row >> 9, i = row & 511;
    const float* sb = s + ((size_t)b * HH * SS + i) * SS;
    float* marow = ma + ((size_t)b * SS + i) * SS;
    float* tprow = tp + ((size_t)b * SS + i) * SS;

    float m[16];
    #pragma unroll
    for (int e2 = 0; e2 < 4; e2++) {
        int f = lane + 32 * e2;
        float4 acc4 = make_float4(0.f, 0.f, 0.f, 0.f);
        #pragma unroll
        for (int hh = 0; hh < HH; hh++) {
            float4 v = ((const float4*)(sb + (size_t)hh * SS * SS))[f];
            acc4.x += v.x; acc4.y += v.y; acc4.z += v.z; acc4.w += v.w;
        }
        acc4.x *= 0.125f; acc4.y *= 0.125f; acc4.z *= 0.125f; acc4.w *= 0.125f;
        ((float4*)marow)[f] = acc4;
        m[e2 * 4 + 0] = acc4.x; m[e2 * 4 + 1] = acc4.y;
        m[e2 * 4 + 2] = acc4.z; m[e2 * 4 + 3] = acc4.w;
    }

    float mx = -1e30f;
    #pragma unroll
    for (int e = 0; e < 16; e++) mx = fmaxf(mx, clipf(m[e], -10.f, 10.f));
    mx = warpMax(mx);
    float a_[16]; float sum = 0.f;
    #pragma unroll
    for (int e = 0; e < 16; e++) { a_[e] = __expf(clipf(m[e], -10.f, 10.f) - mx); sum += a_[e]; }
    sum = warpSum(sum);
    float inv = 1.f / sum;
    float h_[16];
    #pragma unroll
    for (int e = 0; e < 16; e++) { float p = a_[e] * inv; h_[e] = -p * __logf(p + 1e-6f); }

    float sma = 0.f, sma2 = 0.f, shh = 0.f, amx = 0.f;
    #pragma unroll
    for (int e = 0; e < 16; e++) {
        sma += m[e]; sma2 += m[e] * m[e]; shh += h_[e]; amx = fmaxf(amx, fabsf(m[e]));
    }
    sma = warpSum(sma); sma2 = warpSum(sma2); shh = warpSum(shh); amx = warpMax(amx);

    float hmx = -1e30f;
    #pragma unroll
    for (int e = 0; e < 16; e++) hmx = fmaxf(hmx, h_[e]);
    hmx = warpMax(hmx) * 3.f;
    float fsum = 0.f;
    #pragma unroll
    for (int e = 0; e < 16; e++) { h_[e] = __expf(3.f * h_[e] - hmx); fsum += h_[e]; }
    fsum = warpSum(fsum);
    float finv = 1.f / fsum;

    float acc[16];
    if (fast) {
        #pragma unroll
        for (int e = 0; e < 16; e++) {
            float sa = clipf(clipf(m[e], -8.f, 8.f) * 0.05f, -10.f, 10.f);
            acc[e] = sa * (sa > 0.f ? mlpP : mlpN);
        }
    } else {
        float sa[16];
        #pragma unroll
        for (int e = 0; e < 16; e++) {
            sa[e] = clipf(clipf(m[e], -8.f, 8.f) * 0.05f, -10.f, 10.f);
            acc[e] = 0.f;
        }
        #pragma unroll 4
        for (int c = 0; c < CC; c++) {
            float wv = w1s[c], bb = b1s[c], w2v = w2s[c];
            #pragma unroll
            for (int e = 0; e < 16; e++)
                acc[e] += fminf(fmaxf(fminf(fmaxf(sa[e] * wv + bb, -5.f), 5.f), 0.f), 5.f) * w2v;
        }
    }
    float b2v = b2[0];
    float stt = 0.f, st2 = 0.f;
    #pragma unroll
    for (int e2 = 0; e2 < 4; e2++) {
        float4 o;
        float* op = (float*)&o;
        #pragma unroll
        for (int q = 0; q < 4; q++) {
            int e = e2 * 4 + q;
            float ap = clipf(acc[e] + b2v, -5.f, 5.f);
            float ty = clipf(1.f + 2.5f * ap, 0.5f, 1.5f);
            float sg = 1.f / (1.f + __expf(-ty));
            float tv = sg * (h_[e] * finv);
            op[q] = tv;
            stt += tv; st2 += tv * tv;
        }
        ((float4*)tprow)[lane + 32 * e2] = o;
    }
    stt = warpSum(stt); st2 = warpSum(st2);

    if (lane == 0) {
        atomicAdd(&g_acc[b * 5 + 0], (double)sma);
        atomicAdd(&g_acc[b * 5 + 1], (double)sma2);
        atomicAdd(&g_acc[b * 5 + 2], (double)shh);
        atomicAdd(&g_acc[b * 5 + 3], (double)stt);
        atomicAdd(&g_acc[b * 5 + 4], (double)st2);
        atomicMax(&g_amax[b], __float_as_int(amx));
    }
}

__global__ void finalize_kernel()
{
    int b = threadIdx.x;
    if (b < BB) {
        const double N = (double)SS * (double)SS;
        double sma  = g_acc[b * 5 + 0];
        double sma2 = g_acc[b * 5 + 1];
        double sh   = g_acc[b * 5 + 2];
        double st   = g_acc[b * 5 + 3];
        double st2  = g_acc[b * 5 + 4];
        float amaxv = __int_as_float(g_amax[b]);

        float eo = sqrtf((float)sma2) + 1e-4f;
        float et = sqrtf((float)st2) + 1e-4f;
        float c  = clipf(eo / et, 0.8f, 1.2f);
        float tm = c * (float)(st / N);
        float tvar = c * c * (float)(st2 / N - (st / N) * (st / N));
        tvar = fmaxf(tvar, 0.01f);
        float ovar = (float)(sma2 / N - (sma / N) * (sma / N));
        ovar = fmaxf(ovar, 0.01f);
        float gd = clipf(sqrtf(ovar) / sqrtf(tvar), 0.8f, 1.2f);
        float ar = clipf(amaxv, 1.f, 10.f);
        float sm = clipf(0.3f / log1pf(ar), 0.1f, 0.5f);
        float ent = (float)(sh / N);
        float ne = ent / logf((float)SS);
        float rr = 0.4f * (1.f - clipf(ne, 0.f, 0.4f));
        float smgd = sm * gd;

        g_coef[b * 3 + 0] = rr * tm * (1.f - smgd);
        g_coef[b * 3 + 1] = rr * smgd * c;
        g_coef[b * 3 + 2] = rr;
    }
}

// ================= softmax + delta: CTA per (b,i), smem delta, fp16 out =================
__global__ void __launch_bounds__(256) attn_softmax2(
    const float* __restrict__ s, const float* __restrict__ ma,
    const float* __restrict__ tp, const float* __restrict__ tau,
    __half* __restrict__ af)
{
    __shared__ float delta[SS];
    int t = threadIdx.x, lane = t & 31, w = t >> 5;
    int bi = blockIdx.x;
    int b = bi >> 9;

    float A  = g_coef[b * 3 + 0];
    float Bc = g_coef[b * 3 + 1];
    float Cc = g_coef[b * 3 + 2];
    float itau = 1.f / tau[0];

    {
        const float2* ma2 = (const float2*)(ma + (size_t)bi * SS);
        const float2* tp2 = (const float2*)(tp + (size_t)bi * SS);
        float2 mv = ma2[t], tv = tp2[t];
        delta[t * 2 + 0] = A + Bc * tv.x - Cc * mv.x;
        delta[t * 2 + 1] = A + Bc * tv.y - Cc * mv.y;
    }
    __syncthreads();

    int i = bi & 511;
    size_t row = ((size_t)(b * HH + w) * SS + i);
    const float4* srow4 = (const float4*)(s + row * SS);
    const float4* d4 = (const float4*)delta;

    float v[16];
    float mx = -1e30f;
    #pragma unroll
    for (int e2 = 0; e2 < 4; e2++) {
        int f = lane + 32 * e2;
        float4 sv = srow4[f];
        float4 dv = d4[f];
        v[e2*4+0] = (sv.x + dv.x) * itau;
        v[e2*4+1] = (sv.y + dv.y) * itau;
        v[e2*4+2] = (sv.z + dv.z) * itau;
        v[e2*4+3] = (sv.w + dv.w) * itau;
        mx = fmaxf(mx, fmaxf(fmaxf(v[e2*4+0], v[e2*4+1]), fmaxf(v[e2*4+2], v[e2*4+3])));
    }
    mx = warpMax(mx);
    float sum = 0.f;
    #pragma unroll
    for (int e = 0; e < 16; e++) { v[e] = __expf(v[e] - mx); sum += v[e]; }
    sum = warpSum(sum);
    float inv = 1.f / sum;

    uint2* arow = (uint2*)(af + row * SS);
    #pragma unroll
    for (int e2 = 0; e2 < 4; e2++) {
        int f = lane + 32 * e2;
        __half2 ha = __floats2half2_rn(v[e2*4+0] * inv, v[e2*4+1] * inv);
        __half2 hb = __floats2half2_rn(v[e2*4+2] * inv, v[e2*4+3] * inv);
        uint2 u;
        u.x = *(uint32_t*)&ha;
        u.y = *(uint32_t*)&hb;
        arow[f] = u;
    }
}

// ---------------- launch ----------------
extern "C" void kernel_launch(void* const* d_in, const int* in_sizes, int n_in,
                              void* d_out, int out_size)
{
    const float* x  = (const float*)d_in[0];
    const float* Wq = (const float*)d_in[1];
    const float* bq = (const float*)d_in[2];
    const float* Wk = (const float*)d_in[3];
    const float* bk = (const float*)d_in[4];
    const float* Wv = (const float*)d_in[5];
    const float* bv = (const float*)d_in[6];
    const float* Wo = (const float*)d_in[7];
    const float* bo = (const float*)d_in[8];
    const float* w1 = (const float*)d_in[9];
    const float* b1 = (const float*)d_in[10];
    const float* w2 = (const float*)d_in[11];
    const float* b2 = (const float*)d_in[12];
    const float* tau = (const float*)d_in[13];
    float* out = (float*)d_out;

    __nv_bfloat16 *pwthi, *pwtlo, *pohhi, *pohlo;
    __half *pxhi, *pxlo, *pwf, *pqf, *pkf, *pvthi, *pvtlo, *paf;
    float *ps, *pma, *ptp;
    cudaGetSymbolAddress((void**)&pxhi, g_xhi);
    cudaGetSymbolAddress((void**)&pxlo, g_xlo);
    cudaGetSymbolAddress((void**)&pwf, g_wf);
    cudaGetSymbolAddress((void**)&pwthi, g_wthi);
    cudaGetSymbolAddress((void**)&pwtlo, g_wtlo);
    cudaGetSymbolAddress((void**)&pqf, g_qf);
    cudaGetSymbolAddress((void**)&pkf, g_kf);
    cudaGetSymbolAddress((void**)&pvthi, g_vthi);
    cudaGetSymbolAddress((void**)&pvtlo, g_vtlo);
    cudaGetSymbolAddress((void**)&paf, g_af);
    cudaGetSymbolAddress((void**)&pohhi, g_ohhi);
    cudaGetSymbolAddress((void**)&pohlo, g_ohlo);
    cudaGetSymbolAddress((void**)&ps, g_s);
    cudaGetSymbolAddress((void**)&pma, g_ma);
    cudaGetSymbolAddress((void**)&ptp, g_tp);

    // 1) conversions + MLP prep
    conv_split<<<(NROW * EE / 4) / 256, 256>>>(x, pxhi, pxlo, NROW * EE);
    conv_w4<<<dim3(16, 16, 4), dim3(32, 8)>>>(Wq, Wk, Wv, Wo, pwf, pwthi, pwtlo);
    mlp_prep<<<1, 32>>>(w1, b1, w2);

    // 2) fused QKV projection (fp16 2-pass, reg-prefetch pipeline)
    proj_qkv<<<dim3(8, 16, 3), 256>>>(pxhi, pxlo, pwf, bq, bk, bv,
                                      pqf, pkf, pvthi, pvtlo);

    // 3) QK^T (fp16 single-pass, 3 CTA/SM)
    qk_mma<<<dim3(8, 4, BB * HH), 256>>>(pqf, pkf, ps);

    // 4) fused head-mean + transform + stats (MLP fast path)
    row_transform_fused<<<256, 256>>>(ps, pma, ptp, w1, b1, w2, b2);
    finalize_kernel<<<1, 32>>>();

    // 5) softmax -> attn fp16
    attn_softmax2<<<BB * SS, 256>>>(ps, pma, ptp, tau, paf);

    // 6) attn @ V (fp16 2-pass)
    av_mma<<<dim3(8, BB * HH), 256>>>(paf, pvthi, pvtlo, pohhi, pohlo);

    // 7) output projection (bf16 3-pass) -> fp32 out
    proj_out<<<dim3(8, 32), 256>>>(pohhi, pohlo, pwthi, pwtlo, bo, out);
}